// round 1
// baseline (speedup 1.0000x reference)
#include <cuda_runtime.h>
#include <math.h>

#define B 4
#define S 2048
#define D 512
#define H 8
#define DK 64
#define U 53
#define BH (B*H)

// ---------------- scratch (static device allocations; no cudaMalloc) ----------------
__device__ float g_Q[B*H*S*DK];       // [b][h][s][k]
__device__ float g_K[B*H*S*DK];
__device__ float g_spars[B*H*S];
__device__ int   g_topidx[B*H*U];
__device__ float g_xpart[8*B*D];      // partial column sums of x
__device__ float g_xsum[B*D];
__device__ float g_meanV[B*D];        // meanV concat over heads, per batch
__device__ float g_ybase[B*D];        // meanV @ wo^T + bo
__device__ float g_outcat[B*U*D];     // corrected attention rows (pre out-proj)

// ---------------- column sums of x ----------------
__global__ void sumx_part_kernel(const float* __restrict__ x) {
    int blk = blockIdx.x;           // 0..B*8-1
    int b = blk >> 3, sc = blk & 7; // 8 s-chunks of 256
    int d = threadIdx.x;            // 512 threads
    const float* p = x + ((size_t)b*S + sc*256)*D + d;
    float acc = 0.f;
    #pragma unroll 4
    for (int s = 0; s < 256; s++) acc += p[(size_t)s*D];
    g_xpart[(size_t)blk*D + d] = acc;
}

__global__ void sumx_final_kernel() {
    int b = blockIdx.x, d = threadIdx.x;
    float acc = 0.f;
    #pragma unroll
    for (int sc = 0; sc < 8; sc++) acc += g_xpart[(size_t)(b*8+sc)*D + d];
    g_xsum[b*D + d] = acc;
}

// ---------------- Q/K projection GEMM: [8192x512] @ W^T + bias -> [b][h][s][k] ----------------
__global__ void proj_kernel(const float* __restrict__ x, const float* __restrict__ w,
                            const float* __restrict__ bias, int which) {
    __shared__ float As[32][68];
    __shared__ float Bs[32][68];
    float* out = which ? g_K : g_Q;
    int tid = threadIdx.x;
    int tx = tid & 15, ty = tid >> 4;
    int m0 = blockIdx.x * 64;       // global row (b*S+s)
    int n0 = blockIdx.y * 64;       // output feature (one head per tile)
    float acc[4][4] = {};
    for (int d0 = 0; d0 < D; d0 += 32) {
        #pragma unroll
        for (int i = 0; i < 2; i++) {
            int e = tid + i*256;          // 0..511 float4 slots (64 rows x 8 f4)
            int row = e >> 3;
            int c4 = e & 7;
            float4 v = *(const float4*)(x + (size_t)(m0+row)*D + d0 + c4*4);
            As[c4*4+0][row] = v.x; As[c4*4+1][row] = v.y;
            As[c4*4+2][row] = v.z; As[c4*4+3][row] = v.w;
            float4 u = *(const float4*)(w + (size_t)(n0+row)*D + d0 + c4*4);
            Bs[c4*4+0][row] = u.x; Bs[c4*4+1][row] = u.y;
            Bs[c4*4+2][row] = u.z; Bs[c4*4+3][row] = u.w;
        }
        __syncthreads();
        #pragma unroll
        for (int kk = 0; kk < 32; kk++) {
            float4 a = *(const float4*)&As[kk][tx*4];
            float4 bv4 = *(const float4*)&Bs[kk][ty*4];
            float av[4] = {a.x, a.y, a.z, a.w};
            float bw[4] = {bv4.x, bv4.y, bv4.z, bv4.w};
            #pragma unroll
            for (int i = 0; i < 4; i++)
                #pragma unroll
                for (int j = 0; j < 4; j++)
                    acc[i][j] += av[i] * bw[j];
        }
        __syncthreads();
    }
    int h = n0 >> 6; // n-tile is exactly one head (64 wide)
    #pragma unroll
    for (int i = 0; i < 4; i++) {
        int m = m0 + tx*4 + i;
        int b = m >> 11, s = m & (S-1);
        float* op = out + (((size_t)(b*H + h)*S + s)*DK) + (ty*4);
        #pragma unroll
        for (int j = 0; j < 4; j++)
            op[j] = acc[i][j] + bias[n0 + ty*4 + j];
    }
}

// ---------------- fused QK^T row-max/row-mean -> sparsity (never materializes scores) ----------------
__global__ void scores_kernel() {
    __shared__ float Qs[64][68];
    __shared__ float Ks[64][68];
    int tid = threadIdx.x;
    int tx = tid & 15, ty = tid >> 4;
    int bh = blockIdx.x;
    int q0 = blockIdx.y * 64;
    const float* Qb = g_Q + (size_t)bh*S*DK;
    const float* Kb = g_K + (size_t)bh*S*DK;
    // load Q tile (64 rows x 64 depth), transposed into smem
    #pragma unroll
    for (int i = 0; i < 4; i++) {
        int e = tid + i*256;          // 0..1023 float4 (64 rows x 16 f4)
        int row = e >> 4;
        int c4 = e & 15;
        float4 v = *(const float4*)(Qb + (size_t)(q0+row)*DK + c4*4);
        Qs[c4*4+0][row] = v.x; Qs[c4*4+1][row] = v.y;
        Qs[c4*4+2][row] = v.z; Qs[c4*4+3][row] = v.w;
    }
    float vmax[4] = {-1e30f, -1e30f, -1e30f, -1e30f};
    float vsum[4] = {0.f, 0.f, 0.f, 0.f};
    for (int kt = 0; kt < S; kt += 64) {
        __syncthreads();  // protect Ks from previous iteration's readers
        #pragma unroll
        for (int i = 0; i < 4; i++) {
            int e = tid + i*256;
            int row = e >> 4;
            int c4 = e & 15;
            float4 v = *(const float4*)(Kb + (size_t)(kt+row)*DK + c4*4);
            Ks[c4*4+0][row] = v.x; Ks[c4*4+1][row] = v.y;
            Ks[c4*4+2][row] = v.z; Ks[c4*4+3][row] = v.w;
        }
        __syncthreads();
        float acc[4][4] = {};
        #pragma unroll 16
        for (int kk = 0; kk < 64; kk++) {
            float4 a = *(const float4*)&Qs[kk][tx*4];
            float4 bb = *(const float4*)&Ks[kk][ty*4];
            float av[4] = {a.x, a.y, a.z, a.w};
            float bw[4] = {bb.x, bb.y, bb.z, bb.w};
            #pragma unroll
            for (int i = 0; i < 4; i++)
                #pragma unroll
                for (int j = 0; j < 4; j++)
                    acc[i][j] += av[i] * bw[j];
        }
        #pragma unroll
        for (int i = 0; i < 4; i++) {
            #pragma unroll
            for (int j = 0; j < 4; j++) {
                float sc = acc[i][j] * 0.125f;
                vmax[i] = fmaxf(vmax[i], sc);
                vsum[i] += sc;
            }
        }
    }
    __syncthreads();
    float* redm = &Ks[0][0];        // reuse smem: 1024 + 1024 floats
    float* reds = redm + 1024;
    #pragma unroll
    for (int i = 0; i < 4; i++) {
        redm[ty*64 + tx*4 + i] = vmax[i];
        reds[ty*64 + tx*4 + i] = vsum[i];
    }
    __syncthreads();
    if (tid < 64) {
        float m = -1e30f, sum = 0.f;
        #pragma unroll
        for (int t = 0; t < 16; t++) {
            m = fmaxf(m, redm[t*64 + tid]);
            sum += reds[t*64 + tid];
        }
        float mean = sum * (1.0f / (float)S);
        g_spars[bh*S + q0 + tid] = mean - m / logf((float)S);
    }
}

// ---------------- iterative top-53 per (b,h), ties -> lowest index (matches top_k) ----------------
__global__ void topk_kernel() {
    __shared__ float vals[S];
    __shared__ float bm[256];
    __shared__ int   bi[256];
    int bh = blockIdx.x, tid = threadIdx.x;
    for (int i = tid; i < S; i += 256) vals[i] = g_spars[bh*S + i];
    __syncthreads();
    for (int it = 0; it < U; it++) {
        float best = -1e30f; int bidx = S;
        for (int i = tid; i < S; i += 256) {
            float v = vals[i];
            if (v > best || (v == best && i < bidx)) { best = v; bidx = i; }
        }
        bm[tid] = best; bi[tid] = bidx;
        __syncthreads();
        for (int off = 128; off > 0; off >>= 1) {
            if (tid < off) {
                float v2 = bm[tid+off]; int i2 = bi[tid+off];
                if (v2 > bm[tid] || (v2 == bm[tid] && i2 < bi[tid])) { bm[tid] = v2; bi[tid] = i2; }
            }
            __syncthreads();
        }
        if (tid == 0) { g_topidx[bh*U + it] = bi[0]; vals[bi[0]] = -1e30f; }
        __syncthreads();
    }
}

// ---------------- meanV (per batch, concat heads) via xsum; then base output row ----------------
__global__ void meanv_kernel(const float* __restrict__ wv, const float* __restrict__ bv) {
    __shared__ float xs[D];
    int b = blockIdx.x, tid = threadIdx.x;   // 512 threads
    xs[tid] = g_xsum[b*D + tid];
    __syncthreads();
    const float* wr = wv + (size_t)tid * D;
    float acc = 0.f;
    #pragma unroll 8
    for (int d = 0; d < D; d++) acc += xs[d] * wr[d];
    g_meanV[b*D + tid] = acc * (1.0f / (float)S) + bv[tid];
}

__global__ void ybase_kernel(const float* __restrict__ wo, const float* __restrict__ bo) {
    __shared__ float ms[D];
    int b = blockIdx.x, tid = threadIdx.x;
    ms[tid] = g_meanV[b*D + tid];
    __syncthreads();
    const float* wr = wo + (size_t)tid * D;
    float acc = 0.f;
    #pragma unroll 8
    for (int d = 0; d < D; d++) acc += ms[d] * wr[d];
    g_ybase[b*D + tid] = acc + bo[tid];
}

// ---------------- corrections for rows i < U: out = (S*meanV + (e^v-1)*V_j) / (e^v + S-1) ----------------
__global__ void corr_kernel(const float* __restrict__ x, const float* __restrict__ wv,
                            const float* __restrict__ bv) {
    __shared__ float xj[D];
    __shared__ float wvs[64][65];
    __shared__ float sred[64];
    int blk = blockIdx.x;                 // B*H*U blocks
    int b = blk / (H*U);
    int rem = blk % (H*U);
    int h = rem / U;
    int i = rem % U;
    int tid = threadIdx.x;                // 64 threads
    int bh = b*H + h;
    int j = g_topidx[bh*U + i];
    for (int t = tid; t < D; t += 64) xj[t] = x[((size_t)b*S + j)*D + t];
    // v = Q[bh,i] . K[bh,j] / 8
    sred[tid] = g_Q[((size_t)bh*S + i)*DK + tid] * g_K[((size_t)bh*S + j)*DK + tid];
    __syncthreads();
    for (int off = 32; off > 0; off >>= 1) {
        if (tid < off) sred[tid] += sred[tid + off];
        __syncthreads();
    }
    float v = sred[0] * 0.125f;
    // V_j for this head: dot(x[b,j,:], wv[h*64+tid, :]) + bv (tiled through smem)
    float acc = 0.f;
    for (int dt = 0; dt < 8; dt++) {
        __syncthreads();
        #pragma unroll 8
        for (int r = 0; r < 64; r++)
            wvs[r][tid] = wv[((size_t)(h*64 + r))*D + dt*64 + tid];
        __syncthreads();
        #pragma unroll 16
        for (int dd = 0; dd < 64; dd++)
            acc += xj[dt*64 + dd] * wvs[tid][dd];
    }
    float Vj = acc + bv[h*64 + tid];
    float ev = expf(v);
    float Z = ev + (float)(S - 1);
    float mv = g_meanV[b*D + h*64 + tid];
    g_outcat[((size_t)(b*U + i))*D + h*64 + tid] = ((float)S * mv + (ev - 1.0f) * Vj) / Z;
}

// ---------------- out-projection for the 212 corrected rows ----------------
__global__ void outproj_kernel(const float* __restrict__ wo, const float* __restrict__ bo,
                               float* __restrict__ y) {
    __shared__ float As[32][68];
    __shared__ float Bs[32][68];
    int tid = threadIdx.x;
    int tx = tid & 15, ty = tid >> 4;
    int m0 = blockIdx.x * 64;       // row in [0, 256), valid < B*U=212
    int n0 = blockIdx.y * 64;
    float acc[4][4] = {};
    for (int d0 = 0; d0 < D; d0 += 32) {
        #pragma unroll
        for (int i = 0; i < 2; i++) {
            int e = tid + i*256;
            int row = e >> 3;
            int c4 = e & 7;
            float4 v = make_float4(0.f, 0.f, 0.f, 0.f);
            if (m0 + row < B*U)
                v = *(const float4*)(g_outcat + (size_t)(m0+row)*D + d0 + c4*4);
            As[c4*4+0][row] = v.x; As[c4*4+1][row] = v.y;
            As[c4*4+2][row] = v.z; As[c4*4+3][row] = v.w;
            float4 u = *(const float4*)(wo + (size_t)(n0+row)*D + d0 + c4*4);
            Bs[c4*4+0][row] = u.x; Bs[c4*4+1][row] = u.y;
            Bs[c4*4+2][row] = u.z; Bs[c4*4+3][row] = u.w;
        }
        __syncthreads();
        #pragma unroll
        for (int kk = 0; kk < 32; kk++) {
            float4 a = *(const float4*)&As[kk][tx*4];
            float4 bv4 = *(const float4*)&Bs[kk][ty*4];
            float av[4] = {a.x, a.y, a.z, a.w};
            float bw[4] = {bv4.x, bv4.y, bv4.z, bv4.w};
            #pragma unroll
            for (int i = 0; i < 4; i++)
                #pragma unroll
                for (int j = 0; j < 4; j++)
                    acc[i][j] += av[i] * bw[j];
        }
        __syncthreads();
    }
    #pragma unroll
    for (int i = 0; i < 4; i++) {
        int m = m0 + tx*4 + i;
        if (m < B*U) {
            int b = m / U, s = m % U;
            float* op = y + ((size_t)b*S + s)*D + n0 + ty*4;
            #pragma unroll
            for (int j = 0; j < 4; j++)
                op[j] = acc[i][j] + bo[n0 + ty*4 + j];
        }
    }
}

// ---------------- broadcast the uniform rows (s >= U) ----------------
__global__ void bcast_kernel(float* __restrict__ y) {
    int id = blockIdx.x * blockDim.x + threadIdx.x;
    const int per_b = (S - U) * (D/4);
    const int total = B * per_b;
    if (id >= total) return;
    int b = id / per_b;
    int r = id % per_b;
    int s = U + r / (D/4);
    int d4 = r % (D/4);
    float4 v = *(const float4*)(g_ybase + b*D + d4*4);
    *(float4*)(y + ((size_t)b*S + s)*D + d4*4) = v;
}

extern "C" void kernel_launch(void* const* d_in, const int* in_sizes, int n_in,
                              void* d_out, int out_size) {
    const float* x  = (const float*)d_in[0];
    const float* wq = (const float*)d_in[1];
    const float* bq = (const float*)d_in[2];
    const float* wk = (const float*)d_in[3];
    const float* bk = (const float*)d_in[4];
    const float* wv = (const float*)d_in[5];
    const float* bv = (const float*)d_in[6];
    const float* wo = (const float*)d_in[7];
    const float* bo = (const float*)d_in[8];
    float* y = (float*)d_out;

    sumx_part_kernel<<<B*8, 512>>>(x);
    sumx_final_kernel<<<B, 512>>>();

    dim3 pg(B*S/64, D/64);
    proj_kernel<<<pg, 256>>>(x, wq, bq, 0);
    proj_kernel<<<pg, 256>>>(x, wk, bk, 1);

    dim3 sg(BH, S/64);
    scores_kernel<<<sg, 256>>>();

    topk_kernel<<<BH, 256>>>();

    meanv_kernel<<<B, 512>>>(wv, bv);
    ybase_kernel<<<B, 512>>>(wo, bo);

    corr_kernel<<<B*H*U, 64>>>(x, wv, bv);

    dim3 og((B*U + 63)/64, D/64);
    outproj_kernel<<<og, 256>>>(wo, bo, y);

    const int per_b = (S - U) * (D/4);
    bcast_kernel<<<(B*per_b + 255)/256, 256>>>(y);
}

// round 5
// speedup vs baseline: 1.3626x; 1.3626x over previous
#include <cuda_runtime.h>
#include <cuda_bf16.h>
#include <math.h>
#include <stdint.h>

#define B 4
#define S 2048
#define D 512
#define H 8
#define DK 64
#define U 53
#define BH (B*H)

// ---------------- scratch (static device allocations; no cudaMalloc) ----------------
__device__ float g_Q[B*H*S*DK];       // [bh][s][k] fp32 (needed by corr)
__device__ float g_K[B*H*S*DK];
__device__ float g_spars[B*H*S];
__device__ int   g_topidx[B*H*U];
__device__ float g_xpart[8*B*D];
__device__ float g_xsum[B*D];
__device__ float g_meanV[B*D];
__device__ float g_ybase[B*D];
__device__ float g_outcat[B*U*D];
// split bf16 operands, row-major [bh][s][64]
__device__ __nv_bfloat16 g_Qhi[BH*S*DK];
__device__ __nv_bfloat16 g_Qlo[BH*S*DK];
__device__ __nv_bfloat16 g_Khi[BH*S*DK];
__device__ __nv_bfloat16 g_Klo[BH*S*DK];

// ================= warp-mma helpers (sm_80+ path, works on plain sm_100) =================
__device__ __forceinline__ uint32_t smem_u32(const void* p) {
    uint32_t a;
    asm("{ .reg .u64 t; cvta.to.shared.u64 t, %1; cvt.u32.u64 %0, t; }" : "=r"(a) : "l"(p));
    return a;
}

__device__ __forceinline__ void ldsm_x4(uint32_t& r0, uint32_t& r1, uint32_t& r2, uint32_t& r3, uint32_t addr) {
    asm volatile("ldmatrix.sync.aligned.m8n8.x4.shared.b16 {%0,%1,%2,%3}, [%4];"
        : "=r"(r0), "=r"(r1), "=r"(r2), "=r"(r3) : "r"(addr));
}
__device__ __forceinline__ void mma_bf16(float& c0, float& c1, float& c2, float& c3,
                                         uint32_t a0, uint32_t a1, uint32_t a2, uint32_t a3,
                                         uint32_t b0, uint32_t b1) {
    asm volatile("mma.sync.aligned.m16n8k16.row.col.f32.bf16.bf16.f32 "
        "{%0,%1,%2,%3}, {%4,%5,%6,%7}, {%8,%9}, {%0,%1,%2,%3};"
        : "+f"(c0), "+f"(c1), "+f"(c2), "+f"(c3)
        : "r"(a0), "r"(a1), "r"(a2), "r"(a3), "r"(b0), "r"(b1));
}
#define CP_ASYNC16(dst, src) \
    asm volatile("cp.async.cg.shared.global [%0], [%1], 16;" :: "r"(dst), "l"(src))
#define CP_COMMIT() asm volatile("cp.async.commit_group;" ::: "memory")
#define CP_WAIT1()  asm volatile("cp.async.wait_group 1;" ::: "memory")

// ---------------- column sums of x ----------------
__global__ void sumx_part_kernel(const float* __restrict__ x) {
    int blk = blockIdx.x;
    int b = blk >> 3, sc = blk & 7;
    int d = threadIdx.x;
    const float* p = x + ((size_t)b*S + sc*256)*D + d;
    float acc = 0.f;
    #pragma unroll 4
    for (int s = 0; s < 256; s++) acc += p[(size_t)s*D];
    g_xpart[(size_t)blk*D + d] = acc;
}

__global__ void sumx_final_kernel() {
    int b = blockIdx.x, d = threadIdx.x;
    float acc = 0.f;
    #pragma unroll
    for (int sc = 0; sc < 8; sc++) acc += g_xpart[(size_t)(b*8+sc)*D + d];
    g_xsum[b*D + d] = acc;
}

// ---------------- Q/K projection GEMM (fp32 SIMT) ----------------
__global__ void proj_kernel(const float* __restrict__ x, const float* __restrict__ w,
                            const float* __restrict__ bias, int which) {
    __shared__ float As[32][68];
    __shared__ float Bs[32][68];
    float* out = which ? g_K : g_Q;
    int tid = threadIdx.x;
    int tx = tid & 15, ty = tid >> 4;
    int m0 = blockIdx.x * 64;
    int n0 = blockIdx.y * 64;
    float acc[4][4] = {};
    for (int d0 = 0; d0 < D; d0 += 32) {
        #pragma unroll
        for (int i = 0; i < 2; i++) {
            int e = tid + i*256;
            int row = e >> 3;
            int c4 = e & 7;
            float4 v = *(const float4*)(x + (size_t)(m0+row)*D + d0 + c4*4);
            As[c4*4+0][row] = v.x; As[c4*4+1][row] = v.y;
            As[c4*4+2][row] = v.z; As[c4*4+3][row] = v.w;
            float4 u = *(const float4*)(w + (size_t)(n0+row)*D + d0 + c4*4);
            Bs[c4*4+0][row] = u.x; Bs[c4*4+1][row] = u.y;
            Bs[c4*4+2][row] = u.z; Bs[c4*4+3][row] = u.w;
        }
        __syncthreads();
        #pragma unroll
        for (int kk = 0; kk < 32; kk++) {
            float4 a = *(const float4*)&As[kk][tx*4];
            float4 bv4 = *(const float4*)&Bs[kk][ty*4];
            float av[4] = {a.x, a.y, a.z, a.w};
            float bw[4] = {bv4.x, bv4.y, bv4.z, bv4.w};
            #pragma unroll
            for (int i = 0; i < 4; i++)
                #pragma unroll
                for (int j = 0; j < 4; j++)
                    acc[i][j] += av[i] * bw[j];
        }
        __syncthreads();
    }
    int h = n0 >> 6;
    #pragma unroll
    for (int i = 0; i < 4; i++) {
        int m = m0 + tx*4 + i;
        int b = m >> 11, s = m & (S-1);
        float* op = out + (((size_t)(b*H + h)*S + s)*DK) + (ty*4);
        #pragma unroll
        for (int j = 0; j < 4; j++)
            op[j] = acc[i][j] + bias[n0 + ty*4 + j];
    }
}

// ---------------- fp32 -> split-bf16 (hi/lo), row-major ----------------
__global__ void convert_kernel() {
    int id = blockIdx.x * blockDim.x + threadIdx.x;
    const int UNITS = BH*S*DK/8;    // 524288 16B-units per matrix
    if (id >= 2*UNITS) return;
    int mat = id / UNITS;
    int u = id - mat*UNITS;
    const float* src = (mat ? g_K : g_Q) + (size_t)u*8;
    float4 a = *(const float4*)src;
    float4 b4 = *(const float4*)(src + 4);
    float vs[8] = {a.x, a.y, a.z, a.w, b4.x, b4.y, b4.z, b4.w};
    union { __nv_bfloat16 h[8]; int4 v; } hi, lo;
    #pragma unroll
    for (int i = 0; i < 8; i++) {
        hi.h[i] = __float2bfloat16(vs[i]);
        lo.h[i] = __float2bfloat16(vs[i] - __bfloat162float(hi.h[i]));
    }
    ((int4*)(mat ? g_Khi : g_Qhi))[u] = hi.v;
    ((int4*)(mat ? g_Klo : g_Qlo))[u] = lo.v;
}

// ---------------- warp-mma QK^T row-max/row-mean -> sparsity ----------------
// grid (BH, 16). CTA = 128 q-rows of one (b,h); 8 warps x m16.
// K streamed in 128-key tiles (hi+lo), 2-stage cp.async pipeline.
// Per n8 tile: 16 HMMA (hi*hi + hi*lo + lo*hi + lo*lo), fold into row max/sum.
#define SQ_HI 0
#define SQ_LO 16384
#define SK_BASE 32768
#define SK_STAGE 32768
#define SM_TOTAL (SK_BASE + 2*SK_STAGE)   // 96 KB

__device__ __forceinline__ void copy_tile_async(uint32_t sdst, const __nv_bfloat16* gsrc, int tid) {
    // 1024 x 16B units; [128 rows][64 bf16] row-major -> XOR-swizzled smem
    #pragma unroll
    for (int i = 0; i < 4; i++) {
        int u = tid + i*256;
        int row = u >> 3, cu = u & 7;
        uint32_t dst = sdst + row*128 + ((cu ^ (row & 7)) << 4);
        CP_ASYNC16(dst, (const char*)gsrc + (size_t)u*16);
    }
}

__global__ void __launch_bounds__(256) scores_mma_kernel() {
    extern __shared__ char smem[];
    uint32_t sb = smem_u32(smem);
    int tid = threadIdx.x;
    int w = tid >> 5, lane = tid & 31;
    int bh = blockIdx.x;
    int qt = blockIdx.y;

    const __nv_bfloat16* qh_g = g_Qhi + (size_t)(bh*S + qt*128)*DK;
    const __nv_bfloat16* ql_g = g_Qlo + (size_t)(bh*S + qt*128)*DK;
    const __nv_bfloat16* kh_g = g_Khi + (size_t)bh*S*DK;
    const __nv_bfloat16* kl_g = g_Klo + (size_t)bh*S*DK;

    // prologue: Q (hi+lo) + K tile 0 -> group0 ; K tile 1 -> group1
    copy_tile_async(sb + SQ_HI, qh_g, tid);
    copy_tile_async(sb + SQ_LO, ql_g, tid);
    copy_tile_async(sb + SK_BASE + 0*SK_STAGE,         kh_g, tid);
    copy_tile_async(sb + SK_BASE + 0*SK_STAGE + 16384, kl_g, tid);
    CP_COMMIT();
    copy_tile_async(sb + SK_BASE + 1*SK_STAGE,         kh_g + 128*DK, tid);
    copy_tile_async(sb + SK_BASE + 1*SK_STAGE + 16384, kl_g + 128*DK, tid);
    CP_COMMIT();

    CP_WAIT1();
    __syncthreads();

    // A fragments: 4 k-steps x 4 regs, hi and lo (persistent)
    uint32_t aHi[4][4], aLo[4][4];
    {
        int row16 = lane & 15;
        int half = lane >> 4;
        uint32_t rowoff = (uint32_t)(w*16 + row16) * 128;
        #pragma unroll
        for (int ks = 0; ks < 4; ks++) {
            uint32_t unit = (uint32_t)(ks*2 + half);
            uint32_t off = rowoff + ((unit ^ (row16 & 7)) << 4);
            ldsm_x4(aHi[ks][0], aHi[ks][1], aHi[ks][2], aHi[ks][3], sb + SQ_HI + off);
            ldsm_x4(aLo[ks][0], aLo[ks][1], aLo[ks][2], aLo[ks][3], sb + SQ_LO + off);
        }
    }

    float rmax0 = -1e30f, rmax1 = -1e30f, rsum0 = 0.f, rsum1 = 0.f;
    int bi = lane >> 3;           // matrix index within ldmatrix group
    int br = lane & 7;            // row within 8-row group

    #pragma unroll 1
    for (int kt = 0; kt < 16; kt++) {
        if (kt > 0) {
            CP_WAIT1();
            __syncthreads();
        }
        uint32_t kb_hi = sb + SK_BASE + (kt & 1)*SK_STAGE;
        uint32_t kb_lo = kb_hi + 16384;

        #pragma unroll
        for (int t = 0; t < 16; t++) {
            int row = t*8 + br;
            uint32_t rowoff = (uint32_t)row * 128;
            uint32_t sw0 = ((uint32_t)(bi    ) ^ (row & 7)) << 4;
            uint32_t sw1 = ((uint32_t)(bi + 4) ^ (row & 7)) << 4;
            uint32_t bh0,bh1,bh2,bh3,bh4,bh5,bh6,bh7;
            uint32_t bl0,bl1,bl2,bl3,bl4,bl5,bl6,bl7;
            // NON-trans ldmatrix: row-major [n][k] K tile IS the col-major B operand
            ldsm_x4(bh0,bh1,bh2,bh3, kb_hi + rowoff + sw0);
            ldsm_x4(bh4,bh5,bh6,bh7, kb_hi + rowoff + sw1);
            ldsm_x4(bl0,bl1,bl2,bl3, kb_lo + rowoff + sw0);
            ldsm_x4(bl4,bl5,bl6,bl7, kb_lo + rowoff + sw1);

            float c0=0.f, c1=0.f, c2=0.f, c3=0.f;
            mma_bf16(c0,c1,c2,c3, aHi[0][0],aHi[0][1],aHi[0][2],aHi[0][3], bh0,bh1);
            mma_bf16(c0,c1,c2,c3, aHi[1][0],aHi[1][1],aHi[1][2],aHi[1][3], bh2,bh3);
            mma_bf16(c0,c1,c2,c3, aHi[2][0],aHi[2][1],aHi[2][2],aHi[2][3], bh4,bh5);
            mma_bf16(c0,c1,c2,c3, aHi[3][0],aHi[3][1],aHi[3][2],aHi[3][3], bh6,bh7);
            mma_bf16(c0,c1,c2,c3, aHi[0][0],aHi[0][1],aHi[0][2],aHi[0][3], bl0,bl1);
            mma_bf16(c0,c1,c2,c3, aHi[1][0],aHi[1][1],aHi[1][2],aHi[1][3], bl2,bl3);
            mma_bf16(c0,c1,c2,c3, aHi[2][0],aHi[2][1],aHi[2][2],aHi[2][3], bl4,bl5);
            mma_bf16(c0,c1,c2,c3, aHi[3][0],aHi[3][1],aHi[3][2],aHi[3][3], bl6,bl7);
            mma_bf16(c0,c1,c2,c3, aLo[0][0],aLo[0][1],aLo[0][2],aLo[0][3], bh0,bh1);
            mma_bf16(c0,c1,c2,c3, aLo[1][0],aLo[1][1],aLo[1][2],aLo[1][3], bh2,bh3);
            mma_bf16(c0,c1,c2,c3, aLo[2][0],aLo[2][1],aLo[2][2],aLo[2][3], bh4,bh5);
            mma_bf16(c0,c1,c2,c3, aLo[3][0],aLo[3][1],aLo[3][2],aLo[3][3], bh6,bh7);
            mma_bf16(c0,c1,c2,c3, aLo[0][0],aLo[0][1],aLo[0][2],aLo[0][3], bl0,bl1);
            mma_bf16(c0,c1,c2,c3, aLo[1][0],aLo[1][1],aLo[1][2],aLo[1][3], bl2,bl3);
            mma_bf16(c0,c1,c2,c3, aLo[2][0],aLo[2][1],aLo[2][2],aLo[2][3], bl4,bl5);
            mma_bf16(c0,c1,c2,c3, aLo[3][0],aLo[3][1],aLo[3][2],aLo[3][3], bl6,bl7);

            rmax0 = fmaxf(rmax0, fmaxf(c0, c1));
            rsum0 += c0 + c1;
            rmax1 = fmaxf(rmax1, fmaxf(c2, c3));
            rsum1 += c2 + c3;
        }
        __syncthreads();
        if (kt + 2 < 16) {
            copy_tile_async(sb + SK_BASE + (kt & 1)*SK_STAGE,         kh_g + (size_t)(kt+2)*128*DK, tid);
            copy_tile_async(sb + SK_BASE + (kt & 1)*SK_STAGE + 16384, kl_g + (size_t)(kt+2)*128*DK, tid);
        }
        CP_COMMIT();
    }

    // reduce across the 4 lanes sharing each row
    #pragma unroll
    for (int off = 1; off < 4; off <<= 1) {
        rmax0 = fmaxf(rmax0, __shfl_xor_sync(0xFFFFFFFFu, rmax0, off));
        rsum0 += __shfl_xor_sync(0xFFFFFFFFu, rsum0, off);
        rmax1 = fmaxf(rmax1, __shfl_xor_sync(0xFFFFFFFFu, rmax1, off));
        rsum1 += __shfl_xor_sync(0xFFFFFFFFu, rsum1, off);
    }
    if ((lane & 3) == 0) {
        int r0 = qt*128 + w*16 + (lane >> 2);
        float inv_log = 1.0f / logf((float)S);
        g_spars[bh*S + r0]     = rsum0 * (0.125f / (float)S) - rmax0 * 0.125f * inv_log;
        g_spars[bh*S + r0 + 8] = rsum1 * (0.125f / (float)S) - rmax1 * 0.125f * inv_log;
    }
}

// ---------------- iterative top-53 per (b,h), ties -> lowest index ----------------
__global__ void topk_kernel() {
    __shared__ float vals[S];
    __shared__ float bm[256];
    __shared__ int   bi[256];
    int bh = blockIdx.x, tid = threadIdx.x;
    for (int i = tid; i < S; i += 256) vals[i] = g_spars[bh*S + i];
    __syncthreads();
    for (int it = 0; it < U; it++) {
        float best = -1e30f; int bidx = S;
        for (int i = tid; i < S; i += 256) {
            float v = vals[i];
            if (v > best || (v == best && i < bidx)) { best = v; bidx = i; }
        }
        bm[tid] = best; bi[tid] = bidx;
        __syncthreads();
        for (int off = 128; off > 0; off >>= 1) {
            if (tid < off) {
                float v2 = bm[tid+off]; int i2 = bi[tid+off];
                if (v2 > bm[tid] || (v2 == bm[tid] && i2 < bi[tid])) { bm[tid] = v2; bi[tid] = i2; }
            }
            __syncthreads();
        }
        if (tid == 0) { g_topidx[bh*U + it] = bi[0]; vals[bi[0]] = -1e30f; }
        __syncthreads();
    }
}

// ---------------- meanV / base row ----------------
__global__ void meanv_kernel(const float* __restrict__ wv, const float* __restrict__ bv) {
    __shared__ float xs[D];
    int b = blockIdx.x, tid = threadIdx.x;
    xs[tid] = g_xsum[b*D + tid];
    __syncthreads();
    const float* wr = wv + (size_t)tid * D;
    float acc = 0.f;
    #pragma unroll 8
    for (int d = 0; d < D; d++) acc += xs[d] * wr[d];
    g_meanV[b*D + tid] = acc * (1.0f / (float)S) + bv[tid];
}

__global__ void ybase_kernel(const float* __restrict__ wo, const float* __restrict__ bo) {
    __shared__ float ms[D];
    int b = blockIdx.x, tid = threadIdx.x;
    ms[tid] = g_meanV[b*D + tid];
    __syncthreads();
    const float* wr = wo + (size_t)tid * D;
    float acc = 0.f;
    #pragma unroll 8
    for (int d = 0; d < D; d++) acc += ms[d] * wr[d];
    g_ybase[b*D + tid] = acc + bo[tid];
}

// ---------------- corrections for rows i < U ----------------
__global__ void corr_kernel(const float* __restrict__ x, const float* __restrict__ wv,
                            const float* __restrict__ bv) {
    __shared__ float xj[D];
    __shared__ float wvs[64][65];
    __shared__ float sred[64];
    int blk = blockIdx.x;
    int b = blk / (H*U);
    int rem = blk % (H*U);
    int h = rem / U;
    int i = rem % U;
    int tid = threadIdx.x;
    int bh = b*H + h;
    int j = g_topidx[bh*U + i];
    for (int t = tid; t < D; t += 64) xj[t] = x[((size_t)b*S + j)*D + t];
    sred[tid] = g_Q[((size_t)bh*S + i)*DK + tid] * g_K[((size_t)bh*S + j)*DK + tid];
    __syncthreads();
    for (int off = 32; off > 0; off >>= 1) {
        if (tid < off) sred[tid] += sred[tid + off];
        __syncthreads();
    }
    float v = sred[0] * 0.125f;
    float acc = 0.f;
    for (int dt = 0; dt < 8; dt++) {
        __syncthreads();
        #pragma unroll 8
        for (int r = 0; r < 64; r++)
            wvs[r][tid] = wv[((size_t)(h*64 + r))*D + dt*64 + tid];
        __syncthreads();
        #pragma unroll 16
        for (int dd = 0; dd < 64; dd++)
            acc += xj[dt*64 + dd] * wvs[tid][dd];
    }
    float Vj = acc + bv[h*64 + tid];
    float ev = expf(v);
    float Z = ev + (float)(S - 1);
    float mv = g_meanV[b*D + h*64 + tid];
    g_outcat[((size_t)(b*U + i))*D + h*64 + tid] = ((float)S * mv + (ev - 1.0f) * Vj) / Z;
}

// ---------------- out-projection for the 212 corrected rows ----------------
__global__ void outproj_kernel(const float* __restrict__ wo, const float* __restrict__ bo,
                               float* __restrict__ y) {
    __shared__ float As[32][68];
    __shared__ float Bs[32][68];
    int tid = threadIdx.x;
    int tx = tid & 15, ty = tid >> 4;
    int m0 = blockIdx.x * 64;
    int n0 = blockIdx.y * 64;
    float acc[4][4] = {};
    for (int d0 = 0; d0 < D; d0 += 32) {
        #pragma unroll
        for (int i = 0; i < 2; i++) {
            int e = tid + i*256;
            int row = e >> 3;
            int c4 = e & 7;
            float4 v = make_float4(0.f, 0.f, 0.f, 0.f);
            if (m0 + row < B*U)
                v = *(const float4*)(g_outcat + (size_t)(m0+row)*D + d0 + c4*4);
            As[c4*4+0][row] = v.x; As[c4*4+1][row] = v.y;
            As[c4*4+2][row] = v.z; As[c4*4+3][row] = v.w;
            float4 u = *(const float4*)(wo + (size_t)(n0+row)*D + d0 + c4*4);
            Bs[c4*4+0][row] = u.x; Bs[c4*4+1][row] = u.y;
            Bs[c4*4+2][row] = u.z; Bs[c4*4+3][row] = u.w;
        }
        __syncthreads();
        #pragma unroll
        for (int kk = 0; kk < 32; kk++) {
            float4 a = *(const float4*)&As[kk][tx*4];
            float4 bv4 = *(const float4*)&Bs[kk][ty*4];
            float av[4] = {a.x, a.y, a.z, a.w};
            float bw[4] = {bv4.x, bv4.y, bv4.z, bv4.w};
            #pragma unroll
            for (int i = 0; i < 4; i++)
                #pragma unroll
                for (int j = 0; j < 4; j++)
                    acc[i][j] += av[i] * bw[j];
        }
        __syncthreads();
    }
    #pragma unroll
    for (int i = 0; i < 4; i++) {
        int m = m0 + tx*4 + i;
        if (m < B*U) {
            int b = m / U, s = m % U;
            float* op = y + ((size_t)b*S + s)*D + n0 + ty*4;
            #pragma unroll
            for (int j = 0; j < 4; j++)
                op[j] = acc[i][j] + bo[n0 + ty*4 + j];
        }
    }
}

// ---------------- broadcast the uniform rows (s >= U) ----------------
__global__ void bcast_kernel(float* __restrict__ y) {
    int id = blockIdx.x * blockDim.x + threadIdx.x;
    const int per_b = (S - U) * (D/4);
    const int total = B * per_b;
    if (id >= total) return;
    int b = id / per_b;
    int r = id % per_b;
    int s = U + r / (D/4);
    int d4 = r % (D/4);
    float4 v = *(const float4*)(g_ybase + b*D + d4*4);
    *(float4*)(y + ((size_t)b*S + s)*D + d4*4) = v;
}

extern "C" void kernel_launch(void* const* d_in, const int* in_sizes, int n_in,
                              void* d_out, int out_size) {
    const float* x  = (const float*)d_in[0];
    const float* wq = (const float*)d_in[1];
    const float* bq = (const float*)d_in[2];
    const float* wk = (const float*)d_in[3];
    const float* bk = (const float*)d_in[4];
    const float* wv = (const float*)d_in[5];
    const float* bv = (const float*)d_in[6];
    const float* wo = (const float*)d_in[7];
    const float* bo = (const float*)d_in[8];
    float* y = (float*)d_out;

    cudaFuncSetAttribute(scores_mma_kernel, cudaFuncAttributeMaxDynamicSharedMemorySize, SM_TOTAL);

    sumx_part_kernel<<<B*8, 512>>>(x);
    sumx_final_kernel<<<B, 512>>>();

    dim3 pg(B*S/64, D/64);
    proj_kernel<<<pg, 256>>>(x, wq, bq, 0);
    proj_kernel<<<pg, 256>>>(x, wk, bk, 1);

    {
        const int total = 2*BH*S*DK/8;
        convert_kernel<<<(total + 255)/256, 256>>>();
    }

    dim3 sg(BH, 16);
    scores_mma_kernel<<<sg, 256, SM_TOTAL>>>();

    topk_kernel<<<BH, 256>>>();

    meanv_kernel<<<B, 512>>>(wv, bv);
    ybase_kernel<<<B, 512>>>(wo, bo);

    corr_kernel<<<B*H*U, 64>>>(x, wv, bv);

    dim3 og((B*U + 63)/64, D/64);
    outproj_kernel<<<og, 256>>>(wo, bo, y);

    const int per_b = (S - U) * (D/4);
    bcast_kernel<<<(B*per_b + 255)/256, 256>>>(y);
}

// round 6
// speedup vs baseline: 1.7415x; 1.2780x over previous
#include <cuda_runtime.h>
#include <cuda_bf16.h>
#include <math.h>
#include <stdint.h>

#define B 4
#define S 2048
#define D 512
#define H 8
#define DK 64
#define U 53
#define BH (B*H)

// ---------------- scratch (static device allocations; no cudaMalloc) ----------------
__device__ float g_Q[B*H*S*DK];       // [bh][s][k] fp32 (needed by corr)
__device__ float g_K[B*H*S*DK];
__device__ float g_spars[B*H*S];
__device__ int   g_topidx[B*H*U];
__device__ float g_xpart[8*B*D];
__device__ float g_xsum[B*D];
__device__ float g_meanV[B*D];
__device__ float g_ybase[B*D];
__device__ float g_outcat[B*U*D];
// split bf16 Q/K operands, row-major [bh][s][64] (written by proj epilogue)
__device__ __nv_bfloat16 g_Qhi[BH*S*DK];
__device__ __nv_bfloat16 g_Qlo[BH*S*DK];
__device__ __nv_bfloat16 g_Khi[BH*S*DK];
__device__ __nv_bfloat16 g_Klo[BH*S*DK];
// split bf16 inputs for proj mma
__device__ __nv_bfloat16 g_xhi[B*S*D];
__device__ __nv_bfloat16 g_xlo[B*S*D];
__device__ __nv_bfloat16 g_wqhi[D*D];
__device__ __nv_bfloat16 g_wqlo[D*D];
__device__ __nv_bfloat16 g_wkhi[D*D];
__device__ __nv_bfloat16 g_wklo[D*D];

// ================= warp-mma helpers (sm_80+ path, works on plain sm_100) =================
__device__ __forceinline__ uint32_t smem_u32(const void* p) {
    uint32_t a;
    asm("{ .reg .u64 t; cvta.to.shared.u64 t, %1; cvt.u32.u64 %0, t; }" : "=r"(a) : "l"(p));
    return a;
}

__device__ __forceinline__ void ldsm_x4(uint32_t& r0, uint32_t& r1, uint32_t& r2, uint32_t& r3, uint32_t addr) {
    asm volatile("ldmatrix.sync.aligned.m8n8.x4.shared.b16 {%0,%1,%2,%3}, [%4];"
        : "=r"(r0), "=r"(r1), "=r"(r2), "=r"(r3) : "r"(addr));
}
__device__ __forceinline__ void mma_bf16(float& c0, float& c1, float& c2, float& c3,
                                         uint32_t a0, uint32_t a1, uint32_t a2, uint32_t a3,
                                         uint32_t b0, uint32_t b1) {
    asm volatile("mma.sync.aligned.m16n8k16.row.col.f32.bf16.bf16.f32 "
        "{%0,%1,%2,%3}, {%4,%5,%6,%7}, {%8,%9}, {%0,%1,%2,%3};"
        : "+f"(c0), "+f"(c1), "+f"(c2), "+f"(c3)
        : "r"(a0), "r"(a1), "r"(a2), "r"(a3), "r"(b0), "r"(b1));
}
#define CP_ASYNC16(dst, src) \
    asm volatile("cp.async.cg.shared.global [%0], [%1], 16;" :: "r"(dst), "l"(src))
#define CP_COMMIT() asm volatile("cp.async.commit_group;" ::: "memory")
#define CP_WAIT1()  asm volatile("cp.async.wait_group 1;" ::: "memory")

// ---------------- column sums of x ----------------
__global__ void sumx_part_kernel(const float* __restrict__ x) {
    int blk = blockIdx.x;
    int b = blk >> 3, sc = blk & 7;
    int d = threadIdx.x;
    const float* p = x + ((size_t)b*S + sc*256)*D + d;
    float acc = 0.f;
    #pragma unroll 4
    for (int s = 0; s < 256; s++) acc += p[(size_t)s*D];
    g_xpart[(size_t)blk*D + d] = acc;
}

__global__ void sumx_final_kernel() {
    int b = blockIdx.x, d = threadIdx.x;
    float acc = 0.f;
    #pragma unroll
    for (int sc = 0; sc < 8; sc++) acc += g_xpart[(size_t)(b*8+sc)*D + d];
    g_xsum[b*D + d] = acc;
}

// ---------------- fp32 -> split-bf16 for x, wq, wk ----------------
#define XU (B*S*D/8)      // 524288
#define WU (D*D/8)        // 32768
__global__ void convert_xw_kernel(const float* __restrict__ x, const float* __restrict__ wq,
                                  const float* __restrict__ wk) {
    int id = blockIdx.x * blockDim.x + threadIdx.x;
    if (id >= XU + 2*WU) return;
    const float* src;
    __nv_bfloat16 *dh, *dl;
    int u;
    if (id < XU)                { u = id;            src = x  + (size_t)u*8; dh = g_xhi;  dl = g_xlo;  }
    else if (id < XU + WU)      { u = id - XU;       src = wq + (size_t)u*8; dh = g_wqhi; dl = g_wqlo; }
    else                        { u = id - XU - WU;  src = wk + (size_t)u*8; dh = g_wkhi; dl = g_wklo; }
    float4 a = *(const float4*)src;
    float4 b4 = *(const float4*)(src + 4);
    float vs[8] = {a.x, a.y, a.z, a.w, b4.x, b4.y, b4.z, b4.w};
    union { __nv_bfloat16 h[8]; int4 v; } hi, lo;
    #pragma unroll
    for (int i = 0; i < 8; i++) {
        hi.h[i] = __float2bfloat16(vs[i]);
        lo.h[i] = __float2bfloat16(vs[i] - __bfloat162float(hi.h[i]));
    }
    ((int4*)dh)[u] = hi.v;
    ((int4*)dl)[u] = lo.v;
}

// ---------------- Q/K projection via warp-mma (3-term split bf16) ----------------
// grid (64, 4): CTA = 128 rows (m) x 128 cols (n). K=512 streamed in 64-chunks,
// 2-stage cp.async pipeline. 8 warps x m16. Epilogue writes fp32 + hi/lo bf16.
#define PJ_STAGE 65536          // xhi 16K | xlo 16K | whi 16K | wlo 16K
#define PJ_XHI 0
#define PJ_XLO 16384
#define PJ_WHI 32768
#define PJ_WLO 49152
#define PJ_SM_TOTAL (2*PJ_STAGE)  // 128 KB

// copy 128 rows x 64 bf16 (128B/row) from global (row stride 1024B) into swizzled smem
__device__ __forceinline__ void pj_copy(uint32_t sdst, const __nv_bfloat16* g0, int tid) {
    #pragma unroll
    for (int i = 0; i < 4; i++) {
        int u = tid + i*256;
        int row = u >> 3, cu = u & 7;
        uint32_t dst = sdst + row*128 + ((cu ^ (row & 7)) << 4);
        CP_ASYNC16(dst, (const char*)g0 + (size_t)row*1024 + cu*16);
    }
}

__global__ void __launch_bounds__(256) proj_mma_kernel(const float* __restrict__ bias, int which) {
    extern __shared__ char smem[];
    uint32_t sb = smem_u32(smem);
    int tid = threadIdx.x;
    int w = tid >> 5, lane = tid & 31;
    int m0 = blockIdx.x * 128;
    int n0 = blockIdx.y * 128;

    const __nv_bfloat16* xhi = g_xhi + (size_t)m0*D;
    const __nv_bfloat16* xlo = g_xlo + (size_t)m0*D;
    const __nv_bfloat16* whi = (which ? g_wkhi : g_wqhi) + (size_t)n0*D;
    const __nv_bfloat16* wlo = (which ? g_wklo : g_wqlo) + (size_t)n0*D;
    float* outf = which ? g_K : g_Q;
    __nv_bfloat16* outh = which ? g_Khi : g_Qhi;
    __nv_bfloat16* outl = which ? g_Klo : g_Qlo;

    // prologue: chunks 0 and 1
    pj_copy(sb + 0*PJ_STAGE + PJ_XHI, xhi, tid);
    pj_copy(sb + 0*PJ_STAGE + PJ_XLO, xlo, tid);
    pj_copy(sb + 0*PJ_STAGE + PJ_WHI, whi, tid);
    pj_copy(sb + 0*PJ_STAGE + PJ_WLO, wlo, tid);
    CP_COMMIT();
    pj_copy(sb + 1*PJ_STAGE + PJ_XHI, xhi + 64, tid);
    pj_copy(sb + 1*PJ_STAGE + PJ_XLO, xlo + 64, tid);
    pj_copy(sb + 1*PJ_STAGE + PJ_WHI, whi + 64, tid);
    pj_copy(sb + 1*PJ_STAGE + PJ_WLO, wlo + 64, tid);
    CP_COMMIT();

    float c[16][4];
    #pragma unroll
    for (int j = 0; j < 16; j++)
        #pragma unroll
        for (int r = 0; r < 4; r++) c[j][r] = 0.f;

    int row16 = lane & 15;
    int half = lane >> 4;
    int bi = lane >> 3;
    int br = lane & 7;

    #pragma unroll 1
    for (int kt = 0; kt < 8; kt++) {
        CP_WAIT1();
        __syncthreads();
        uint32_t st = sb + (kt & 1)*PJ_STAGE;

        // A fragments: 4 k16-steps, hi+lo
        uint32_t aHi[4][4], aLo[4][4];
        {
            uint32_t rowoff = (uint32_t)(w*16 + row16) * 128;
            #pragma unroll
            for (int ks = 0; ks < 4; ks++) {
                uint32_t unit = (uint32_t)(ks*2 + half);
                uint32_t off = rowoff + ((unit ^ (row16 & 7)) << 4);
                ldsm_x4(aHi[ks][0], aHi[ks][1], aHi[ks][2], aHi[ks][3], st + PJ_XHI + off);
                ldsm_x4(aLo[ks][0], aLo[ks][1], aLo[ks][2], aLo[ks][3], st + PJ_XLO + off);
            }
        }

        #pragma unroll
        for (int j = 0; j < 16; j++) {
            int row = j*8 + br;
            uint32_t rowoff = (uint32_t)row * 128;
            uint32_t sw0 = ((uint32_t)(bi    ) ^ (row & 7)) << 4;
            uint32_t sw1 = ((uint32_t)(bi + 4) ^ (row & 7)) << 4;
            uint32_t bh0,bh1,bh2,bh3,bh4,bh5,bh6,bh7;
            uint32_t bl0,bl1,bl2,bl3,bl4,bl5,bl6,bl7;
            ldsm_x4(bh0,bh1,bh2,bh3, st + PJ_WHI + rowoff + sw0);
            ldsm_x4(bh4,bh5,bh6,bh7, st + PJ_WHI + rowoff + sw1);
            ldsm_x4(bl0,bl1,bl2,bl3, st + PJ_WLO + rowoff + sw0);
            ldsm_x4(bl4,bl5,bl6,bl7, st + PJ_WLO + rowoff + sw1);

            mma_bf16(c[j][0],c[j][1],c[j][2],c[j][3], aHi[0][0],aHi[0][1],aHi[0][2],aHi[0][3], bh0,bh1);
            mma_bf16(c[j][0],c[j][1],c[j][2],c[j][3], aHi[1][0],aHi[1][1],aHi[1][2],aHi[1][3], bh2,bh3);
            mma_bf16(c[j][0],c[j][1],c[j][2],c[j][3], aHi[2][0],aHi[2][1],aHi[2][2],aHi[2][3], bh4,bh5);
            mma_bf16(c[j][0],c[j][1],c[j][2],c[j][3], aHi[3][0],aHi[3][1],aHi[3][2],aHi[3][3], bh6,bh7);
            mma_bf16(c[j][0],c[j][1],c[j][2],c[j][3], aHi[0][0],aHi[0][1],aHi[0][2],aHi[0][3], bl0,bl1);
            mma_bf16(c[j][0],c[j][1],c[j][2],c[j][3], aHi[1][0],aHi[1][1],aHi[1][2],aHi[1][3], bl2,bl3);
            mma_bf16(c[j][0],c[j][1],c[j][2],c[j][3], aHi[2][0],aHi[2][1],aHi[2][2],aHi[2][3], bl4,bl5);
            mma_bf16(c[j][0],c[j][1],c[j][2],c[j][3], aHi[3][0],aHi[3][1],aHi[3][2],aHi[3][3], bl6,bl7);
            mma_bf16(c[j][0],c[j][1],c[j][2],c[j][3], aLo[0][0],aLo[0][1],aLo[0][2],aLo[0][3], bh0,bh1);
            mma_bf16(c[j][0],c[j][1],c[j][2],c[j][3], aLo[1][0],aLo[1][1],aLo[1][2],aLo[1][3], bh2,bh3);
            mma_bf16(c[j][0],c[j][1],c[j][2],c[j][3], aLo[2][0],aLo[2][1],aLo[2][2],aLo[2][3], bh4,bh5);
            mma_bf16(c[j][0],c[j][1],c[j][2],c[j][3], aLo[3][0],aLo[3][1],aLo[3][2],aLo[3][3], bh6,bh7);
        }
        __syncthreads();
        if (kt + 2 < 8) {
            uint32_t st2 = sb + (kt & 1)*PJ_STAGE;
            int koff = (kt + 2) * 64;
            pj_copy(st2 + PJ_XHI, xhi + koff, tid);
            pj_copy(st2 + PJ_XLO, xlo + koff, tid);
            pj_copy(st2 + PJ_WHI, whi + koff, tid);
            pj_copy(st2 + PJ_WLO, wlo + koff, tid);
        }
        CP_COMMIT();
    }

    // epilogue: bias + write fp32 and hi/lo bf16 into [bh][s][64] layout
    int r0 = m0 + w*16 + (lane >> 2);
    #pragma unroll
    for (int j = 0; j < 16; j++) {
        int n = n0 + j*8 + (lane & 3)*2;
        int h = n >> 6, k = n & 63;
        float b0 = bias[n], b1 = bias[n+1];
        #pragma unroll
        for (int rr = 0; rr < 2; rr++) {
            int m = r0 + rr*8;
            int b_ = m >> 11, s = m & (S-1);
            size_t idx = (((size_t)(b_*H + h)*S + s)*DK) + k;
            float v0 = c[j][rr*2+0] + b0;
            float v1 = c[j][rr*2+1] + b1;
            *(float2*)(outf + idx) = make_float2(v0, v1);
            union { __nv_bfloat16 h2[2]; uint32_t u; } ph, pl;
            ph.h2[0] = __float2bfloat16(v0);
            ph.h2[1] = __float2bfloat16(v1);
            pl.h2[0] = __float2bfloat16(v0 - __bfloat162float(ph.h2[0]));
            pl.h2[1] = __float2bfloat16(v1 - __bfloat162float(ph.h2[1]));
            *(uint32_t*)(outh + idx) = ph.u;
            *(uint32_t*)(outl + idx) = pl.u;
        }
    }
}

// ---------------- warp-mma QK^T row-max/row-mean -> sparsity (3-term) ----------------
#define SQ_HI 0
#define SQ_LO 16384
#define SK_BASE 32768
#define SK_STAGE 32768
#define SM_TOTAL (SK_BASE + 2*SK_STAGE)   // 96 KB

__device__ __forceinline__ void copy_tile_async(uint32_t sdst, const __nv_bfloat16* gsrc, int tid) {
    #pragma unroll
    for (int i = 0; i < 4; i++) {
        int u = tid + i*256;
        int row = u >> 3, cu = u & 7;
        uint32_t dst = sdst + row*128 + ((cu ^ (row & 7)) << 4);
        CP_ASYNC16(dst, (const char*)gsrc + (size_t)u*16);
    }
}

__global__ void __launch_bounds__(256) scores_mma_kernel() {
    extern __shared__ char smem[];
    uint32_t sb = smem_u32(smem);
    int tid = threadIdx.x;
    int w = tid >> 5, lane = tid & 31;
    int bh = blockIdx.x;
    int qt = blockIdx.y;

    const __nv_bfloat16* qh_g = g_Qhi + (size_t)(bh*S + qt*128)*DK;
    const __nv_bfloat16* ql_g = g_Qlo + (size_t)(bh*S + qt*128)*DK;
    const __nv_bfloat16* kh_g = g_Khi + (size_t)bh*S*DK;
    const __nv_bfloat16* kl_g = g_Klo + (size_t)bh*S*DK;

    copy_tile_async(sb + SQ_HI, qh_g, tid);
    copy_tile_async(sb + SQ_LO, ql_g, tid);
    copy_tile_async(sb + SK_BASE + 0*SK_STAGE,         kh_g, tid);
    copy_tile_async(sb + SK_BASE + 0*SK_STAGE + 16384, kl_g, tid);
    CP_COMMIT();
    copy_tile_async(sb + SK_BASE + 1*SK_STAGE,         kh_g + 128*DK, tid);
    copy_tile_async(sb + SK_BASE + 1*SK_STAGE + 16384, kl_g + 128*DK, tid);
    CP_COMMIT();

    CP_WAIT1();
    __syncthreads();

    uint32_t aHi[4][4], aLo[4][4];
    {
        int row16 = lane & 15;
        int half = lane >> 4;
        uint32_t rowoff = (uint32_t)(w*16 + row16) * 128;
        #pragma unroll
        for (int ks = 0; ks < 4; ks++) {
            uint32_t unit = (uint32_t)(ks*2 + half);
            uint32_t off = rowoff + ((unit ^ (row16 & 7)) << 4);
            ldsm_x4(aHi[ks][0], aHi[ks][1], aHi[ks][2], aHi[ks][3], sb + SQ_HI + off);
            ldsm_x4(aLo[ks][0], aLo[ks][1], aLo[ks][2], aLo[ks][3], sb + SQ_LO + off);
        }
    }

    float rmax0 = -1e30f, rmax1 = -1e30f, rsum0 = 0.f, rsum1 = 0.f;
    int bi = lane >> 3;
    int br = lane & 7;

    #pragma unroll 1
    for (int kt = 0; kt < 16; kt++) {
        if (kt > 0) {
            CP_WAIT1();
            __syncthreads();
        }
        uint32_t kb_hi = sb + SK_BASE + (kt & 1)*SK_STAGE;
        uint32_t kb_lo = kb_hi + 16384;

        #pragma unroll
        for (int t = 0; t < 16; t++) {
            int row = t*8 + br;
            uint32_t rowoff = (uint32_t)row * 128;
            uint32_t sw0 = ((uint32_t)(bi    ) ^ (row & 7)) << 4;
            uint32_t sw1 = ((uint32_t)(bi + 4) ^ (row & 7)) << 4;
            uint32_t bh0,bh1,bh2,bh3,bh4,bh5,bh6,bh7;
            uint32_t bl0,bl1,bl2,bl3,bl4,bl5,bl6,bl7;
            ldsm_x4(bh0,bh1,bh2,bh3, kb_hi + rowoff + sw0);
            ldsm_x4(bh4,bh5,bh6,bh7, kb_hi + rowoff + sw1);
            ldsm_x4(bl0,bl1,bl2,bl3, kb_lo + rowoff + sw0);
            ldsm_x4(bl4,bl5,bl6,bl7, kb_lo + rowoff + sw1);

            float c0=0.f, c1=0.f, c2=0.f, c3=0.f;
            mma_bf16(c0,c1,c2,c3, aHi[0][0],aHi[0][1],aHi[0][2],aHi[0][3], bh0,bh1);
            mma_bf16(c0,c1,c2,c3, aHi[1][0],aHi[1][1],aHi[1][2],aHi[1][3], bh2,bh3);
            mma_bf16(c0,c1,c2,c3, aHi[2][0],aHi[2][1],aHi[2][2],aHi[2][3], bh4,bh5);
            mma_bf16(c0,c1,c2,c3, aHi[3][0],aHi[3][1],aHi[3][2],aHi[3][3], bh6,bh7);
            mma_bf16(c0,c1,c2,c3, aHi[0][0],aHi[0][1],aHi[0][2],aHi[0][3], bl0,bl1);
            mma_bf16(c0,c1,c2,c3, aHi[1][0],aHi[1][1],aHi[1][2],aHi[1][3], bl2,bl3);
            mma_bf16(c0,c1,c2,c3, aHi[2][0],aHi[2][1],aHi[2][2],aHi[2][3], bl4,bl5);
            mma_bf16(c0,c1,c2,c3, aHi[3][0],aHi[3][1],aHi[3][2],aHi[3][3], bl6,bl7);
            mma_bf16(c0,c1,c2,c3, aLo[0][0],aLo[0][1],aLo[0][2],aLo[0][3], bh0,bh1);
            mma_bf16(c0,c1,c2,c3, aLo[1][0],aLo[1][1],aLo[1][2],aLo[1][3], bh2,bh3);
            mma_bf16(c0,c1,c2,c3, aLo[2][0],aLo[2][1],aLo[2][2],aLo[2][3], bh4,bh5);
            mma_bf16(c0,c1,c2,c3, aLo[3][0],aLo[3][1],aLo[3][2],aLo[3][3], bh6,bh7);

            rmax0 = fmaxf(rmax0, fmaxf(c0, c1));
            rsum0 += c0 + c1;
            rmax1 = fmaxf(rmax1, fmaxf(c2, c3));
            rsum1 += c2 + c3;
        }
        __syncthreads();
        if (kt + 2 < 16) {
            copy_tile_async(sb + SK_BASE + (kt & 1)*SK_STAGE,         kh_g + (size_t)(kt+2)*128*DK, tid);
            copy_tile_async(sb + SK_BASE + (kt & 1)*SK_STAGE + 16384, kl_g + (size_t)(kt+2)*128*DK, tid);
        }
        CP_COMMIT();
    }

    #pragma unroll
    for (int off = 1; off < 4; off <<= 1) {
        rmax0 = fmaxf(rmax0, __shfl_xor_sync(0xFFFFFFFFu, rmax0, off));
        rsum0 += __shfl_xor_sync(0xFFFFFFFFu, rsum0, off);
        rmax1 = fmaxf(rmax1, __shfl_xor_sync(0xFFFFFFFFu, rmax1, off));
        rsum1 += __shfl_xor_sync(0xFFFFFFFFu, rsum1, off);
    }
    if ((lane & 3) == 0) {
        int r0 = qt*128 + w*16 + (lane >> 2);
        float inv_log = 1.0f / logf((float)S);
        g_spars[bh*S + r0]     = rsum0 * (0.125f / (float)S) - rmax0 * 0.125f * inv_log;
        g_spars[bh*S + r0 + 8] = rsum1 * (0.125f / (float)S) - rmax1 * 0.125f * inv_log;
    }
}

// ---------------- iterative top-53 per (b,h), ties -> lowest index ----------------
__global__ void topk_kernel() {
    __shared__ float vals[S];
    __shared__ float bm[256];
    __shared__ int   bi[256];
    int bh = blockIdx.x, tid = threadIdx.x;
    for (int i = tid; i < S; i += 256) vals[i] = g_spars[bh*S + i];
    __syncthreads();
    for (int it = 0; it < U; it++) {
        float best = -1e30f; int bidx = S;
        for (int i = tid; i < S; i += 256) {
            float v = vals[i];
            if (v > best || (v == best && i < bidx)) { best = v; bidx = i; }
        }
        bm[tid] = best; bi[tid] = bidx;
        __syncthreads();
        for (int off = 128; off > 0; off >>= 1) {
            if (tid < off) {
                float v2 = bm[tid+off]; int i2 = bi[tid+off];
                if (v2 > bm[tid] || (v2 == bm[tid] && i2 < bi[tid])) { bm[tid] = v2; bi[tid] = i2; }
            }
            __syncthreads();
        }
        if (tid == 0) { g_topidx[bh*U + it] = bi[0]; vals[bi[0]] = -1e30f; }
        __syncthreads();
    }
}

// ---------------- meanV / base row ----------------
__global__ void meanv_kernel(const float* __restrict__ wv, const float* __restrict__ bv) {
    __shared__ float xs[D];
    int b = blockIdx.x, tid = threadIdx.x;
    xs[tid] = g_xsum[b*D + tid];
    __syncthreads();
    const float* wr = wv + (size_t)tid * D;
    float acc = 0.f;
    #pragma unroll 8
    for (int d = 0; d < D; d++) acc += xs[d] * wr[d];
    g_meanV[b*D + tid] = acc * (1.0f / (float)S) + bv[tid];
}

__global__ void ybase_kernel(const float* __restrict__ wo, const float* __restrict__ bo) {
    __shared__ float ms[D];
    int b = blockIdx.x, tid = threadIdx.x;
    ms[tid] = g_meanV[b*D + tid];
    __syncthreads();
    const float* wr = wo + (size_t)tid * D;
    float acc = 0.f;
    #pragma unroll 8
    for (int d = 0; d < D; d++) acc += ms[d] * wr[d];
    g_ybase[b*D + tid] = acc + bo[tid];
}

// ---------------- corrections for rows i < U ----------------
__global__ void corr_kernel(const float* __restrict__ x, const float* __restrict__ wv,
                            const float* __restrict__ bv) {
    __shared__ float xj[D];
    __shared__ float wvs[64][65];
    __shared__ float sred[64];
    int blk = blockIdx.x;
    int b = blk / (H*U);
    int rem = blk % (H*U);
    int h = rem / U;
    int i = rem % U;
    int tid = threadIdx.x;
    int bh = b*H + h;
    int j = g_topidx[bh*U + i];
    for (int t = tid; t < D; t += 64) xj[t] = x[((size_t)b*S + j)*D + t];
    sred[tid] = g_Q[((size_t)bh*S + i)*DK + tid] * g_K[((size_t)bh*S + j)*DK + tid];
    __syncthreads();
    for (int off = 32; off > 0; off >>= 1) {
        if (tid < off) sred[tid] += sred[tid + off];
        __syncthreads();
    }
    float v = sred[0] * 0.125f;
    float acc = 0.f;
    for (int dt = 0; dt < 8; dt++) {
        __syncthreads();
        #pragma unroll 8
        for (int r = 0; r < 64; r++)
            wvs[r][tid] = wv[((size_t)(h*64 + r))*D + dt*64 + tid];
        __syncthreads();
        #pragma unroll 16
        for (int dd = 0; dd < 64; dd++)
            acc += xj[dt*64 + dd] * wvs[tid][dd];
    }
    float Vj = acc + bv[h*64 + tid];
    float ev = expf(v);
    float Z = ev + (float)(S - 1);
    float mv = g_meanV[b*D + h*64 + tid];
    g_outcat[((size_t)(b*U + i))*D + h*64 + tid] = ((float)S * mv + (ev - 1.0f) * Vj) / Z;
}

// ---------------- out-projection for the 212 corrected rows ----------------
__global__ void outproj_kernel(const float* __restrict__ wo, const float* __restrict__ bo,
                               float* __restrict__ y) {
    __shared__ float As[32][68];
    __shared__ float Bs[32][68];
    int tid = threadIdx.x;
    int tx = tid & 15, ty = tid >> 4;
    int m0 = blockIdx.x * 64;
    int n0 = blockIdx.y * 64;
    float acc[4][4] = {};
    for (int d0 = 0; d0 < D; d0 += 32) {
        #pragma unroll
        for (int i = 0; i < 2; i++) {
            int e = tid + i*256;
            int row = e >> 3;
            int c4 = e & 7;
            float4 v = make_float4(0.f, 0.f, 0.f, 0.f);
            if (m0 + row < B*U)
                v = *(const float4*)(g_outcat + (size_t)(m0+row)*D + d0 + c4*4);
            As[c4*4+0][row] = v.x; As[c4*4+1][row] = v.y;
            As[c4*4+2][row] = v.z; As[c4*4+3][row] = v.w;
            float4 u = *(const float4*)(wo + (size_t)(n0+row)*D + d0 + c4*4);
            Bs[c4*4+0][row] = u.x; Bs[c4*4+1][row] = u.y;
            Bs[c4*4+2][row] = u.z; Bs[c4*4+3][row] = u.w;
        }
        __syncthreads();
        #pragma unroll
        for (int kk = 0; kk < 32; kk++) {
            float4 a = *(const float4*)&As[kk][tx*4];
            float4 bv4 = *(const float4*)&Bs[kk][ty*4];
            float av[4] = {a.x, a.y, a.z, a.w};
            float bw[4] = {bv4.x, bv4.y, bv4.z, bv4.w};
            #pragma unroll
            for (int i = 0; i < 4; i++)
                #pragma unroll
                for (int j = 0; j < 4; j++)
                    acc[i][j] += av[i] * bw[j];
        }
        __syncthreads();
    }
    #pragma unroll
    for (int i = 0; i < 4; i++) {
        int m = m0 + tx*4 + i;
        if (m < B*U) {
            int b = m / U, s = m % U;
            float* op = y + ((size_t)b*S + s)*D + n0 + ty*4;
            #pragma unroll
            for (int j = 0; j < 4; j++)
                op[j] = acc[i][j] + bo[n0 + ty*4 + j];
        }
    }
}

// ---------------- broadcast the uniform rows (s >= U) ----------------
__global__ void bcast_kernel(float* __restrict__ y) {
    int id = blockIdx.x * blockDim.x + threadIdx.x;
    const int per_b = (S - U) * (D/4);
    const int total = B * per_b;
    if (id >= total) return;
    int b = id / per_b;
    int r = id % per_b;
    int s = U + r / (D/4);
    int d4 = r % (D/4);
    float4 v = *(const float4*)(g_ybase + b*D + d4*4);
    *(float4*)(y + ((size_t)b*S + s)*D + d4*4) = v;
}

extern "C" void kernel_launch(void* const* d_in, const int* in_sizes, int n_in,
                              void* d_out, int out_size) {
    const float* x  = (const float*)d_in[0];
    const float* wq = (const float*)d_in[1];
    const float* bq = (const float*)d_in[2];
    const float* wk = (const float*)d_in[3];
    const float* bk = (const float*)d_in[4];
    const float* wv = (const float*)d_in[5];
    const float* bv = (const float*)d_in[6];
    const float* wo = (const float*)d_in[7];
    const float* bo = (const float*)d_in[8];
    float* y = (float*)d_out;

    cudaFuncSetAttribute(scores_mma_kernel, cudaFuncAttributeMaxDynamicSharedMemorySize, SM_TOTAL);
    cudaFuncSetAttribute(proj_mma_kernel, cudaFuncAttributeMaxDynamicSharedMemorySize, PJ_SM_TOTAL);

    sumx_part_kernel<<<B*8, 512>>>(x);
    sumx_final_kernel<<<B, 512>>>();

    {
        const int total = XU + 2*WU;
        convert_xw_kernel<<<(total + 255)/256, 256>>>(x, wq, wk);
    }

    dim3 pg(B*S/128, D/128);
    proj_mma_kernel<<<pg, 256, PJ_SM_TOTAL>>>(bq, 0);
    proj_mma_kernel<<<pg, 256, PJ_SM_TOTAL>>>(bk, 1);

    dim3 sg(BH, 16);
    scores_mma_kernel<<<sg, 256, SM_TOTAL>>>();

    topk_kernel<<<BH, 256>>>();

    meanv_kernel<<<B, 512>>>(wv, bv);
    ybase_kernel<<<B, 512>>>(wo, bo);

    corr_kernel<<<B*H*U, 64>>>(x, wv, bv);

    dim3 og((B*U + 63)/64, D/64);
    outproj_kernel<<<og, 256>>>(wo, bo, y);

    const int per_b = (S - U) * (D/4);
    bcast_kernel<<<(B*per_b + 255)/256, 256>>>(y);
}

// round 7
// speedup vs baseline: 1.8398x; 1.0564x over previous
#include <cuda_runtime.h>
#include <cuda_bf16.h>
#include <math.h>
#include <stdint.h>

#define B 4
#define S 2048
#define D 512
#define H 8
#define DK 64
#define U 53
#define BH (B*H)

// ---------------- scratch (static device allocations; no cudaMalloc) ----------------
__device__ float g_Q[B*H*S*DK];       // [bh][s][k] fp32 (needed by corr)
__device__ float g_K[B*H*S*DK];
__device__ float g_spars[B*H*S];
__device__ int   g_topidx[B*H*U];
__device__ float g_xpart[8*B*D];
__device__ float g_xsum[B*D];
__device__ float g_meanV[B*D];
__device__ float g_ybase[B*D];
__device__ float g_outcat[B*U*D];
// split bf16 Q/K operands, row-major [bh][s][64] (written by proj epilogue)
__device__ __nv_bfloat16 g_Qhi[BH*S*DK];
__device__ __nv_bfloat16 g_Qlo[BH*S*DK];
__device__ __nv_bfloat16 g_Khi[BH*S*DK];
__device__ __nv_bfloat16 g_Klo[BH*S*DK];
// split bf16 inputs for proj mma
__device__ __nv_bfloat16 g_xhi[B*S*D];
__device__ __nv_bfloat16 g_xlo[B*S*D];
__device__ __nv_bfloat16 g_wqhi[D*D];
__device__ __nv_bfloat16 g_wqlo[D*D];
__device__ __nv_bfloat16 g_wkhi[D*D];
__device__ __nv_bfloat16 g_wklo[D*D];

// ================= warp-mma helpers (sm_80+ path, works on plain sm_100) =================
__device__ __forceinline__ uint32_t smem_u32(const void* p) {
    uint32_t a;
    asm("{ .reg .u64 t; cvta.to.shared.u64 t, %1; cvt.u32.u64 %0, t; }" : "=r"(a) : "l"(p));
    return a;
}

__device__ __forceinline__ void ldsm_x4(uint32_t& r0, uint32_t& r1, uint32_t& r2, uint32_t& r3, uint32_t addr) {
    asm volatile("ldmatrix.sync.aligned.m8n8.x4.shared.b16 {%0,%1,%2,%3}, [%4];"
        : "=r"(r0), "=r"(r1), "=r"(r2), "=r"(r3) : "r"(addr));
}
__device__ __forceinline__ void mma_bf16(float& c0, float& c1, float& c2, float& c3,
                                         uint32_t a0, uint32_t a1, uint32_t a2, uint32_t a3,
                                         uint32_t b0, uint32_t b1) {
    asm volatile("mma.sync.aligned.m16n8k16.row.col.f32.bf16.bf16.f32 "
        "{%0,%1,%2,%3}, {%4,%5,%6,%7}, {%8,%9}, {%0,%1,%2,%3};"
        : "+f"(c0), "+f"(c1), "+f"(c2), "+f"(c3)
        : "r"(a0), "r"(a1), "r"(a2), "r"(a3), "r"(b0), "r"(b1));
}
#define CP_ASYNC16(dst, src) \
    asm volatile("cp.async.cg.shared.global [%0], [%1], 16;" :: "r"(dst), "l"(src))
#define CP_COMMIT() asm volatile("cp.async.commit_group;" ::: "memory")
#define CP_WAIT1()  asm volatile("cp.async.wait_group 1;" ::: "memory")

// ---------------- column sums of x ----------------
__global__ void sumx_part_kernel(const float* __restrict__ x) {
    int blk = blockIdx.x;
    int b = blk >> 3, sc = blk & 7;
    int d = threadIdx.x;
    const float* p = x + ((size_t)b*S + sc*256)*D + d;
    float acc = 0.f;
    #pragma unroll 4
    for (int s = 0; s < 256; s++) acc += p[(size_t)s*D];
    g_xpart[(size_t)blk*D + d] = acc;
}

__global__ void sumx_final_kernel() {
    int b = blockIdx.x, d = threadIdx.x;
    float acc = 0.f;
    #pragma unroll
    for (int sc = 0; sc < 8; sc++) acc += g_xpart[(size_t)(b*8+sc)*D + d];
    g_xsum[b*D + d] = acc;
}

// ---------------- fp32 -> split-bf16 for x, wq, wk ----------------
#define XU (B*S*D/8)      // 524288
#define WU (D*D/8)        // 32768
__global__ void convert_xw_kernel(const float* __restrict__ x, const float* __restrict__ wq,
                                  const float* __restrict__ wk) {
    int id = blockIdx.x * blockDim.x + threadIdx.x;
    if (id >= XU + 2*WU) return;
    const float* src;
    __nv_bfloat16 *dh, *dl;
    int u;
    if (id < XU)                { u = id;            src = x  + (size_t)u*8; dh = g_xhi;  dl = g_xlo;  }
    else if (id < XU + WU)      { u = id - XU;       src = wq + (size_t)u*8; dh = g_wqhi; dl = g_wqlo; }
    else                        { u = id - XU - WU;  src = wk + (size_t)u*8; dh = g_wkhi; dl = g_wklo; }
    float4 a = *(const float4*)src;
    float4 b4 = *(const float4*)(src + 4);
    float vs[8] = {a.x, a.y, a.z, a.w, b4.x, b4.y, b4.z, b4.w};
    union { __nv_bfloat16 h[8]; int4 v; } hi, lo;
    #pragma unroll
    for (int i = 0; i < 8; i++) {
        hi.h[i] = __float2bfloat16(vs[i]);
        lo.h[i] = __float2bfloat16(vs[i] - __bfloat162float(hi.h[i]));
    }
    ((int4*)dh)[u] = hi.v;
    ((int4*)dl)[u] = lo.v;
}

// ---------------- Q/K projection via warp-mma (3-term split bf16) ----------------
#define PJ_STAGE 65536          // xhi 16K | xlo 16K | whi 16K | wlo 16K
#define PJ_XHI 0
#define PJ_XLO 16384
#define PJ_WHI 32768
#define PJ_WLO 49152
#define PJ_SM_TOTAL (2*PJ_STAGE)  // 128 KB

__device__ __forceinline__ void pj_copy(uint32_t sdst, const __nv_bfloat16* g0, int tid) {
    #pragma unroll
    for (int i = 0; i < 4; i++) {
        int u = tid + i*256;
        int row = u >> 3, cu = u & 7;
        uint32_t dst = sdst + row*128 + ((cu ^ (row & 7)) << 4);
        CP_ASYNC16(dst, (const char*)g0 + (size_t)row*1024 + cu*16);
    }
}

__global__ void __launch_bounds__(256) proj_mma_kernel(const float* __restrict__ bias, int which) {
    extern __shared__ char smem[];
    uint32_t sb = smem_u32(smem);
    int tid = threadIdx.x;
    int w = tid >> 5, lane = tid & 31;
    int m0 = blockIdx.x * 128;
    int n0 = blockIdx.y * 128;

    const __nv_bfloat16* xhi = g_xhi + (size_t)m0*D;
    const __nv_bfloat16* xlo = g_xlo + (size_t)m0*D;
    const __nv_bfloat16* whi = (which ? g_wkhi : g_wqhi) + (size_t)n0*D;
    const __nv_bfloat16* wlo = (which ? g_wklo : g_wqlo) + (size_t)n0*D;
    float* outf = which ? g_K : g_Q;
    __nv_bfloat16* outh = which ? g_Khi : g_Qhi;
    __nv_bfloat16* outl = which ? g_Klo : g_Qlo;

    pj_copy(sb + 0*PJ_STAGE + PJ_XHI, xhi, tid);
    pj_copy(sb + 0*PJ_STAGE + PJ_XLO, xlo, tid);
    pj_copy(sb + 0*PJ_STAGE + PJ_WHI, whi, tid);
    pj_copy(sb + 0*PJ_STAGE + PJ_WLO, wlo, tid);
    CP_COMMIT();
    pj_copy(sb + 1*PJ_STAGE + PJ_XHI, xhi + 64, tid);
    pj_copy(sb + 1*PJ_STAGE + PJ_XLO, xlo + 64, tid);
    pj_copy(sb + 1*PJ_STAGE + PJ_WHI, whi + 64, tid);
    pj_copy(sb + 1*PJ_STAGE + PJ_WLO, wlo + 64, tid);
    CP_COMMIT();

    float c[16][4];
    #pragma unroll
    for (int j = 0; j < 16; j++)
        #pragma unroll
        for (int r = 0; r < 4; r++) c[j][r] = 0.f;

    int row16 = lane & 15;
    int half = lane >> 4;
    int bi = lane >> 3;
    int br = lane & 7;

    #pragma unroll 1
    for (int kt = 0; kt < 8; kt++) {
        CP_WAIT1();
        __syncthreads();
        uint32_t st = sb + (kt & 1)*PJ_STAGE;

        uint32_t aHi[4][4], aLo[4][4];
        {
            uint32_t rowoff = (uint32_t)(w*16 + row16) * 128;
            #pragma unroll
            for (int ks = 0; ks < 4; ks++) {
                uint32_t unit = (uint32_t)(ks*2 + half);
                uint32_t off = rowoff + ((unit ^ (row16 & 7)) << 4);
                ldsm_x4(aHi[ks][0], aHi[ks][1], aHi[ks][2], aHi[ks][3], st + PJ_XHI + off);
                ldsm_x4(aLo[ks][0], aLo[ks][1], aLo[ks][2], aLo[ks][3], st + PJ_XLO + off);
            }
        }

        #pragma unroll
        for (int j = 0; j < 16; j++) {
            int row = j*8 + br;
            uint32_t rowoff = (uint32_t)row * 128;
            uint32_t sw0 = ((uint32_t)(bi    ) ^ (row & 7)) << 4;
            uint32_t sw1 = ((uint32_t)(bi + 4) ^ (row & 7)) << 4;
            uint32_t bh0,bh1,bh2,bh3,bh4,bh5,bh6,bh7;
            uint32_t bl0,bl1,bl2,bl3,bl4,bl5,bl6,bl7;
            ldsm_x4(bh0,bh1,bh2,bh3, st + PJ_WHI + rowoff + sw0);
            ldsm_x4(bh4,bh5,bh6,bh7, st + PJ_WHI + rowoff + sw1);
            ldsm_x4(bl0,bl1,bl2,bl3, st + PJ_WLO + rowoff + sw0);
            ldsm_x4(bl4,bl5,bl6,bl7, st + PJ_WLO + rowoff + sw1);

            mma_bf16(c[j][0],c[j][1],c[j][2],c[j][3], aHi[0][0],aHi[0][1],aHi[0][2],aHi[0][3], bh0,bh1);
            mma_bf16(c[j][0],c[j][1],c[j][2],c[j][3], aHi[1][0],aHi[1][1],aHi[1][2],aHi[1][3], bh2,bh3);
            mma_bf16(c[j][0],c[j][1],c[j][2],c[j][3], aHi[2][0],aHi[2][1],aHi[2][2],aHi[2][3], bh4,bh5);
            mma_bf16(c[j][0],c[j][1],c[j][2],c[j][3], aHi[3][0],aHi[3][1],aHi[3][2],aHi[3][3], bh6,bh7);
            mma_bf16(c[j][0],c[j][1],c[j][2],c[j][3], aHi[0][0],aHi[0][1],aHi[0][2],aHi[0][3], bl0,bl1);
            mma_bf16(c[j][0],c[j][1],c[j][2],c[j][3], aHi[1][0],aHi[1][1],aHi[1][2],aHi[1][3], bl2,bl3);
            mma_bf16(c[j][0],c[j][1],c[j][2],c[j][3], aHi[2][0],aHi[2][1],aHi[2][2],aHi[2][3], bl4,bl5);
            mma_bf16(c[j][0],c[j][1],c[j][2],c[j][3], aHi[3][0],aHi[3][1],aHi[3][2],aHi[3][3], bl6,bl7);
            mma_bf16(c[j][0],c[j][1],c[j][2],c[j][3], aLo[0][0],aLo[0][1],aLo[0][2],aLo[0][3], bh0,bh1);
            mma_bf16(c[j][0],c[j][1],c[j][2],c[j][3], aLo[1][0],aLo[1][1],aLo[1][2],aLo[1][3], bh2,bh3);
            mma_bf16(c[j][0],c[j][1],c[j][2],c[j][3], aLo[2][0],aLo[2][1],aLo[2][2],aLo[2][3], bh4,bh5);
            mma_bf16(c[j][0],c[j][1],c[j][2],c[j][3], aLo[3][0],aLo[3][1],aLo[3][2],aLo[3][3], bh6,bh7);
        }
        __syncthreads();
        if (kt + 2 < 8) {
            uint32_t st2 = sb + (kt & 1)*PJ_STAGE;
            int koff = (kt + 2) * 64;
            pj_copy(st2 + PJ_XHI, xhi + koff, tid);
            pj_copy(st2 + PJ_XLO, xlo + koff, tid);
            pj_copy(st2 + PJ_WHI, whi + koff, tid);
            pj_copy(st2 + PJ_WLO, wlo + koff, tid);
        }
        CP_COMMIT();
    }

    int r0 = m0 + w*16 + (lane >> 2);
    #pragma unroll
    for (int j = 0; j < 16; j++) {
        int n = n0 + j*8 + (lane & 3)*2;
        int h = n >> 6, k = n & 63;
        float b0 = bias[n], b1 = bias[n+1];
        #pragma unroll
        for (int rr = 0; rr < 2; rr++) {
            int m = r0 + rr*8;
            int b_ = m >> 11, s = m & (S-1);
            size_t idx = (((size_t)(b_*H + h)*S + s)*DK) + k;
            float v0 = c[j][rr*2+0] + b0;
            float v1 = c[j][rr*2+1] + b1;
            *(float2*)(outf + idx) = make_float2(v0, v1);
            union { __nv_bfloat16 h2[2]; uint32_t u; } ph, pl;
            ph.h2[0] = __float2bfloat16(v0);
            ph.h2[1] = __float2bfloat16(v1);
            pl.h2[0] = __float2bfloat16(v0 - __bfloat162float(ph.h2[0]));
            pl.h2[1] = __float2bfloat16(v1 - __bfloat162float(ph.h2[1]));
            *(uint32_t*)(outh + idx) = ph.u;
            *(uint32_t*)(outl + idx) = pl.u;
        }
    }
}

// ---------------- warp-mma QK^T row-max/row-mean -> sparsity (3-term, dual-accum) ----------------
#define SQ_HI 0
#define SQ_LO 16384
#define SK_BASE 32768
#define SK_STAGE 32768
#define SM_TOTAL (SK_BASE + 2*SK_STAGE)   // 96 KB

__device__ __forceinline__ void copy_tile_async(uint32_t sdst, const __nv_bfloat16* gsrc, int tid) {
    #pragma unroll
    for (int i = 0; i < 4; i++) {
        int u = tid + i*256;
        int row = u >> 3, cu = u & 7;
        uint32_t dst = sdst + row*128 + ((cu ^ (row & 7)) << 4);
        CP_ASYNC16(dst, (const char*)gsrc + (size_t)u*16);
    }
}

__global__ void __launch_bounds__(256) scores_mma_kernel() {
    extern __shared__ char smem[];
    uint32_t sb = smem_u32(smem);
    int tid = threadIdx.x;
    int w = tid >> 5, lane = tid & 31;
    int bh = blockIdx.x;
    int qt = blockIdx.y;

    const __nv_bfloat16* qh_g = g_Qhi + (size_t)(bh*S + qt*128)*DK;
    const __nv_bfloat16* ql_g = g_Qlo + (size_t)(bh*S + qt*128)*DK;
    const __nv_bfloat16* kh_g = g_Khi + (size_t)bh*S*DK;
    const __nv_bfloat16* kl_g = g_Klo + (size_t)bh*S*DK;

    copy_tile_async(sb + SQ_HI, qh_g, tid);
    copy_tile_async(sb + SQ_LO, ql_g, tid);
    copy_tile_async(sb + SK_BASE + 0*SK_STAGE,         kh_g, tid);
    copy_tile_async(sb + SK_BASE + 0*SK_STAGE + 16384, kl_g, tid);
    CP_COMMIT();
    copy_tile_async(sb + SK_BASE + 1*SK_STAGE,         kh_g + 128*DK, tid);
    copy_tile_async(sb + SK_BASE + 1*SK_STAGE + 16384, kl_g + 128*DK, tid);
    CP_COMMIT();

    CP_WAIT1();
    __syncthreads();

    uint32_t aHi[4][4], aLo[4][4];
    {
        int row16 = lane & 15;
        int half = lane >> 4;
        uint32_t rowoff = (uint32_t)(w*16 + row16) * 128;
        #pragma unroll
        for (int ks = 0; ks < 4; ks++) {
            uint32_t unit = (uint32_t)(ks*2 + half);
            uint32_t off = rowoff + ((unit ^ (row16 & 7)) << 4);
            ldsm_x4(aHi[ks][0], aHi[ks][1], aHi[ks][2], aHi[ks][3], sb + SQ_HI + off);
            ldsm_x4(aLo[ks][0], aLo[ks][1], aLo[ks][2], aLo[ks][3], sb + SQ_LO + off);
        }
    }

    float rmax0 = -1e30f, rmax1 = -1e30f, rsum0 = 0.f, rsum1 = 0.f;
    int bi = lane >> 3;
    int br = lane & 7;

    #pragma unroll 1
    for (int kt = 0; kt < 16; kt++) {
        if (kt > 0) {
            CP_WAIT1();
            __syncthreads();
        }
        uint32_t kb_hi = sb + SK_BASE + (kt & 1)*SK_STAGE;
        uint32_t kb_lo = kb_hi + 16384;

        #pragma unroll
        for (int t = 0; t < 16; t++) {
            int row = t*8 + br;
            uint32_t rowoff = (uint32_t)row * 128;
            uint32_t sw0 = ((uint32_t)(bi    ) ^ (row & 7)) << 4;
            uint32_t sw1 = ((uint32_t)(bi + 4) ^ (row & 7)) << 4;
            uint32_t bh0,bh1,bh2,bh3,bh4,bh5,bh6,bh7;
            uint32_t bl0,bl1,bl2,bl3,bl4,bl5,bl6,bl7;
            ldsm_x4(bh0,bh1,bh2,bh3, kb_hi + rowoff + sw0);
            ldsm_x4(bh4,bh5,bh6,bh7, kb_hi + rowoff + sw1);
            ldsm_x4(bl0,bl1,bl2,bl3, kb_lo + rowoff + sw0);
            ldsm_x4(bl4,bl5,bl6,bl7, kb_lo + rowoff + sw1);

            // two independent 6-MMA chains (same math as the 12-chain)
            float cA0=0.f, cA1=0.f, cA2=0.f, cA3=0.f;
            float cB0=0.f, cB1=0.f, cB2=0.f, cB3=0.f;
            mma_bf16(cA0,cA1,cA2,cA3, aHi[0][0],aHi[0][1],aHi[0][2],aHi[0][3], bh0,bh1);
            mma_bf16(cB0,cB1,cB2,cB3, aHi[0][0],aHi[0][1],aHi[0][2],aHi[0][3], bl0,bl1);
            mma_bf16(cA0,cA1,cA2,cA3, aHi[1][0],aHi[1][1],aHi[1][2],aHi[1][3], bh2,bh3);
            mma_bf16(cB0,cB1,cB2,cB3, aHi[1][0],aHi[1][1],aHi[1][2],aHi[1][3], bl2,bl3);
            mma_bf16(cA0,cA1,cA2,cA3, aHi[2][0],aHi[2][1],aHi[2][2],aHi[2][3], bh4,bh5);
            mma_bf16(cB0,cB1,cB2,cB3, aHi[2][0],aHi[2][1],aHi[2][2],aHi[2][3], bl4,bl5);
            mma_bf16(cA0,cA1,cA2,cA3, aHi[3][0],aHi[3][1],aHi[3][2],aHi[3][3], bh6,bh7);
            mma_bf16(cB0,cB1,cB2,cB3, aHi[3][0],aHi[3][1],aHi[3][2],aHi[3][3], bl6,bl7);
            mma_bf16(cA0,cA1,cA2,cA3, aLo[0][0],aLo[0][1],aLo[0][2],aLo[0][3], bh0,bh1);
            mma_bf16(cB0,cB1,cB2,cB3, aLo[2][0],aLo[2][1],aLo[2][2],aLo[2][3], bh4,bh5);
            mma_bf16(cA0,cA1,cA2,cA3, aLo[1][0],aLo[1][1],aLo[1][2],aLo[1][3], bh2,bh3);
            mma_bf16(cB0,cB1,cB2,cB3, aLo[3][0],aLo[3][1],aLo[3][2],aLo[3][3], bh6,bh7);

            float c0 = cA0 + cB0, c1 = cA1 + cB1, c2 = cA2 + cB2, c3 = cA3 + cB3;
            rmax0 = fmaxf(rmax0, fmaxf(c0, c1));
            rsum0 += c0 + c1;
            rmax1 = fmaxf(rmax1, fmaxf(c2, c3));
            rsum1 += c2 + c3;
        }
        __syncthreads();
        if (kt + 2 < 16) {
            copy_tile_async(sb + SK_BASE + (kt & 1)*SK_STAGE,         kh_g + (size_t)(kt+2)*128*DK, tid);
            copy_tile_async(sb + SK_BASE + (kt & 1)*SK_STAGE + 16384, kl_g + (size_t)(kt+2)*128*DK, tid);
        }
        CP_COMMIT();
    }

    #pragma unroll
    for (int off = 1; off < 4; off <<= 1) {
        rmax0 = fmaxf(rmax0, __shfl_xor_sync(0xFFFFFFFFu, rmax0, off));
        rsum0 += __shfl_xor_sync(0xFFFFFFFFu, rsum0, off);
        rmax1 = fmaxf(rmax1, __shfl_xor_sync(0xFFFFFFFFu, rmax1, off));
        rsum1 += __shfl_xor_sync(0xFFFFFFFFu, rsum1, off);
    }
    if ((lane & 3) == 0) {
        int r0 = qt*128 + w*16 + (lane >> 2);
        float inv_log = 1.0f / logf((float)S);
        g_spars[bh*S + r0]     = rsum0 * (0.125f / (float)S) - rmax0 * 0.125f * inv_log;
        g_spars[bh*S + r0 + 8] = rsum1 * (0.125f / (float)S) - rmax1 * 0.125f * inv_log;
    }
}

// ---------------- iterative top-53 per (b,h): warp-shuffle reduce, ties -> lowest index ----------------
__global__ void topk_kernel() {
    __shared__ float vals[S];
    __shared__ float wm[8];
    __shared__ int   wi[8];
    int bh = blockIdx.x, tid = threadIdx.x;
    int lane = tid & 31, wid = tid >> 5;
    for (int i = tid; i < S; i += 256) vals[i] = g_spars[bh*S + i];
    __syncthreads();
    for (int it = 0; it < U; it++) {
        float best = -1e30f; int bidx = S;
        #pragma unroll
        for (int k = 0; k < 8; k++) {
            int i = tid + k*256;
            float v = vals[i];
            if (v > best || (v == best && i < bidx)) { best = v; bidx = i; }
        }
        #pragma unroll
        for (int off = 16; off > 0; off >>= 1) {
            float v2 = __shfl_down_sync(0xFFFFFFFFu, best, off);
            int i2 = __shfl_down_sync(0xFFFFFFFFu, bidx, off);
            if (v2 > best || (v2 == best && i2 < bidx)) { best = v2; bidx = i2; }
        }
        if (lane == 0) { wm[wid] = best; wi[wid] = bidx; }
        __syncthreads();
        if (tid == 0) {
            float m = wm[0]; int mi = wi[0];
            #pragma unroll
            for (int t = 1; t < 8; t++)
                if (wm[t] > m || (wm[t] == m && wi[t] < mi)) { m = wm[t]; mi = wi[t]; }
            g_topidx[bh*U + it] = mi;
            vals[mi] = -1e30f;
        }
        __syncthreads();
    }
}

// ---------------- meanV / base row ----------------
__global__ void meanv_kernel(const float* __restrict__ wv, const float* __restrict__ bv) {
    __shared__ float xs[D];
    int b = blockIdx.x, tid = threadIdx.x;
    xs[tid] = g_xsum[b*D + tid];
    __syncthreads();
    const float* wr = wv + (size_t)tid * D;
    float acc = 0.f;
    #pragma unroll 8
    for (int d = 0; d < D; d++) acc += xs[d] * wr[d];
    g_meanV[b*D + tid] = acc * (1.0f / (float)S) + bv[tid];
}

__global__ void ybase_kernel(const float* __restrict__ wo, const float* __restrict__ bo) {
    __shared__ float ms[D];
    int b = blockIdx.x, tid = threadIdx.x;
    ms[tid] = g_meanV[b*D + tid];
    __syncthreads();
    const float* wr = wo + (size_t)tid * D;
    float acc = 0.f;
    #pragma unroll 8
    for (int d = 0; d < D; d++) acc += ms[d] * wr[d];
    g_ybase[b*D + tid] = acc + bo[tid];
}

// ---------------- corrections for rows i < U ----------------
__global__ void corr_kernel(const float* __restrict__ x, const float* __restrict__ wv,
                            const float* __restrict__ bv) {
    __shared__ float xj[D];
    __shared__ float wvs[64][65];
    __shared__ float sred[64];
    int blk = blockIdx.x;
    int b = blk / (H*U);
    int rem = blk % (H*U);
    int h = rem / U;
    int i = rem % U;
    int tid = threadIdx.x;
    int bh = b*H + h;
    int j = g_topidx[bh*U + i];
    for (int t = tid; t < D; t += 64) xj[t] = x[((size_t)b*S + j)*D + t];
    sred[tid] = g_Q[((size_t)bh*S + i)*DK + tid] * g_K[((size_t)bh*S + j)*DK + tid];
    __syncthreads();
    for (int off = 32; off > 0; off >>= 1) {
        if (tid < off) sred[tid] += sred[tid + off];
        __syncthreads();
    }
    float v = sred[0] * 0.125f;
    float acc = 0.f;
    for (int dt = 0; dt < 8; dt++) {
        __syncthreads();
        #pragma unroll 8
        for (int r = 0; r < 64; r++)
            wvs[r][tid] = wv[((size_t)(h*64 + r))*D + dt*64 + tid];
        __syncthreads();
        #pragma unroll 16
        for (int dd = 0; dd < 64; dd++)
            acc += xj[dt*64 + dd] * wvs[tid][dd];
    }
    float Vj = acc + bv[h*64 + tid];
    float ev = expf(v);
    float Z = ev + (float)(S - 1);
    float mv = g_meanV[b*D + h*64 + tid];
    g_outcat[((size_t)(b*U + i))*D + h*64 + tid] = ((float)S * mv + (ev - 1.0f) * Vj) / Z;
}

// ---------------- out-projection for the 212 corrected rows ----------------
__global__ void outproj_kernel(const float* __restrict__ wo, const float* __restrict__ bo,
                               float* __restrict__ y) {
    __shared__ float As[32][68];
    __shared__ float Bs[32][68];
    int tid = threadIdx.x;
    int tx = tid & 15, ty = tid >> 4;
    int m0 = blockIdx.x * 64;
    int n0 = blockIdx.y * 64;
    float acc[4][4] = {};
    for (int d0 = 0; d0 < D; d0 += 32) {
        #pragma unroll
        for (int i = 0; i < 2; i++) {
            int e = tid + i*256;
            int row = e >> 3;
            int c4 = e & 7;
            float4 v = make_float4(0.f, 0.f, 0.f, 0.f);
            if (m0 + row < B*U)
                v = *(const float4*)(g_outcat + (size_t)(m0+row)*D + d0 + c4*4);
            As[c4*4+0][row] = v.x; As[c4*4+1][row] = v.y;
            As[c4*4+2][row] = v.z; As[c4*4+3][row] = v.w;
            float4 u = *(const float4*)(wo + (size_t)(n0+row)*D + d0 + c4*4);
            Bs[c4*4+0][row] = u.x; Bs[c4*4+1][row] = u.y;
            Bs[c4*4+2][row] = u.z; Bs[c4*4+3][row] = u.w;
        }
        __syncthreads();
        #pragma unroll
        for (int kk = 0; kk < 32; kk++) {
            float4 a = *(const float4*)&As[kk][tx*4];
            float4 bv4 = *(const float4*)&Bs[kk][ty*4];
            float av[4] = {a.x, a.y, a.z, a.w};
            float bw[4] = {bv4.x, bv4.y, bv4.z, bv4.w};
            #pragma unroll
            for (int i = 0; i < 4; i++)
                #pragma unroll
                for (int j = 0; j < 4; j++)
                    acc[i][j] += av[i] * bw[j];
        }
        __syncthreads();
    }
    #pragma unroll
    for (int i = 0; i < 4; i++) {
        int m = m0 + tx*4 + i;
        if (m < B*U) {
            int b = m / U, s = m % U;
            float* op = y + ((size_t)b*S + s)*D + n0 + ty*4;
            #pragma unroll
            for (int j = 0; j < 4; j++)
                op[j] = acc[i][j] + bo[n0 + ty*4 + j];
        }
    }
}

// ---------------- broadcast the uniform rows (s >= U) ----------------
__global__ void bcast_kernel(float* __restrict__ y) {
    int id = blockIdx.x * blockDim.x + threadIdx.x;
    const int per_b = (S - U) * (D/4);
    const int total = B * per_b;
    if (id >= total) return;
    int b = id / per_b;
    int r = id % per_b;
    int s = U + r / (D/4);
    int d4 = r % (D/4);
    float4 v = *(const float4*)(g_ybase + b*D + d4*4);
    *(float4*)(y + ((size_t)b*S + s)*D + d4*4) = v;
}

extern "C" void kernel_launch(void* const* d_in, const int* in_sizes, int n_in,
                              void* d_out, int out_size) {
    const float* x  = (const float*)d_in[0];
    const float* wq = (const float*)d_in[1];
    const float* bq = (const float*)d_in[2];
    const float* wk = (const float*)d_in[3];
    const float* bk = (const float*)d_in[4];
    const float* wv = (const float*)d_in[5];
    const float* bv = (const float*)d_in[6];
    const float* wo = (const float*)d_in[7];
    const float* bo = (const float*)d_in[8];
    float* y = (float*)d_out;

    cudaFuncSetAttribute(scores_mma_kernel, cudaFuncAttributeMaxDynamicSharedMemorySize, SM_TOTAL);
    cudaFuncSetAttribute(proj_mma_kernel, cudaFuncAttributeMaxDynamicSharedMemorySize, PJ_SM_TOTAL);

    // Launch order arranged so scores_mma is user-launch #5 (ncu -s 5 -c 1
    // captures it, accounting for the harness's poison-memset at index 0).
    sumx_part_kernel<<<B*8, 512>>>(x);                                     // 1

    {
        const int total = XU + 2*WU;
        convert_xw_kernel<<<(total + 255)/256, 256>>>(x, wq, wk);          // 2
    }

    dim3 pg(B*S/128, D/128);
    proj_mma_kernel<<<pg, 256, PJ_SM_TOTAL>>>(bq, 0);                      // 3
    proj_mma_kernel<<<pg, 256, PJ_SM_TOTAL>>>(bk, 1);                      // 4

    dim3 sg(BH, 16);
    scores_mma_kernel<<<sg, 256, SM_TOTAL>>>();                            // 5 <- ncu

    sumx_final_kernel<<<B, 512>>>();                                       // 6

    topk_kernel<<<BH, 256>>>();                                            // 7

    meanv_kernel<<<B, 512>>>(wv, bv);                                      // 8
    ybase_kernel<<<B, 512>>>(wo, bo);                                      // 9

    corr_kernel<<<B*H*U, 64>>>(x, wv, bv);                                 // 10

    dim3 og((B*U + 63)/64, D/64);
    outproj_kernel<<<og, 256>>>(wo, bo, y);                                // 11

    const int per_b = (S - U) * (D/4);
    bcast_kernel<<<(B*per_b + 255)/256, 256>>>(y);                         // 12
}

// round 8
// speedup vs baseline: 1.8508x; 1.0060x over previous
#include <cuda_runtime.h>
#include <cuda_bf16.h>
#include <math.h>
#include <stdint.h>

#define B 4
#define S 2048
#define D 512
#define H 8
#define DK 64
#define U 53
#define BH (B*H)

// ---------------- scratch (static device allocations; no cudaMalloc) ----------------
__device__ float g_Q[B*H*S*DK];       // [bh][s][k] fp32 (needed by corr)
__device__ float g_K[B*H*S*DK];
__device__ float g_spars[B*H*S];
__device__ int   g_topidx[B*H*U];
__device__ float g_xpart[8*B*D];
__device__ float g_xsum[B*D];
__device__ float g_meanV[B*D];
__device__ float g_ybase[B*D];
__device__ float g_outcat[B*U*D];
// split bf16 Q/K operands, row-major [bh][s][64] (written by proj epilogue)
__device__ __nv_bfloat16 g_Qhi[BH*S*DK];
__device__ __nv_bfloat16 g_Qlo[BH*S*DK];
__device__ __nv_bfloat16 g_Khi[BH*S*DK];
__device__ __nv_bfloat16 g_Klo[BH*S*DK];
// split bf16 inputs for proj mma
__device__ __nv_bfloat16 g_xhi[B*S*D];
__device__ __nv_bfloat16 g_xlo[B*S*D];
__device__ __nv_bfloat16 g_wqhi[D*D];
__device__ __nv_bfloat16 g_wqlo[D*D];
__device__ __nv_bfloat16 g_wkhi[D*D];
__device__ __nv_bfloat16 g_wklo[D*D];

// ================= warp-mma helpers (sm_80+ path, works on plain sm_100) =================
__device__ __forceinline__ uint32_t smem_u32(const void* p) {
    uint32_t a;
    asm("{ .reg .u64 t; cvta.to.shared.u64 t, %1; cvt.u32.u64 %0, t; }" : "=r"(a) : "l"(p));
    return a;
}

__device__ __forceinline__ void ldsm_x4(uint32_t& r0, uint32_t& r1, uint32_t& r2, uint32_t& r3, uint32_t addr) {
    asm volatile("ldmatrix.sync.aligned.m8n8.x4.shared.b16 {%0,%1,%2,%3}, [%4];"
        : "=r"(r0), "=r"(r1), "=r"(r2), "=r"(r3) : "r"(addr));
}
__device__ __forceinline__ void mma_bf16(float& c0, float& c1, float& c2, float& c3,
                                         uint32_t a0, uint32_t a1, uint32_t a2, uint32_t a3,
                                         uint32_t b0, uint32_t b1) {
    asm volatile("mma.sync.aligned.m16n8k16.row.col.f32.bf16.bf16.f32 "
        "{%0,%1,%2,%3}, {%4,%5,%6,%7}, {%8,%9}, {%0,%1,%2,%3};"
        : "+f"(c0), "+f"(c1), "+f"(c2), "+f"(c3)
        : "r"(a0), "r"(a1), "r"(a2), "r"(a3), "r"(b0), "r"(b1));
}
#define CP_ASYNC16(dst, src) \
    asm volatile("cp.async.cg.shared.global [%0], [%1], 16;" :: "r"(dst), "l"(src))
#define CP_COMMIT() asm volatile("cp.async.commit_group;" ::: "memory")
#define CP_WAIT1()  asm volatile("cp.async.wait_group 1;" ::: "memory")

// ---------------- column sums of x ----------------
__global__ void sumx_part_kernel(const float* __restrict__ x) {
    int blk = blockIdx.x;
    int b = blk >> 3, sc = blk & 7;
    int d = threadIdx.x;
    const float* p = x + ((size_t)b*S + sc*256)*D + d;
    float acc = 0.f;
    #pragma unroll 4
    for (int s = 0; s < 256; s++) acc += p[(size_t)s*D];
    g_xpart[(size_t)blk*D + d] = acc;
}

__global__ void sumx_final_kernel() {
    int b = blockIdx.x, d = threadIdx.x;
    float acc = 0.f;
    #pragma unroll
    for (int sc = 0; sc < 8; sc++) acc += g_xpart[(size_t)(b*8+sc)*D + d];
    g_xsum[b*D + d] = acc;
}

// ---------------- fp32 -> split-bf16 for x, wq, wk ----------------
#define XU (B*S*D/8)      // 524288
#define WU (D*D/8)        // 32768
__global__ void convert_xw_kernel(const float* __restrict__ x, const float* __restrict__ wq,
                                  const float* __restrict__ wk) {
    int id = blockIdx.x * blockDim.x + threadIdx.x;
    if (id >= XU + 2*WU) return;
    const float* src;
    __nv_bfloat16 *dh, *dl;
    int u;
    if (id < XU)                { u = id;            src = x  + (size_t)u*8; dh = g_xhi;  dl = g_xlo;  }
    else if (id < XU + WU)      { u = id - XU;       src = wq + (size_t)u*8; dh = g_wqhi; dl = g_wqlo; }
    else                        { u = id - XU - WU;  src = wk + (size_t)u*8; dh = g_wkhi; dl = g_wklo; }
    float4 a = *(const float4*)src;
    float4 b4 = *(const float4*)(src + 4);
    float vs[8] = {a.x, a.y, a.z, a.w, b4.x, b4.y, b4.z, b4.w};
    union { __nv_bfloat16 h[8]; int4 v; } hi, lo;
    #pragma unroll
    for (int i = 0; i < 8; i++) {
        hi.h[i] = __float2bfloat16(vs[i]);
        lo.h[i] = __float2bfloat16(vs[i] - __bfloat162float(hi.h[i]));
    }
    ((int4*)dh)[u] = hi.v;
    ((int4*)dl)[u] = lo.v;
}

// ---------------- Q/K projection via warp-mma (3-term split bf16) ----------------
#define PJ_STAGE 65536          // xhi 16K | xlo 16K | whi 16K | wlo 16K
#define PJ_XHI 0
#define PJ_XLO 16384
#define PJ_WHI 32768
#define PJ_WLO 49152
#define PJ_SM_TOTAL (2*PJ_STAGE)  // 128 KB

__device__ __forceinline__ void pj_copy(uint32_t sdst, const __nv_bfloat16* g0, int tid) {
    #pragma unroll
    for (int i = 0; i < 4; i++) {
        int u = tid + i*256;
        int row = u >> 3, cu = u & 7;
        uint32_t dst = sdst + row*128 + ((cu ^ (row & 7)) << 4);
        CP_ASYNC16(dst, (const char*)g0 + (size_t)row*1024 + cu*16);
    }
}

__global__ void __launch_bounds__(256) proj_mma_kernel(const float* __restrict__ bias, int which) {
    extern __shared__ char smem[];
    uint32_t sb = smem_u32(smem);
    int tid = threadIdx.x;
    int w = tid >> 5, lane = tid & 31;
    int m0 = blockIdx.x * 128;
    int n0 = blockIdx.y * 128;

    const __nv_bfloat16* xhi = g_xhi + (size_t)m0*D;
    const __nv_bfloat16* xlo = g_xlo + (size_t)m0*D;
    const __nv_bfloat16* whi = (which ? g_wkhi : g_wqhi) + (size_t)n0*D;
    const __nv_bfloat16* wlo = (which ? g_wklo : g_wqlo) + (size_t)n0*D;
    float* outf = which ? g_K : g_Q;
    __nv_bfloat16* outh = which ? g_Khi : g_Qhi;
    __nv_bfloat16* outl = which ? g_Klo : g_Qlo;

    pj_copy(sb + 0*PJ_STAGE + PJ_XHI, xhi, tid);
    pj_copy(sb + 0*PJ_STAGE + PJ_XLO, xlo, tid);
    pj_copy(sb + 0*PJ_STAGE + PJ_WHI, whi, tid);
    pj_copy(sb + 0*PJ_STAGE + PJ_WLO, wlo, tid);
    CP_COMMIT();
    pj_copy(sb + 1*PJ_STAGE + PJ_XHI, xhi + 64, tid);
    pj_copy(sb + 1*PJ_STAGE + PJ_XLO, xlo + 64, tid);
    pj_copy(sb + 1*PJ_STAGE + PJ_WHI, whi + 64, tid);
    pj_copy(sb + 1*PJ_STAGE + PJ_WLO, wlo + 64, tid);
    CP_COMMIT();

    float c[16][4];
    #pragma unroll
    for (int j = 0; j < 16; j++)
        #pragma unroll
        for (int r = 0; r < 4; r++) c[j][r] = 0.f;

    int row16 = lane & 15;
    int half = lane >> 4;
    int bi = lane >> 3;
    int br = lane & 7;

    #pragma unroll 1
    for (int kt = 0; kt < 8; kt++) {
        CP_WAIT1();
        __syncthreads();
        uint32_t st = sb + (kt & 1)*PJ_STAGE;

        uint32_t aHi[4][4], aLo[4][4];
        {
            uint32_t rowoff = (uint32_t)(w*16 + row16) * 128;
            #pragma unroll
            for (int ks = 0; ks < 4; ks++) {
                uint32_t unit = (uint32_t)(ks*2 + half);
                uint32_t off = rowoff + ((unit ^ (row16 & 7)) << 4);
                ldsm_x4(aHi[ks][0], aHi[ks][1], aHi[ks][2], aHi[ks][3], st + PJ_XHI + off);
                ldsm_x4(aLo[ks][0], aLo[ks][1], aLo[ks][2], aLo[ks][3], st + PJ_XLO + off);
            }
        }

        #pragma unroll
        for (int j = 0; j < 16; j++) {
            int row = j*8 + br;
            uint32_t rowoff = (uint32_t)row * 128;
            uint32_t sw0 = ((uint32_t)(bi    ) ^ (row & 7)) << 4;
            uint32_t sw1 = ((uint32_t)(bi + 4) ^ (row & 7)) << 4;
            uint32_t bh0,bh1,bh2,bh3,bh4,bh5,bh6,bh7;
            uint32_t bl0,bl1,bl2,bl3,bl4,bl5,bl6,bl7;
            ldsm_x4(bh0,bh1,bh2,bh3, st + PJ_WHI + rowoff + sw0);
            ldsm_x4(bh4,bh5,bh6,bh7, st + PJ_WHI + rowoff + sw1);
            ldsm_x4(bl0,bl1,bl2,bl3, st + PJ_WLO + rowoff + sw0);
            ldsm_x4(bl4,bl5,bl6,bl7, st + PJ_WLO + rowoff + sw1);

            mma_bf16(c[j][0],c[j][1],c[j][2],c[j][3], aHi[0][0],aHi[0][1],aHi[0][2],aHi[0][3], bh0,bh1);
            mma_bf16(c[j][0],c[j][1],c[j][2],c[j][3], aHi[1][0],aHi[1][1],aHi[1][2],aHi[1][3], bh2,bh3);
            mma_bf16(c[j][0],c[j][1],c[j][2],c[j][3], aHi[2][0],aHi[2][1],aHi[2][2],aHi[2][3], bh4,bh5);
            mma_bf16(c[j][0],c[j][1],c[j][2],c[j][3], aHi[3][0],aHi[3][1],aHi[3][2],aHi[3][3], bh6,bh7);
            mma_bf16(c[j][0],c[j][1],c[j][2],c[j][3], aHi[0][0],aHi[0][1],aHi[0][2],aHi[0][3], bl0,bl1);
            mma_bf16(c[j][0],c[j][1],c[j][2],c[j][3], aHi[1][0],aHi[1][1],aHi[1][2],aHi[1][3], bl2,bl3);
            mma_bf16(c[j][0],c[j][1],c[j][2],c[j][3], aHi[2][0],aHi[2][1],aHi[2][2],aHi[2][3], bl4,bl5);
            mma_bf16(c[j][0],c[j][1],c[j][2],c[j][3], aHi[3][0],aHi[3][1],aHi[3][2],aHi[3][3], bl6,bl7);
            mma_bf16(c[j][0],c[j][1],c[j][2],c[j][3], aLo[0][0],aLo[0][1],aLo[0][2],aLo[0][3], bh0,bh1);
            mma_bf16(c[j][0],c[j][1],c[j][2],c[j][3], aLo[1][0],aLo[1][1],aLo[1][2],aLo[1][3], bh2,bh3);
            mma_bf16(c[j][0],c[j][1],c[j][2],c[j][3], aLo[2][0],aLo[2][1],aLo[2][2],aLo[2][3], bh4,bh5);
            mma_bf16(c[j][0],c[j][1],c[j][2],c[j][3], aLo[3][0],aLo[3][1],aLo[3][2],aLo[3][3], bh6,bh7);
        }
        __syncthreads();
        if (kt + 2 < 8) {
            uint32_t st2 = sb + (kt & 1)*PJ_STAGE;
            int koff = (kt + 2) * 64;
            pj_copy(st2 + PJ_XHI, xhi + koff, tid);
            pj_copy(st2 + PJ_XLO, xlo + koff, tid);
            pj_copy(st2 + PJ_WHI, whi + koff, tid);
            pj_copy(st2 + PJ_WLO, wlo + koff, tid);
        }
        CP_COMMIT();
    }

    int r0 = m0 + w*16 + (lane >> 2);
    #pragma unroll
    for (int j = 0; j < 16; j++) {
        int n = n0 + j*8 + (lane & 3)*2;
        int h = n >> 6, k = n & 63;
        float b0 = bias[n], b1 = bias[n+1];
        #pragma unroll
        for (int rr = 0; rr < 2; rr++) {
            int m = r0 + rr*8;
            int b_ = m >> 11, s = m & (S-1);
            size_t idx = (((size_t)(b_*H + h)*S + s)*DK) + k;
            float v0 = c[j][rr*2+0] + b0;
            float v1 = c[j][rr*2+1] + b1;
            *(float2*)(outf + idx) = make_float2(v0, v1);
            union { __nv_bfloat16 h2[2]; uint32_t u; } ph, pl;
            ph.h2[0] = __float2bfloat16(v0);
            ph.h2[1] = __float2bfloat16(v1);
            pl.h2[0] = __float2bfloat16(v0 - __bfloat162float(ph.h2[0]));
            pl.h2[1] = __float2bfloat16(v1 - __bfloat162float(ph.h2[1]));
            *(uint32_t*)(outh + idx) = ph.u;
            *(uint32_t*)(outl + idx) = pl.u;
        }
    }
}

// ---------------- warp-mma QK^T row-max/row-mean -> sparsity ----------------
// 128 threads, 4 warps, each warp handles m32 (two m16 row-blocks) so every
// B fragment feeds 24 MMAs instead of 12. Same grid (BH,16), same 96KB smem.
#define SQ_HI 0
#define SQ_LO 16384
#define SK_BASE 32768
#define SK_STAGE 32768
#define SM_TOTAL (SK_BASE + 2*SK_STAGE)   // 96 KB

__device__ __forceinline__ void copy_tile_async128(uint32_t sdst, const __nv_bfloat16* gsrc, int tid) {
    #pragma unroll
    for (int i = 0; i < 8; i++) {
        int u = tid + i*128;
        int row = u >> 3, cu = u & 7;
        uint32_t dst = sdst + row*128 + ((cu ^ (row & 7)) << 4);
        CP_ASYNC16(dst, (const char*)gsrc + (size_t)u*16);
    }
}

__global__ void __launch_bounds__(128) scores_mma_kernel() {
    extern __shared__ char smem[];
    uint32_t sb = smem_u32(smem);
    int tid = threadIdx.x;
    int w = tid >> 5, lane = tid & 31;
    int bh = blockIdx.x;
    int qt = blockIdx.y;

    const __nv_bfloat16* qh_g = g_Qhi + (size_t)(bh*S + qt*128)*DK;
    const __nv_bfloat16* ql_g = g_Qlo + (size_t)(bh*S + qt*128)*DK;
    const __nv_bfloat16* kh_g = g_Khi + (size_t)bh*S*DK;
    const __nv_bfloat16* kl_g = g_Klo + (size_t)bh*S*DK;

    copy_tile_async128(sb + SQ_HI, qh_g, tid);
    copy_tile_async128(sb + SQ_LO, ql_g, tid);
    copy_tile_async128(sb + SK_BASE + 0*SK_STAGE,         kh_g, tid);
    copy_tile_async128(sb + SK_BASE + 0*SK_STAGE + 16384, kl_g, tid);
    CP_COMMIT();
    copy_tile_async128(sb + SK_BASE + 1*SK_STAGE,         kh_g + 128*DK, tid);
    copy_tile_async128(sb + SK_BASE + 1*SK_STAGE + 16384, kl_g + 128*DK, tid);
    CP_COMMIT();

    CP_WAIT1();
    __syncthreads();

    // A fragments for both m16 row-blocks of this warp's m32
    uint32_t aHi[2][4][4], aLo[2][4][4];
    {
        int row16 = lane & 15;
        int half = lane >> 4;
        #pragma unroll
        for (int rb = 0; rb < 2; rb++) {
            uint32_t rowoff = (uint32_t)(w*32 + rb*16 + row16) * 128;
            #pragma unroll
            for (int ks = 0; ks < 4; ks++) {
                uint32_t unit = (uint32_t)(ks*2 + half);
                uint32_t off = rowoff + ((unit ^ (row16 & 7)) << 4);
                ldsm_x4(aHi[rb][ks][0], aHi[rb][ks][1], aHi[rb][ks][2], aHi[rb][ks][3], sb + SQ_HI + off);
                ldsm_x4(aLo[rb][ks][0], aLo[rb][ks][1], aLo[rb][ks][2], aLo[rb][ks][3], sb + SQ_LO + off);
            }
        }
    }

    float rmax0[2] = {-1e30f, -1e30f}, rmax1[2] = {-1e30f, -1e30f};
    float rsum0[2] = {0.f, 0.f},       rsum1[2] = {0.f, 0.f};
    int bi = lane >> 3;
    int br = lane & 7;

    #pragma unroll 1
    for (int kt = 0; kt < 16; kt++) {
        if (kt > 0) {
            CP_WAIT1();
            __syncthreads();
        }
        uint32_t kb_hi = sb + SK_BASE + (kt & 1)*SK_STAGE;
        uint32_t kb_lo = kb_hi + 16384;

        #pragma unroll
        for (int t = 0; t < 16; t++) {
            int row = t*8 + br;
            uint32_t rowoff = (uint32_t)row * 128;
            uint32_t sw0 = ((uint32_t)(bi    ) ^ (row & 7)) << 4;
            uint32_t sw1 = ((uint32_t)(bi + 4) ^ (row & 7)) << 4;
            uint32_t bh0,bh1,bh2,bh3,bh4,bh5,bh6,bh7;
            uint32_t bl0,bl1,bl2,bl3,bl4,bl5,bl6,bl7;
            ldsm_x4(bh0,bh1,bh2,bh3, kb_hi + rowoff + sw0);
            ldsm_x4(bh4,bh5,bh6,bh7, kb_hi + rowoff + sw1);
            ldsm_x4(bl0,bl1,bl2,bl3, kb_lo + rowoff + sw0);
            ldsm_x4(bl4,bl5,bl6,bl7, kb_lo + rowoff + sw1);

            #pragma unroll
            for (int rb = 0; rb < 2; rb++) {
                // two independent 6-MMA chains (same math as a 12-chain)
                float cA0=0.f, cA1=0.f, cA2=0.f, cA3=0.f;
                float cB0=0.f, cB1=0.f, cB2=0.f, cB3=0.f;
                mma_bf16(cA0,cA1,cA2,cA3, aHi[rb][0][0],aHi[rb][0][1],aHi[rb][0][2],aHi[rb][0][3], bh0,bh1);
                mma_bf16(cB0,cB1,cB2,cB3, aHi[rb][0][0],aHi[rb][0][1],aHi[rb][0][2],aHi[rb][0][3], bl0,bl1);
                mma_bf16(cA0,cA1,cA2,cA3, aHi[rb][1][0],aHi[rb][1][1],aHi[rb][1][2],aHi[rb][1][3], bh2,bh3);
                mma_bf16(cB0,cB1,cB2,cB3, aHi[rb][1][0],aHi[rb][1][1],aHi[rb][1][2],aHi[rb][1][3], bl2,bl3);
                mma_bf16(cA0,cA1,cA2,cA3, aHi[rb][2][0],aHi[rb][2][1],aHi[rb][2][2],aHi[rb][2][3], bh4,bh5);
                mma_bf16(cB0,cB1,cB2,cB3, aHi[rb][2][0],aHi[rb][2][1],aHi[rb][2][2],aHi[rb][2][3], bl4,bl5);
                mma_bf16(cA0,cA1,cA2,cA3, aHi[rb][3][0],aHi[rb][3][1],aHi[rb][3][2],aHi[rb][3][3], bh6,bh7);
                mma_bf16(cB0,cB1,cB2,cB3, aHi[rb][3][0],aHi[rb][3][1],aHi[rb][3][2],aHi[rb][3][3], bl6,bl7);
                mma_bf16(cA0,cA1,cA2,cA3, aLo[rb][0][0],aLo[rb][0][1],aLo[rb][0][2],aLo[rb][0][3], bh0,bh1);
                mma_bf16(cB0,cB1,cB2,cB3, aLo[rb][2][0],aLo[rb][2][1],aLo[rb][2][2],aLo[rb][2][3], bh4,bh5);
                mma_bf16(cA0,cA1,cA2,cA3, aLo[rb][1][0],aLo[rb][1][1],aLo[rb][1][2],aLo[rb][1][3], bh2,bh3);
                mma_bf16(cB0,cB1,cB2,cB3, aLo[rb][3][0],aLo[rb][3][1],aLo[rb][3][2],aLo[rb][3][3], bh6,bh7);

                float c0 = cA0 + cB0, c1 = cA1 + cB1, c2 = cA2 + cB2, c3 = cA3 + cB3;
                rmax0[rb] = fmaxf(rmax0[rb], fmaxf(c0, c1));
                rsum0[rb] += c0 + c1;
                rmax1[rb] = fmaxf(rmax1[rb], fmaxf(c2, c3));
                rsum1[rb] += c2 + c3;
            }
        }
        __syncthreads();
        if (kt + 2 < 16) {
            copy_tile_async128(sb + SK_BASE + (kt & 1)*SK_STAGE,         kh_g + (size_t)(kt+2)*128*DK, tid);
            copy_tile_async128(sb + SK_BASE + (kt & 1)*SK_STAGE + 16384, kl_g + (size_t)(kt+2)*128*DK, tid);
        }
        CP_COMMIT();
    }

    #pragma unroll
    for (int rb = 0; rb < 2; rb++) {
        float m0v = rmax0[rb], m1v = rmax1[rb], s0v = rsum0[rb], s1v = rsum1[rb];
        #pragma unroll
        for (int off = 1; off < 4; off <<= 1) {
            m0v = fmaxf(m0v, __shfl_xor_sync(0xFFFFFFFFu, m0v, off));
            s0v += __shfl_xor_sync(0xFFFFFFFFu, s0v, off);
            m1v = fmaxf(m1v, __shfl_xor_sync(0xFFFFFFFFu, m1v, off));
            s1v += __shfl_xor_sync(0xFFFFFFFFu, s1v, off);
        }
        if ((lane & 3) == 0) {
            int r0 = qt*128 + w*32 + rb*16 + (lane >> 2);
            float inv_log = 1.0f / logf((float)S);
            g_spars[bh*S + r0]     = s0v * (0.125f / (float)S) - m0v * 0.125f * inv_log;
            g_spars[bh*S + r0 + 8] = s1v * (0.125f / (float)S) - m1v * 0.125f * inv_log;
        }
    }
}

// ---------------- iterative top-53 per (b,h): warp-shuffle reduce, ties -> lowest index ----------------
__global__ void topk_kernel() {
    __shared__ float vals[S];
    __shared__ float wm[8];
    __shared__ int   wi[8];
    int bh = blockIdx.x, tid = threadIdx.x;
    int lane = tid & 31, wid = tid >> 5;
    for (int i = tid; i < S; i += 256) vals[i] = g_spars[bh*S + i];
    __syncthreads();
    for (int it = 0; it < U; it++) {
        float best = -1e30f; int bidx = S;
        #pragma unroll
        for (int k = 0; k < 8; k++) {
            int i = tid + k*256;
            float v = vals[i];
            if (v > best || (v == best && i < bidx)) { best = v; bidx = i; }
        }
        #pragma unroll
        for (int off = 16; off > 0; off >>= 1) {
            float v2 = __shfl_down_sync(0xFFFFFFFFu, best, off);
            int i2 = __shfl_down_sync(0xFFFFFFFFu, bidx, off);
            if (v2 > best || (v2 == best && i2 < bidx)) { best = v2; bidx = i2; }
        }
        if (lane == 0) { wm[wid] = best; wi[wid] = bidx; }
        __syncthreads();
        if (tid == 0) {
            float m = wm[0]; int mi = wi[0];
            #pragma unroll
            for (int t = 1; t < 8; t++)
                if (wm[t] > m || (wm[t] == m && wi[t] < mi)) { m = wm[t]; mi = wi[t]; }
            g_topidx[bh*U + it] = mi;
            vals[mi] = -1e30f;
        }
        __syncthreads();
    }
}

// ---------------- meanV / base row ----------------
__global__ void meanv_kernel(const float* __restrict__ wv, const float* __restrict__ bv) {
    __shared__ float xs[D];
    int b = blockIdx.x, tid = threadIdx.x;
    xs[tid] = g_xsum[b*D + tid];
    __syncthreads();
    const float* wr = wv + (size_t)tid * D;
    float acc = 0.f;
    #pragma unroll 8
    for (int d = 0; d < D; d++) acc += xs[d] * wr[d];
    g_meanV[b*D + tid] = acc * (1.0f / (float)S) + bv[tid];
}

__global__ void ybase_kernel(const float* __restrict__ wo, const float* __restrict__ bo) {
    __shared__ float ms[D];
    int b = blockIdx.x, tid = threadIdx.x;
    ms[tid] = g_meanV[b*D + tid];
    __syncthreads();
    const float* wr = wo + (size_t)tid * D;
    float acc = 0.f;
    #pragma unroll 8
    for (int d = 0; d < D; d++) acc += ms[d] * wr[d];
    g_ybase[b*D + tid] = acc + bo[tid];
}

// ---------------- corrections for rows i < U ----------------
__global__ void corr_kernel(const float* __restrict__ x, const float* __restrict__ wv,
                            const float* __restrict__ bv) {
    __shared__ float xj[D];
    __shared__ float wvs[64][65];
    __shared__ float sred[64];
    int blk = blockIdx.x;
    int b = blk / (H*U);
    int rem = blk % (H*U);
    int h = rem / U;
    int i = rem % U;
    int tid = threadIdx.x;
    int bh = b*H + h;
    int j = g_topidx[bh*U + i];
    for (int t = tid; t < D; t += 64) xj[t] = x[((size_t)b*S + j)*D + t];
    sred[tid] = g_Q[((size_t)bh*S + i)*DK + tid] * g_K[((size_t)bh*S + j)*DK + tid];
    __syncthreads();
    for (int off = 32; off > 0; off >>= 1) {
        if (tid < off) sred[tid] += sred[tid + off];
        __syncthreads();
    }
    float v = sred[0] * 0.125f;
    float acc = 0.f;
    for (int dt = 0; dt < 8; dt++) {
        __syncthreads();
        #pragma unroll 8
        for (int r = 0; r < 64; r++)
            wvs[r][tid] = wv[((size_t)(h*64 + r))*D + dt*64 + tid];
        __syncthreads();
        #pragma unroll 16
        for (int dd = 0; dd < 64; dd++)
            acc += xj[dt*64 + dd] * wvs[tid][dd];
    }
    float Vj = acc + bv[h*64 + tid];
    float ev = expf(v);
    float Z = ev + (float)(S - 1);
    float mv = g_meanV[b*D + h*64 + tid];
    g_outcat[((size_t)(b*U + i))*D + h*64 + tid] = ((float)S * mv + (ev - 1.0f) * Vj) / Z;
}

// ---------------- out-projection for the 212 corrected rows ----------------
__global__ void outproj_kernel(const float* __restrict__ wo, const float* __restrict__ bo,
                               float* __restrict__ y) {
    __shared__ float As[32][68];
    __shared__ float Bs[32][68];
    int tid = threadIdx.x;
    int tx = tid & 15, ty = tid >> 4;
    int m0 = blockIdx.x * 64;
    int n0 = blockIdx.y * 64;
    float acc[4][4] = {};
    for (int d0 = 0; d0 < D; d0 += 32) {
        #pragma unroll
        for (int i = 0; i < 2; i++) {
            int e = tid + i*256;
            int row = e >> 3;
            int c4 = e & 7;
            float4 v = make_float4(0.f, 0.f, 0.f, 0.f);
            if (m0 + row < B*U)
                v = *(const float4*)(g_outcat + (size_t)(m0+row)*D + d0 + c4*4);
            As[c4*4+0][row] = v.x; As[c4*4+1][row] = v.y;
            As[c4*4+2][row] = v.z; As[c4*4+3][row] = v.w;
            float4 u = *(const float4*)(wo + (size_t)(n0+row)*D + d0 + c4*4);
            Bs[c4*4+0][row] = u.x; Bs[c4*4+1][row] = u.y;
            Bs[c4*4+2][row] = u.z; Bs[c4*4+3][row] = u.w;
        }
        __syncthreads();
        #pragma unroll
        for (int kk = 0; kk < 32; kk++) {
            float4 a = *(const float4*)&As[kk][tx*4];
            float4 bv4 = *(const float4*)&Bs[kk][ty*4];
            float av[4] = {a.x, a.y, a.z, a.w};
            float bw[4] = {bv4.x, bv4.y, bv4.z, bv4.w};
            #pragma unroll
            for (int i = 0; i < 4; i++)
                #pragma unroll
                for (int j = 0; j < 4; j++)
                    acc[i][j] += av[i] * bw[j];
        }
        __syncthreads();
    }
    #pragma unroll
    for (int i = 0; i < 4; i++) {
        int m = m0 + tx*4 + i;
        if (m < B*U) {
            int b = m / U, s = m % U;
            float* op = y + ((size_t)b*S + s)*D + n0 + ty*4;
            #pragma unroll
            for (int j = 0; j < 4; j++)
                op[j] = acc[i][j] + bo[n0 + ty*4 + j];
        }
    }
}

// ---------------- broadcast the uniform rows (s >= U) ----------------
__global__ void bcast_kernel(float* __restrict__ y) {
    int id = blockIdx.x * blockDim.x + threadIdx.x;
    const int per_b = (S - U) * (D/4);
    const int total = B * per_b;
    if (id >= total) return;
    int b = id / per_b;
    int r = id % per_b;
    int s = U + r / (D/4);
    int d4 = r % (D/4);
    float4 v = *(const float4*)(g_ybase + b*D + d4*4);
    *(float4*)(y + ((size_t)b*S + s)*D + d4*4) = v;
}

extern "C" void kernel_launch(void* const* d_in, const int* in_sizes, int n_in,
                              void* d_out, int out_size) {
    const float* x  = (const float*)d_in[0];
    const float* wq = (const float*)d_in[1];
    const float* bq = (const float*)d_in[2];
    const float* wk = (const float*)d_in[3];
    const float* bk = (const float*)d_in[4];
    const float* wv = (const float*)d_in[5];
    const float* bv = (const float*)d_in[6];
    const float* wo = (const float*)d_in[7];
    const float* bo = (const float*)d_in[8];
    float* y = (float*)d_out;

    cudaFuncSetAttribute(scores_mma_kernel, cudaFuncAttributeMaxDynamicSharedMemorySize, SM_TOTAL);
    cudaFuncSetAttribute(proj_mma_kernel, cudaFuncAttributeMaxDynamicSharedMemorySize, PJ_SM_TOTAL);

    // Order chosen so scores_mma is user-launch #4: under the 2-prelaunch
    // hypothesis ncu (-s 5 -c 1) then captures it.
    {
        const int total = XU + 2*WU;
        convert_xw_kernel<<<(total + 255)/256, 256>>>(x, wq, wk);          // u1
    }

    dim3 pg(B*S/128, D/128);
    proj_mma_kernel<<<pg, 256, PJ_SM_TOTAL>>>(bq, 0);                      // u2
    proj_mma_kernel<<<pg, 256, PJ_SM_TOTAL>>>(bk, 1);                      // u3

    dim3 sg(BH, 16);
    scores_mma_kernel<<<sg, 128, SM_TOTAL>>>();                            // u4 <- ncu?

    sumx_part_kernel<<<B*8, 512>>>(x);                                     // u5
    sumx_final_kernel<<<B, 512>>>();                                       // u6

    topk_kernel<<<BH, 256>>>();                                            // u7

    meanv_kernel<<<B, 512>>>(wv, bv);                                      // u8
    ybase_kernel<<<B, 512>>>(wo, bo);                                      // u9

    corr_kernel<<<B*H*U, 64>>>(x, wv, bv);                                 // u10

    dim3 og((B*U + 63)/64, D/64);
    outproj_kernel<<<og, 256>>>(wo, bo, y);                                // u11

    const int per_b = (S - U) * (D/4);
    bcast_kernel<<<(B*per_b + 255)/256, 256>>>(y);                         // u12
}

// round 9
// speedup vs baseline: 2.6612x; 1.4379x over previous
#include <cuda_runtime.h>
#include <cuda_bf16.h>
#include <math.h>
#include <stdint.h>

#define B 4
#define S 2048
#define D 512
#define H 8
#define DK 64
#define U 53
#define BH (B*H)

// ---------------- scratch (static device allocations; no cudaMalloc) ----------------
__device__ float g_Q[B*H*S*DK];       // [bh][s][k] fp32 (needed by corr)
__device__ float g_K[B*H*S*DK];
__device__ float g_spars[B*H*S];
__device__ int   g_topidx[B*H*U];
__device__ float g_xpart[32*B*D];
__device__ float g_xsum[B*D];
__device__ float g_meanV[B*D];
__device__ float g_ybase[B*D];
__device__ float g_outcat[B*U*D];
// split bf16 Q/K operands, row-major [bh][s][64] (written by proj epilogue)
__device__ __nv_bfloat16 g_Qhi[BH*S*DK];
__device__ __nv_bfloat16 g_Qlo[BH*S*DK];
__device__ __nv_bfloat16 g_Khi[BH*S*DK];
__device__ __nv_bfloat16 g_Klo[BH*S*DK];
// split bf16 inputs for proj mma
__device__ __nv_bfloat16 g_xhi[B*S*D];
__device__ __nv_bfloat16 g_xlo[B*S*D];
__device__ __nv_bfloat16 g_wqhi[D*D];
__device__ __nv_bfloat16 g_wqlo[D*D];
__device__ __nv_bfloat16 g_wkhi[D*D];
__device__ __nv_bfloat16 g_wklo[D*D];

// ================= warp-mma helpers =================
__device__ __forceinline__ uint32_t smem_u32(const void* p) {
    uint32_t a;
    asm("{ .reg .u64 t; cvta.to.shared.u64 t, %1; cvt.u32.u64 %0, t; }" : "=r"(a) : "l"(p));
    return a;
}

__device__ __forceinline__ void ldsm_x4(uint32_t& r0, uint32_t& r1, uint32_t& r2, uint32_t& r3, uint32_t addr) {
    asm volatile("ldmatrix.sync.aligned.m8n8.x4.shared.b16 {%0,%1,%2,%3}, [%4];"
        : "=r"(r0), "=r"(r1), "=r"(r2), "=r"(r3) : "r"(addr));
}
__device__ __forceinline__ void mma_bf16(float& c0, float& c1, float& c2, float& c3,
                                         uint32_t a0, uint32_t a1, uint32_t a2, uint32_t a3,
                                         uint32_t b0, uint32_t b1) {
    asm volatile("mma.sync.aligned.m16n8k16.row.col.f32.bf16.bf16.f32 "
        "{%0,%1,%2,%3}, {%4,%5,%6,%7}, {%8,%9}, {%0,%1,%2,%3};"
        : "+f"(c0), "+f"(c1), "+f"(c2), "+f"(c3)
        : "r"(a0), "r"(a1), "r"(a2), "r"(a3), "r"(b0), "r"(b1));
}
#define CP_ASYNC16(dst, src) \
    asm volatile("cp.async.cg.shared.global [%0], [%1], 16;" :: "r"(dst), "l"(src))
#define CP_COMMIT() asm volatile("cp.async.commit_group;" ::: "memory")
#define CP_WAIT1()  asm volatile("cp.async.wait_group 1;" ::: "memory")

// ---------------- column sums of x ----------------
__global__ void sumx_part_kernel(const float* __restrict__ x) {
    int blk = blockIdx.x;            // B*32
    int b = blk >> 5, sc = blk & 31; // 32 s-chunks of 64
    int d = threadIdx.x;
    const float* p = x + ((size_t)b*S + sc*64)*D + d;
    float acc = 0.f;
    #pragma unroll 8
    for (int s = 0; s < 64; s++) acc += p[(size_t)s*D];
    g_xpart[(size_t)blk*D + d] = acc;
}

__global__ void sumx_final_kernel() {
    int b = blockIdx.x, d = threadIdx.x;
    float acc = 0.f;
    #pragma unroll 8
    for (int sc = 0; sc < 32; sc++) acc += g_xpart[(size_t)(b*32+sc)*D + d];
    g_xsum[b*D + d] = acc;
}

// ---------------- fp32 -> split-bf16 for x, wq, wk ----------------
#define XU (B*S*D/8)      // 524288
#define WU (D*D/8)        // 32768
__global__ void convert_xw_kernel(const float* __restrict__ x, const float* __restrict__ wq,
                                  const float* __restrict__ wk) {
    int id = blockIdx.x * blockDim.x + threadIdx.x;
    if (id >= XU + 2*WU) return;
    const float* src;
    __nv_bfloat16 *dh, *dl;
    int u;
    if (id < XU)                { u = id;            src = x  + (size_t)u*8; dh = g_xhi;  dl = g_xlo;  }
    else if (id < XU + WU)      { u = id - XU;       src = wq + (size_t)u*8; dh = g_wqhi; dl = g_wqlo; }
    else                        { u = id - XU - WU;  src = wk + (size_t)u*8; dh = g_wkhi; dl = g_wklo; }
    float4 a = *(const float4*)src;
    float4 b4 = *(const float4*)(src + 4);
    float vs[8] = {a.x, a.y, a.z, a.w, b4.x, b4.y, b4.z, b4.w};
    union { __nv_bfloat16 h[8]; int4 v; } hi, lo;
    #pragma unroll
    for (int i = 0; i < 8; i++) {
        hi.h[i] = __float2bfloat16(vs[i]);
        lo.h[i] = __float2bfloat16(vs[i] - __bfloat162float(hi.h[i]));
    }
    ((int4*)dh)[u] = hi.v;
    ((int4*)dl)[u] = lo.v;
}

// ---------------- Q/K projection via warp-mma (3-term split bf16), z = which ----------------
#define PJ_STAGE 65536
#define PJ_XHI 0
#define PJ_XLO 16384
#define PJ_WHI 32768
#define PJ_WLO 49152
#define PJ_SM_TOTAL (2*PJ_STAGE)  // 128 KB

__device__ __forceinline__ void pj_copy(uint32_t sdst, const __nv_bfloat16* g0, int tid) {
    #pragma unroll
    for (int i = 0; i < 4; i++) {
        int u = tid + i*256;
        int row = u >> 3, cu = u & 7;
        uint32_t dst = sdst + row*128 + ((cu ^ (row & 7)) << 4);
        CP_ASYNC16(dst, (const char*)g0 + (size_t)row*1024 + cu*16);
    }
}

__global__ void __launch_bounds__(256) proj_mma_kernel(const float* __restrict__ bq,
                                                       const float* __restrict__ bk) {
    extern __shared__ char smem[];
    uint32_t sb = smem_u32(smem);
    int tid = threadIdx.x;
    int w = tid >> 5, lane = tid & 31;
    int m0 = blockIdx.x * 128;
    int n0 = blockIdx.y * 128;
    int which = blockIdx.z;
    const float* bias = which ? bk : bq;

    const __nv_bfloat16* xhi = g_xhi + (size_t)m0*D;
    const __nv_bfloat16* xlo = g_xlo + (size_t)m0*D;
    const __nv_bfloat16* whi = (which ? g_wkhi : g_wqhi) + (size_t)n0*D;
    const __nv_bfloat16* wlo = (which ? g_wklo : g_wqlo) + (size_t)n0*D;
    float* outf = which ? g_K : g_Q;
    __nv_bfloat16* outh = which ? g_Khi : g_Qhi;
    __nv_bfloat16* outl = which ? g_Klo : g_Qlo;

    pj_copy(sb + 0*PJ_STAGE + PJ_XHI, xhi, tid);
    pj_copy(sb + 0*PJ_STAGE + PJ_XLO, xlo, tid);
    pj_copy(sb + 0*PJ_STAGE + PJ_WHI, whi, tid);
    pj_copy(sb + 0*PJ_STAGE + PJ_WLO, wlo, tid);
    CP_COMMIT();
    pj_copy(sb + 1*PJ_STAGE + PJ_XHI, xhi + 64, tid);
    pj_copy(sb + 1*PJ_STAGE + PJ_XLO, xlo + 64, tid);
    pj_copy(sb + 1*PJ_STAGE + PJ_WHI, whi + 64, tid);
    pj_copy(sb + 1*PJ_STAGE + PJ_WLO, wlo + 64, tid);
    CP_COMMIT();

    float c[16][4];
    #pragma unroll
    for (int j = 0; j < 16; j++)
        #pragma unroll
        for (int r = 0; r < 4; r++) c[j][r] = 0.f;

    int row16 = lane & 15;
    int half = lane >> 4;
    int bi = lane >> 3;
    int br = lane & 7;

    #pragma unroll 1
    for (int kt = 0; kt < 8; kt++) {
        CP_WAIT1();
        __syncthreads();
        uint32_t st = sb + (kt & 1)*PJ_STAGE;

        uint32_t aHi[4][4], aLo[4][4];
        {
            uint32_t rowoff = (uint32_t)(w*16 + row16) * 128;
            #pragma unroll
            for (int ks = 0; ks < 4; ks++) {
                uint32_t unit = (uint32_t)(ks*2 + half);
                uint32_t off = rowoff + ((unit ^ (row16 & 7)) << 4);
                ldsm_x4(aHi[ks][0], aHi[ks][1], aHi[ks][2], aHi[ks][3], st + PJ_XHI + off);
                ldsm_x4(aLo[ks][0], aLo[ks][1], aLo[ks][2], aLo[ks][3], st + PJ_XLO + off);
            }
        }

        #pragma unroll
        for (int j = 0; j < 16; j++) {
            int row = j*8 + br;
            uint32_t rowoff = (uint32_t)row * 128;
            uint32_t sw0 = ((uint32_t)(bi    ) ^ (row & 7)) << 4;
            uint32_t sw1 = ((uint32_t)(bi + 4) ^ (row & 7)) << 4;
            uint32_t bh0,bh1,bh2,bh3,bh4,bh5,bh6,bh7;
            uint32_t bl0,bl1,bl2,bl3,bl4,bl5,bl6,bl7;
            ldsm_x4(bh0,bh1,bh2,bh3, st + PJ_WHI + rowoff + sw0);
            ldsm_x4(bh4,bh5,bh6,bh7, st + PJ_WHI + rowoff + sw1);
            ldsm_x4(bl0,bl1,bl2,bl3, st + PJ_WLO + rowoff + sw0);
            ldsm_x4(bl4,bl5,bl6,bl7, st + PJ_WLO + rowoff + sw1);

            mma_bf16(c[j][0],c[j][1],c[j][2],c[j][3], aHi[0][0],aHi[0][1],aHi[0][2],aHi[0][3], bh0,bh1);
            mma_bf16(c[j][0],c[j][1],c[j][2],c[j][3], aHi[1][0],aHi[1][1],aHi[1][2],aHi[1][3], bh2,bh3);
            mma_bf16(c[j][0],c[j][1],c[j][2],c[j][3], aHi[2][0],aHi[2][1],aHi[2][2],aHi[2][3], bh4,bh5);
            mma_bf16(c[j][0],c[j][1],c[j][2],c[j][3], aHi[3][0],aHi[3][1],aHi[3][2],aHi[3][3], bh6,bh7);
            mma_bf16(c[j][0],c[j][1],c[j][2],c[j][3], aHi[0][0],aHi[0][1],aHi[0][2],aHi[0][3], bl0,bl1);
            mma_bf16(c[j][0],c[j][1],c[j][2],c[j][3], aHi[1][0],aHi[1][1],aHi[1][2],aHi[1][3], bl2,bl3);
            mma_bf16(c[j][0],c[j][1],c[j][2],c[j][3], aHi[2][0],aHi[2][1],aHi[2][2],aHi[2][3], bl4,bl5);
            mma_bf16(c[j][0],c[j][1],c[j][2],c[j][3], aHi[3][0],aHi[3][1],aHi[3][2],aHi[3][3], bl6,bl7);
            mma_bf16(c[j][0],c[j][1],c[j][2],c[j][3], aLo[0][0],aLo[0][1],aLo[0][2],aLo[0][3], bh0,bh1);
            mma_bf16(c[j][0],c[j][1],c[j][2],c[j][3], aLo[1][0],aLo[1][1],aLo[1][2],aLo[1][3], bh2,bh3);
            mma_bf16(c[j][0],c[j][1],c[j][2],c[j][3], aLo[2][0],aLo[2][1],aLo[2][2],aLo[2][3], bh4,bh5);
            mma_bf16(c[j][0],c[j][1],c[j][2],c[j][3], aLo[3][0],aLo[3][1],aLo[3][2],aLo[3][3], bh6,bh7);
        }
        __syncthreads();
        if (kt + 2 < 8) {
            uint32_t st2 = sb + (kt & 1)*PJ_STAGE;
            int koff = (kt + 2) * 64;
            pj_copy(st2 + PJ_XHI, xhi + koff, tid);
            pj_copy(st2 + PJ_XLO, xlo + koff, tid);
            pj_copy(st2 + PJ_WHI, whi + koff, tid);
            pj_copy(st2 + PJ_WLO, wlo + koff, tid);
        }
        CP_COMMIT();
    }

    int r0 = m0 + w*16 + (lane >> 2);
    #pragma unroll
    for (int j = 0; j < 16; j++) {
        int n = n0 + j*8 + (lane & 3)*2;
        int h = n >> 6, k = n & 63;
        float b0 = bias[n], b1 = bias[n+1];
        #pragma unroll
        for (int rr = 0; rr < 2; rr++) {
            int m = r0 + rr*8;
            int b_ = m >> 11, s = m & (S-1);
            size_t idx = (((size_t)(b_*H + h)*S + s)*DK) + k;
            float v0 = c[j][rr*2+0] + b0;
            float v1 = c[j][rr*2+1] + b1;
            *(float2*)(outf + idx) = make_float2(v0, v1);
            union { __nv_bfloat16 h2[2]; uint32_t u; } ph, pl;
            ph.h2[0] = __float2bfloat16(v0);
            ph.h2[1] = __float2bfloat16(v1);
            pl.h2[0] = __float2bfloat16(v0 - __bfloat162float(ph.h2[0]));
            pl.h2[1] = __float2bfloat16(v1 - __bfloat162float(ph.h2[1]));
            *(uint32_t*)(outh + idx) = ph.u;
            *(uint32_t*)(outl + idx) = pl.u;
        }
    }
}

// ---------------- warp-mma QK^T row-max/row-mean -> sparsity (m32/warp) ----------------
#define SQ_HI 0
#define SQ_LO 16384
#define SK_BASE 32768
#define SK_STAGE 32768
#define SM_TOTAL (SK_BASE + 2*SK_STAGE)   // 96 KB

__device__ __forceinline__ void copy_tile_async128(uint32_t sdst, const __nv_bfloat16* gsrc, int tid) {
    #pragma unroll
    for (int i = 0; i < 8; i++) {
        int u = tid + i*128;
        int row = u >> 3, cu = u & 7;
        uint32_t dst = sdst + row*128 + ((cu ^ (row & 7)) << 4);
        CP_ASYNC16(dst, (const char*)gsrc + (size_t)u*16);
    }
}

__global__ void __launch_bounds__(128) scores_mma_kernel() {
    extern __shared__ char smem[];
    uint32_t sb = smem_u32(smem);
    int tid = threadIdx.x;
    int w = tid >> 5, lane = tid & 31;
    int bh = blockIdx.x;
    int qt = blockIdx.y;

    const __nv_bfloat16* qh_g = g_Qhi + (size_t)(bh*S + qt*128)*DK;
    const __nv_bfloat16* ql_g = g_Qlo + (size_t)(bh*S + qt*128)*DK;
    const __nv_bfloat16* kh_g = g_Khi + (size_t)bh*S*DK;
    const __nv_bfloat16* kl_g = g_Klo + (size_t)bh*S*DK;

    copy_tile_async128(sb + SQ_HI, qh_g, tid);
    copy_tile_async128(sb + SQ_LO, ql_g, tid);
    copy_tile_async128(sb + SK_BASE + 0*SK_STAGE,         kh_g, tid);
    copy_tile_async128(sb + SK_BASE + 0*SK_STAGE + 16384, kl_g, tid);
    CP_COMMIT();
    copy_tile_async128(sb + SK_BASE + 1*SK_STAGE,         kh_g + 128*DK, tid);
    copy_tile_async128(sb + SK_BASE + 1*SK_STAGE + 16384, kl_g + 128*DK, tid);
    CP_COMMIT();

    CP_WAIT1();
    __syncthreads();

    uint32_t aHi[2][4][4], aLo[2][4][4];
    {
        int row16 = lane & 15;
        int half = lane >> 4;
        #pragma unroll
        for (int rb = 0; rb < 2; rb++) {
            uint32_t rowoff = (uint32_t)(w*32 + rb*16 + row16) * 128;
            #pragma unroll
            for (int ks = 0; ks < 4; ks++) {
                uint32_t unit = (uint32_t)(ks*2 + half);
                uint32_t off = rowoff + ((unit ^ (row16 & 7)) << 4);
                ldsm_x4(aHi[rb][ks][0], aHi[rb][ks][1], aHi[rb][ks][2], aHi[rb][ks][3], sb + SQ_HI + off);
                ldsm_x4(aLo[rb][ks][0], aLo[rb][ks][1], aLo[rb][ks][2], aLo[rb][ks][3], sb + SQ_LO + off);
            }
        }
    }

    float rmax0[2] = {-1e30f, -1e30f}, rmax1[2] = {-1e30f, -1e30f};
    float rsum0[2] = {0.f, 0.f},       rsum1[2] = {0.f, 0.f};
    int bi = lane >> 3;
    int br = lane & 7;

    #pragma unroll 1
    for (int kt = 0; kt < 16; kt++) {
        if (kt > 0) {
            CP_WAIT1();
            __syncthreads();
        }
        uint32_t kb_hi = sb + SK_BASE + (kt & 1)*SK_STAGE;
        uint32_t kb_lo = kb_hi + 16384;

        #pragma unroll
        for (int t = 0; t < 16; t++) {
            int row = t*8 + br;
            uint32_t rowoff = (uint32_t)row * 128;
            uint32_t sw0 = ((uint32_t)(bi    ) ^ (row & 7)) << 4;
            uint32_t sw1 = ((uint32_t)(bi + 4) ^ (row & 7)) << 4;
            uint32_t bh0,bh1,bh2,bh3,bh4,bh5,bh6,bh7;
            uint32_t bl0,bl1,bl2,bl3,bl4,bl5,bl6,bl7;
            ldsm_x4(bh0,bh1,bh2,bh3, kb_hi + rowoff + sw0);
            ldsm_x4(bh4,bh5,bh6,bh7, kb_hi + rowoff + sw1);
            ldsm_x4(bl0,bl1,bl2,bl3, kb_lo + rowoff + sw0);
            ldsm_x4(bl4,bl5,bl6,bl7, kb_lo + rowoff + sw1);

            #pragma unroll
            for (int rb = 0; rb < 2; rb++) {
                float cA0=0.f, cA1=0.f, cA2=0.f, cA3=0.f;
                float cB0=0.f, cB1=0.f, cB2=0.f, cB3=0.f;
                mma_bf16(cA0,cA1,cA2,cA3, aHi[rb][0][0],aHi[rb][0][1],aHi[rb][0][2],aHi[rb][0][3], bh0,bh1);
                mma_bf16(cB0,cB1,cB2,cB3, aHi[rb][0][0],aHi[rb][0][1],aHi[rb][0][2],aHi[rb][0][3], bl0,bl1);
                mma_bf16(cA0,cA1,cA2,cA3, aHi[rb][1][0],aHi[rb][1][1],aHi[rb][1][2],aHi[rb][1][3], bh2,bh3);
                mma_bf16(cB0,cB1,cB2,cB3, aHi[rb][1][0],aHi[rb][1][1],aHi[rb][1][2],aHi[rb][1][3], bl2,bl3);
                mma_bf16(cA0,cA1,cA2,cA3, aHi[rb][2][0],aHi[rb][2][1],aHi[rb][2][2],aHi[rb][2][3], bh4,bh5);
                mma_bf16(cB0,cB1,cB2,cB3, aHi[rb][2][0],aHi[rb][2][1],aHi[rb][2][2],aHi[rb][2][3], bl4,bl5);
                mma_bf16(cA0,cA1,cA2,cA3, aHi[rb][3][0],aHi[rb][3][1],aHi[rb][3][2],aHi[rb][3][3], bh6,bh7);
                mma_bf16(cB0,cB1,cB2,cB3, aHi[rb][3][0],aHi[rb][3][1],aHi[rb][3][2],aHi[rb][3][3], bl6,bl7);
                mma_bf16(cA0,cA1,cA2,cA3, aLo[rb][0][0],aLo[rb][0][1],aLo[rb][0][2],aLo[rb][0][3], bh0,bh1);
                mma_bf16(cB0,cB1,cB2,cB3, aLo[rb][2][0],aLo[rb][2][1],aLo[rb][2][2],aLo[rb][2][3], bh4,bh5);
                mma_bf16(cA0,cA1,cA2,cA3, aLo[rb][1][0],aLo[rb][1][1],aLo[rb][1][2],aLo[rb][1][3], bh2,bh3);
                mma_bf16(cB0,cB1,cB2,cB3, aLo[rb][3][0],aLo[rb][3][1],aLo[rb][3][2],aLo[rb][3][3], bh6,bh7);

                float c0 = cA0 + cB0, c1 = cA1 + cB1, c2 = cA2 + cB2, c3 = cA3 + cB3;
                rmax0[rb] = fmaxf(rmax0[rb], fmaxf(c0, c1));
                rsum0[rb] += c0 + c1;
                rmax1[rb] = fmaxf(rmax1[rb], fmaxf(c2, c3));
                rsum1[rb] += c2 + c3;
            }
        }
        __syncthreads();
        if (kt + 2 < 16) {
            copy_tile_async128(sb + SK_BASE + (kt & 1)*SK_STAGE,         kh_g + (size_t)(kt+2)*128*DK, tid);
            copy_tile_async128(sb + SK_BASE + (kt & 1)*SK_STAGE + 16384, kl_g + (size_t)(kt+2)*128*DK, tid);
        }
        CP_COMMIT();
    }

    #pragma unroll
    for (int rb = 0; rb < 2; rb++) {
        float m0v = rmax0[rb], m1v = rmax1[rb], s0v = rsum0[rb], s1v = rsum1[rb];
        #pragma unroll
        for (int off = 1; off < 4; off <<= 1) {
            m0v = fmaxf(m0v, __shfl_xor_sync(0xFFFFFFFFu, m0v, off));
            s0v += __shfl_xor_sync(0xFFFFFFFFu, s0v, off);
            m1v = fmaxf(m1v, __shfl_xor_sync(0xFFFFFFFFu, m1v, off));
            s1v += __shfl_xor_sync(0xFFFFFFFFu, s1v, off);
        }
        if ((lane & 3) == 0) {
            int r0 = qt*128 + w*32 + rb*16 + (lane >> 2);
            float inv_log = 1.0f / logf((float)S);
            g_spars[bh*S + r0]     = s0v * (0.125f / (float)S) - m0v * 0.125f * inv_log;
            g_spars[bh*S + r0 + 8] = s1v * (0.125f / (float)S) - m1v * 0.125f * inv_log;
        }
    }
}

// ---------------- iterative top-53 per (b,h) ----------------
__global__ void topk_kernel() {
    __shared__ float vals[S];
    __shared__ float wm[8];
    __shared__ int   wi[8];
    int bh = blockIdx.x, tid = threadIdx.x;
    int lane = tid & 31, wid = tid >> 5;
    for (int i = tid; i < S; i += 256) vals[i] = g_spars[bh*S + i];
    __syncthreads();
    for (int it = 0; it < U; it++) {
        float best = -1e30f; int bidx = S;
        #pragma unroll
        for (int k = 0; k < 8; k++) {
            int i = tid + k*256;
            float v = vals[i];
            if (v > best || (v == best && i < bidx)) { best = v; bidx = i; }
        }
        #pragma unroll
        for (int off = 16; off > 0; off >>= 1) {
            float v2 = __shfl_down_sync(0xFFFFFFFFu, best, off);
            int i2 = __shfl_down_sync(0xFFFFFFFFu, bidx, off);
            if (v2 > best || (v2 == best && i2 < bidx)) { best = v2; bidx = i2; }
        }
        if (lane == 0) { wm[wid] = best; wi[wid] = bidx; }
        __syncthreads();
        if (tid == 0) {
            float m = wm[0]; int mi = wi[0];
            #pragma unroll
            for (int t = 1; t < 8; t++)
                if (wm[t] > m || (wm[t] == m && wi[t] < mi)) { m = wm[t]; mi = wi[t]; }
            g_topidx[bh*U + it] = mi;
            vals[mi] = -1e30f;
        }
        __syncthreads();
    }
}

// ---------------- fused meanV + ybase (warp-per-output, coalesced) ----------------
__global__ void __launch_bounds__(512) meanv_ybase_kernel(
        const float* __restrict__ wv, const float* __restrict__ bv,
        const float* __restrict__ wo, const float* __restrict__ bo) {
    __shared__ float xs[D];
    __shared__ float mv[D];
    int b = blockIdx.x, tid = threadIdx.x;
    int lane = tid & 31, w = tid >> 5;      // 16 warps, 32 outputs each
    xs[tid] = g_xsum[b*D + tid];
    __syncthreads();
    #pragma unroll 1
    for (int oo = 0; oo < 32; oo++) {
        int o = w*32 + oo;
        const float* wr = wv + (size_t)o*D + lane;
        float acc = 0.f;
        #pragma unroll
        for (int k = 0; k < 16; k++) acc += xs[lane + k*32] * wr[k*32];
        #pragma unroll
        for (int off = 16; off > 0; off >>= 1) acc += __shfl_xor_sync(0xFFFFFFFFu, acc, off);
        if (lane == 0) {
            float m = acc * (1.0f/(float)S) + bv[o];
            mv[o] = m;
            g_meanV[b*D + o] = m;
        }
    }
    __syncthreads();
    #pragma unroll 1
    for (int oo = 0; oo < 32; oo++) {
        int o = w*32 + oo;
        const float* wr = wo + (size_t)o*D + lane;
        float acc = 0.f;
        #pragma unroll
        for (int k = 0; k < 16; k++) acc += mv[lane + k*32] * wr[k*32];
        #pragma unroll
        for (int off = 16; off > 0; off >>= 1) acc += __shfl_xor_sync(0xFFFFFFFFu, acc, off);
        if (lane == 0) g_ybase[b*D + o] = acc + bo[o];
    }
}

// ---------------- corrections: one block per (b,h), 4x4 register-tiled ----------------
__global__ void __launch_bounds__(256) corr_kernel(const float* __restrict__ x,
                                                   const float* __restrict__ wv,
                                                   const float* __restrict__ bv) {
    __shared__ float sbuf[64*65 + 56*65];   // phase1: sq(53*64)+sk(53*64); phase2: wvs+xjs
    __shared__ int   s_idx[56];
    __shared__ float s_v[56];
    int bh = blockIdx.x;
    int b = bh / H, h = bh % H;
    int tid = threadIdx.x;
    if (tid < U) s_idx[tid] = g_topidx[bh*U + tid];
    __syncthreads();

    // phase 1: v_i = Q[bh,i] . K[bh,j_i] / 8
    float* sq = sbuf;
    float* sk = sbuf + U*DK;
    for (int e = tid; e < U*DK; e += 256) sq[e] = g_Q[(size_t)bh*S*DK + e];  // rows 0..52 contiguous
    for (int e = tid; e < U*DK; e += 256) {
        int i = e >> 6, d = e & 63;
        sk[e] = g_K[((size_t)bh*S + s_idx[i])*DK + d];
    }
    __syncthreads();
    if (tid < U) {
        float acc = 0.f;
        #pragma unroll 8
        for (int d = 0; d < DK; d++) acc += sq[tid*DK + d] * sk[tid*DK + d];
        s_v[tid] = acc * 0.125f;
    }
    __syncthreads();

    // phase 2: Vj[i][col] = x[b, j_i, :] . wv[h*64+col, :], tiled over 8 chunks of 64
    float* wvs = sbuf;              // [64][65]
    float* xjs = sbuf + 64*65;      // [56][65], rows >= U zeroed
    int ci = tid & 15, ri = tid >> 4;   // ci: 16 col-tiles of 4, ri: 16 -> use < 14
    float acc[4][4] = {};
    for (int dt = 0; dt < 8; dt++) {
        __syncthreads();
        for (int e = tid; e < 64*64; e += 256) {
            int r = e >> 6, c2 = e & 63;
            wvs[r*65 + c2] = wv[((size_t)(h*64 + r))*D + dt*64 + c2];
        }
        for (int e = tid; e < 56*64; e += 256) {
            int i = e >> 6, c2 = e & 63;
            xjs[i*65 + c2] = (i < U) ? x[((size_t)b*S + s_idx[i])*D + dt*64 + c2] : 0.f;
        }
        __syncthreads();
        if (ri < 14) {
            #pragma unroll 4
            for (int dd = 0; dd < 64; dd++) {
                float xv0 = xjs[(ri*4+0)*65 + dd];
                float xv1 = xjs[(ri*4+1)*65 + dd];
                float xv2 = xjs[(ri*4+2)*65 + dd];
                float xv3 = xjs[(ri*4+3)*65 + dd];
                float w0 = wvs[(ci*4+0)*65 + dd];
                float w1 = wvs[(ci*4+1)*65 + dd];
                float w2 = wvs[(ci*4+2)*65 + dd];
                float w3 = wvs[(ci*4+3)*65 + dd];
                acc[0][0] += xv0*w0; acc[0][1] += xv0*w1; acc[0][2] += xv0*w2; acc[0][3] += xv0*w3;
                acc[1][0] += xv1*w0; acc[1][1] += xv1*w1; acc[1][2] += xv1*w2; acc[1][3] += xv1*w3;
                acc[2][0] += xv2*w0; acc[2][1] += xv2*w1; acc[2][2] += xv2*w2; acc[2][3] += xv2*w3;
                acc[3][0] += xv3*w0; acc[3][1] += xv3*w1; acc[3][2] += xv3*w2; acc[3][3] += xv3*w3;
            }
        }
    }

    if (ri < 14) {
        #pragma unroll
        for (int r = 0; r < 4; r++) {
            int i = ri*4 + r;
            if (i >= U) continue;
            float ev = expf(s_v[i]);
            float em1 = ev - 1.0f;
            float Z = ev + (float)(S - 1);
            #pragma unroll
            for (int c2 = 0; c2 < 4; c2++) {
                int col = ci*4 + c2;
                float Vj = acc[r][c2] + bv[h*64 + col];
                float mvv = g_meanV[b*D + h*64 + col];
                g_outcat[((size_t)(b*U + i))*D + h*64 + col] = ((float)S * mvv + em1 * Vj) / Z;
            }
        }
    }
}

// ---------------- out-projection for the 212 corrected rows ----------------
__global__ void outproj_kernel(const float* __restrict__ wo, const float* __restrict__ bo,
                               float* __restrict__ y) {
    __shared__ float As[32][68];
    __shared__ float Bs[32][68];
    int tid = threadIdx.x;
    int tx = tid & 15, ty = tid >> 4;
    int m0 = blockIdx.x * 64;
    int n0 = blockIdx.y * 64;
    float acc[4][4] = {};
    for (int d0 = 0; d0 < D; d0 += 32) {
        #pragma unroll
        for (int i = 0; i < 2; i++) {
            int e = tid + i*256;
            int row = e >> 3;
            int c4 = e & 7;
            float4 v = make_float4(0.f, 0.f, 0.f, 0.f);
            if (m0 + row < B*U)
                v = *(const float4*)(g_outcat + (size_t)(m0+row)*D + d0 + c4*4);
            As[c4*4+0][row] = v.x; As[c4*4+1][row] = v.y;
            As[c4*4+2][row] = v.z; As[c4*4+3][row] = v.w;
            float4 u = *(const float4*)(wo + (size_t)(n0+row)*D + d0 + c4*4);
            Bs[c4*4+0][row] = u.x; Bs[c4*4+1][row] = u.y;
            Bs[c4*4+2][row] = u.z; Bs[c4*4+3][row] = u.w;
        }
        __syncthreads();
        #pragma unroll
        for (int kk = 0; kk < 32; kk++) {
            float4 a = *(const float4*)&As[kk][tx*4];
            float4 bv4 = *(const float4*)&Bs[kk][ty*4];
            float av[4] = {a.x, a.y, a.z, a.w};
            float bw[4] = {bv4.x, bv4.y, bv4.z, bv4.w};
            #pragma unroll
            for (int i = 0; i < 4; i++)
                #pragma unroll
                for (int j = 0; j < 4; j++)
                    acc[i][j] += av[i] * bw[j];
        }
        __syncthreads();
    }
    #pragma unroll
    for (int i = 0; i < 4; i++) {
        int m = m0 + tx*4 + i;
        if (m < B*U) {
            int b = m / U, s = m % U;
            float* op = y + ((size_t)b*S + s)*D + n0 + ty*4;
            #pragma unroll
            for (int j = 0; j < 4; j++)
                op[j] = acc[i][j] + bo[n0 + ty*4 + j];
        }
    }
}

// ---------------- broadcast the uniform rows (s >= U) ----------------
__global__ void bcast_kernel(float* __restrict__ y) {
    int id = blockIdx.x * blockDim.x + threadIdx.x;
    const int per_b = (S - U) * (D/4);
    const int total = B * per_b;
    if (id >= total) return;
    int b = id / per_b;
    int r = id % per_b;
    int s = U + r / (D/4);
    int d4 = r % (D/4);
    float4 v = *(const float4*)(g_ybase + b*D + d4*4);
    *(float4*)(y + ((size_t)b*S + s)*D + d4*4) = v;
}

extern "C" void kernel_launch(void* const* d_in, const int* in_sizes, int n_in,
                              void* d_out, int out_size) {
    const float* x  = (const float*)d_in[0];
    const float* wq = (const float*)d_in[1];
    const float* bq = (const float*)d_in[2];
    const float* wk = (const float*)d_in[3];
    const float* bk = (const float*)d_in[4];
    const float* wv = (const float*)d_in[5];
    const float* bv = (const float*)d_in[6];
    const float* wo = (const float*)d_in[7];
    const float* bo = (const float*)d_in[8];
    float* y = (float*)d_out;

    cudaFuncSetAttribute(scores_mma_kernel, cudaFuncAttributeMaxDynamicSharedMemorySize, SM_TOTAL);
    cudaFuncSetAttribute(proj_mma_kernel, cudaFuncAttributeMaxDynamicSharedMemorySize, PJ_SM_TOTAL);

    {
        const int total = XU + 2*WU;
        convert_xw_kernel<<<(total + 255)/256, 256>>>(x, wq, wk);          // u1
    }

    dim3 pg(B*S/128, D/128, 2);
    proj_mma_kernel<<<pg, 256, PJ_SM_TOTAL>>>(bq, bk);                     // u2

    sumx_part_kernel<<<B*32, 512>>>(x);                                    // u3

    dim3 sg(BH, 16);
    scores_mma_kernel<<<sg, 128, SM_TOTAL>>>();                            // u4 <- ncu

    sumx_final_kernel<<<B, 512>>>();                                       // u5

    topk_kernel<<<BH, 256>>>();                                            // u6

    meanv_ybase_kernel<<<B, 512>>>(wv, bv, wo, bo);                        // u7

    corr_kernel<<<BH, 256>>>(x, wv, bv);                                   // u8

    dim3 og((B*U + 63)/64, D/64);
    outproj_kernel<<<og, 256>>>(wo, bo, y);                                // u9

    const int per_b = (S - U) * (D/4);
    bcast_kernel<<<(B*per_b + 255)/256, 256>>>(y);                         // u10
}

// round 10
// speedup vs baseline: 2.7433x; 1.0308x over previous
#include <cuda_runtime.h>
#include <cuda_bf16.h>
#include <math.h>
#include <stdint.h>

#define B 4
#define S 2048
#define D 512
#define H 8
#define DK 64
#define U 53
#define BH (B*H)

// ---------------- scratch (static device allocations; no cudaMalloc) ----------------
__device__ float g_Q[B*H*S*DK];       // [bh][s][k] fp32 (needed by corr)
__device__ float g_K[B*H*S*DK];
__device__ float g_spars[B*H*S];
__device__ int   g_topidx[B*H*U];
__device__ float g_xpart[32*B*D];
__device__ float g_meanV[B*D];
__device__ float g_ybase[B*D];
__device__ float g_outcat[B*U*D];
// split bf16 Q/K operands, row-major [bh][s][64] (written by proj epilogue)
__device__ __nv_bfloat16 g_Qhi[BH*S*DK];
__device__ __nv_bfloat16 g_Qlo[BH*S*DK];
__device__ __nv_bfloat16 g_Khi[BH*S*DK];
__device__ __nv_bfloat16 g_Klo[BH*S*DK];
// split bf16 inputs for proj mma
__device__ __nv_bfloat16 g_xhi[B*S*D];
__device__ __nv_bfloat16 g_xlo[B*S*D];
__device__ __nv_bfloat16 g_wqhi[D*D];
__device__ __nv_bfloat16 g_wqlo[D*D];
__device__ __nv_bfloat16 g_wkhi[D*D];
__device__ __nv_bfloat16 g_wklo[D*D];

// ================= warp-mma helpers =================
__device__ __forceinline__ uint32_t smem_u32(const void* p) {
    uint32_t a;
    asm("{ .reg .u64 t; cvta.to.shared.u64 t, %1; cvt.u32.u64 %0, t; }" : "=r"(a) : "l"(p));
    return a;
}

__device__ __forceinline__ void ldsm_x4(uint32_t& r0, uint32_t& r1, uint32_t& r2, uint32_t& r3, uint32_t addr) {
    asm volatile("ldmatrix.sync.aligned.m8n8.x4.shared.b16 {%0,%1,%2,%3}, [%4];"
        : "=r"(r0), "=r"(r1), "=r"(r2), "=r"(r3) : "r"(addr));
}
__device__ __forceinline__ void mma_bf16(float& c0, float& c1, float& c2, float& c3,
                                         uint32_t a0, uint32_t a1, uint32_t a2, uint32_t a3,
                                         uint32_t b0, uint32_t b1) {
    asm volatile("mma.sync.aligned.m16n8k16.row.col.f32.bf16.bf16.f32 "
        "{%0,%1,%2,%3}, {%4,%5,%6,%7}, {%8,%9}, {%0,%1,%2,%3};"
        : "+f"(c0), "+f"(c1), "+f"(c2), "+f"(c3)
        : "r"(a0), "r"(a1), "r"(a2), "r"(a3), "r"(b0), "r"(b1));
}
#define CP_ASYNC16(dst, src) \
    asm volatile("cp.async.cg.shared.global [%0], [%1], 16;" :: "r"(dst), "l"(src))
#define CP_COMMIT() asm volatile("cp.async.commit_group;" ::: "memory")
#define CP_WAIT1()  asm volatile("cp.async.wait_group 1;" ::: "memory")

// ---------------- column sums of x (partials) ----------------
__global__ void sumx_part_kernel(const float* __restrict__ x) {
    int blk = blockIdx.x;            // B*32
    int b = blk >> 5, sc = blk & 31; // 32 s-chunks of 64
    int d = threadIdx.x;
    const float* p = x + ((size_t)b*S + sc*64)*D + d;
    float acc = 0.f;
    #pragma unroll 8
    for (int s = 0; s < 64; s++) acc += p[(size_t)s*D];
    g_xpart[(size_t)blk*D + d] = acc;
}

// ---------------- fp32 -> split-bf16 for x, wq, wk ----------------
#define XU (B*S*D/8)      // 524288
#define WU (D*D/8)        // 32768
__global__ void convert_xw_kernel(const float* __restrict__ x, const float* __restrict__ wq,
                                  const float* __restrict__ wk) {
    int id = blockIdx.x * blockDim.x + threadIdx.x;
    if (id >= XU + 2*WU) return;
    const float* src;
    __nv_bfloat16 *dh, *dl;
    int u;
    if (id < XU)                { u = id;            src = x  + (size_t)u*8; dh = g_xhi;  dl = g_xlo;  }
    else if (id < XU + WU)      { u = id - XU;       src = wq + (size_t)u*8; dh = g_wqhi; dl = g_wqlo; }
    else                        { u = id - XU - WU;  src = wk + (size_t)u*8; dh = g_wkhi; dl = g_wklo; }
    float4 a = *(const float4*)src;
    float4 b4 = *(const float4*)(src + 4);
    float vs[8] = {a.x, a.y, a.z, a.w, b4.x, b4.y, b4.z, b4.w};
    union { __nv_bfloat16 h[8]; int4 v; } hi, lo;
    #pragma unroll
    for (int i = 0; i < 8; i++) {
        hi.h[i] = __float2bfloat16(vs[i]);
        lo.h[i] = __float2bfloat16(vs[i] - __bfloat162float(hi.h[i]));
    }
    ((int4*)dh)[u] = hi.v;
    ((int4*)dl)[u] = lo.v;
}

// ---------------- Q/K projection via warp-mma (3-term split bf16) ----------------
// CTA = 128 rows x 64 cols; K=512 in 64-chunks, 2-stage cp.async.
// stage = x(32KB) + w(16KB) = 48KB; double-buffer 96KB -> 2 CTAs/SM.
#define PJ_STAGE 49152
#define PJ_XHI 0
#define PJ_XLO 16384
#define PJ_WHI 32768
#define PJ_WLO 40960
#define PJ_SM_TOTAL (2*PJ_STAGE)  // 96 KB

__device__ __forceinline__ void pj_copy_x(uint32_t sdst, const __nv_bfloat16* g0, int tid) {
    #pragma unroll
    for (int i = 0; i < 4; i++) {
        int u = tid + i*256;            // 1024 units (128 rows x 8)
        int row = u >> 3, cu = u & 7;
        uint32_t dst = sdst + row*128 + ((cu ^ (row & 7)) << 4);
        CP_ASYNC16(dst, (const char*)g0 + (size_t)row*1024 + cu*16);
    }
}
__device__ __forceinline__ void pj_copy_w(uint32_t sdst, const __nv_bfloat16* g0, int tid) {
    #pragma unroll
    for (int i = 0; i < 2; i++) {
        int u = tid + i*256;            // 512 units (64 rows x 8)
        int row = u >> 3, cu = u & 7;
        uint32_t dst = sdst + row*128 + ((cu ^ (row & 7)) << 4);
        CP_ASYNC16(dst, (const char*)g0 + (size_t)row*1024 + cu*16);
    }
}

__global__ void __launch_bounds__(256, 2) proj_mma_kernel(const float* __restrict__ bq,
                                                          const float* __restrict__ bk) {
    extern __shared__ char smem[];
    uint32_t sb = smem_u32(smem);
    int tid = threadIdx.x;
    int w = tid >> 5, lane = tid & 31;
    int m0 = blockIdx.x * 128;
    int n0 = blockIdx.y * 64;
    int which = blockIdx.z;
    const float* bias = which ? bk : bq;

    const __nv_bfloat16* xhi = g_xhi + (size_t)m0*D;
    const __nv_bfloat16* xlo = g_xlo + (size_t)m0*D;
    const __nv_bfloat16* whi = (which ? g_wkhi : g_wqhi) + (size_t)n0*D;
    const __nv_bfloat16* wlo = (which ? g_wklo : g_wqlo) + (size_t)n0*D;
    float* outf = which ? g_K : g_Q;
    __nv_bfloat16* outh = which ? g_Khi : g_Qhi;
    __nv_bfloat16* outl = which ? g_Klo : g_Qlo;

    pj_copy_x(sb + 0*PJ_STAGE + PJ_XHI, xhi, tid);
    pj_copy_x(sb + 0*PJ_STAGE + PJ_XLO, xlo, tid);
    pj_copy_w(sb + 0*PJ_STAGE + PJ_WHI, whi, tid);
    pj_copy_w(sb + 0*PJ_STAGE + PJ_WLO, wlo, tid);
    CP_COMMIT();
    pj_copy_x(sb + 1*PJ_STAGE + PJ_XHI, xhi + 64, tid);
    pj_copy_x(sb + 1*PJ_STAGE + PJ_XLO, xlo + 64, tid);
    pj_copy_w(sb + 1*PJ_STAGE + PJ_WHI, whi + 64, tid);
    pj_copy_w(sb + 1*PJ_STAGE + PJ_WLO, wlo + 64, tid);
    CP_COMMIT();

    float c[8][4];
    #pragma unroll
    for (int j = 0; j < 8; j++)
        #pragma unroll
        for (int r = 0; r < 4; r++) c[j][r] = 0.f;

    int row16 = lane & 15;
    int half = lane >> 4;
    int bi = lane >> 3;
    int br = lane & 7;

    #pragma unroll 1
    for (int kt = 0; kt < 8; kt++) {
        CP_WAIT1();
        __syncthreads();
        uint32_t st = sb + (kt & 1)*PJ_STAGE;

        uint32_t aHi[4][4], aLo[4][4];
        {
            uint32_t rowoff = (uint32_t)(w*16 + row16) * 128;
            #pragma unroll
            for (int ks = 0; ks < 4; ks++) {
                uint32_t unit = (uint32_t)(ks*2 + half);
                uint32_t off = rowoff + ((unit ^ (row16 & 7)) << 4);
                ldsm_x4(aHi[ks][0], aHi[ks][1], aHi[ks][2], aHi[ks][3], st + PJ_XHI + off);
                ldsm_x4(aLo[ks][0], aLo[ks][1], aLo[ks][2], aLo[ks][3], st + PJ_XLO + off);
            }
        }

        #pragma unroll
        for (int j = 0; j < 8; j++) {
            int row = j*8 + br;
            uint32_t rowoff = (uint32_t)row * 128;
            uint32_t sw0 = ((uint32_t)(bi    ) ^ (row & 7)) << 4;
            uint32_t sw1 = ((uint32_t)(bi + 4) ^ (row & 7)) << 4;
            uint32_t bh0,bh1,bh2,bh3,bh4,bh5,bh6,bh7;
            uint32_t bl0,bl1,bl2,bl3,bl4,bl5,bl6,bl7;
            ldsm_x4(bh0,bh1,bh2,bh3, st + PJ_WHI + rowoff + sw0);
            ldsm_x4(bh4,bh5,bh6,bh7, st + PJ_WHI + rowoff + sw1);
            ldsm_x4(bl0,bl1,bl2,bl3, st + PJ_WLO + rowoff + sw0);
            ldsm_x4(bl4,bl5,bl6,bl7, st + PJ_WLO + rowoff + sw1);

            mma_bf16(c[j][0],c[j][1],c[j][2],c[j][3], aHi[0][0],aHi[0][1],aHi[0][2],aHi[0][3], bh0,bh1);
            mma_bf16(c[j][0],c[j][1],c[j][2],c[j][3], aHi[1][0],aHi[1][1],aHi[1][2],aHi[1][3], bh2,bh3);
            mma_bf16(c[j][0],c[j][1],c[j][2],c[j][3], aHi[2][0],aHi[2][1],aHi[2][2],aHi[2][3], bh4,bh5);
            mma_bf16(c[j][0],c[j][1],c[j][2],c[j][3], aHi[3][0],aHi[3][1],aHi[3][2],aHi[3][3], bh6,bh7);
            mma_bf16(c[j][0],c[j][1],c[j][2],c[j][3], aHi[0][0],aHi[0][1],aHi[0][2],aHi[0][3], bl0,bl1);
            mma_bf16(c[j][0],c[j][1],c[j][2],c[j][3], aHi[1][0],aHi[1][1],aHi[1][2],aHi[1][3], bl2,bl3);
            mma_bf16(c[j][0],c[j][1],c[j][2],c[j][3], aHi[2][0],aHi[2][1],aHi[2][2],aHi[2][3], bl4,bl5);
            mma_bf16(c[j][0],c[j][1],c[j][2],c[j][3], aHi[3][0],aHi[3][1],aHi[3][2],aHi[3][3], bl6,bl7);
            mma_bf16(c[j][0],c[j][1],c[j][2],c[j][3], aLo[0][0],aLo[0][1],aLo[0][2],aLo[0][3], bh0,bh1);
            mma_bf16(c[j][0],c[j][1],c[j][2],c[j][3], aLo[1][0],aLo[1][1],aLo[1][2],aLo[1][3], bh2,bh3);
            mma_bf16(c[j][0],c[j][1],c[j][2],c[j][3], aLo[2][0],aLo[2][1],aLo[2][2],aLo[2][3], bh4,bh5);
            mma_bf16(c[j][0],c[j][1],c[j][2],c[j][3], aLo[3][0],aLo[3][1],aLo[3][2],aLo[3][3], bh6,bh7);
        }
        __syncthreads();
        if (kt + 2 < 8) {
            uint32_t st2 = sb + (kt & 1)*PJ_STAGE;
            int koff = (kt + 2) * 64;
            pj_copy_x(st2 + PJ_XHI, xhi + koff, tid);
            pj_copy_x(st2 + PJ_XLO, xlo + koff, tid);
            pj_copy_w(st2 + PJ_WHI, whi + koff, tid);
            pj_copy_w(st2 + PJ_WLO, wlo + koff, tid);
        }
        CP_COMMIT();
    }

    int r0 = m0 + w*16 + (lane >> 2);
    #pragma unroll
    for (int j = 0; j < 8; j++) {
        int n = n0 + j*8 + (lane & 3)*2;
        int h = n >> 6, k = n & 63;
        float b0 = bias[n], b1 = bias[n+1];
        #pragma unroll
        for (int rr = 0; rr < 2; rr++) {
            int m = r0 + rr*8;
            int b_ = m >> 11, s = m & (S-1);
            size_t idx = (((size_t)(b_*H + h)*S + s)*DK) + k;
            float v0 = c[j][rr*2+0] + b0;
            float v1 = c[j][rr*2+1] + b1;
            *(float2*)(outf + idx) = make_float2(v0, v1);
            union { __nv_bfloat16 h2[2]; uint32_t u; } ph, pl;
            ph.h2[0] = __float2bfloat16(v0);
            ph.h2[1] = __float2bfloat16(v1);
            pl.h2[0] = __float2bfloat16(v0 - __bfloat162float(ph.h2[0]));
            pl.h2[1] = __float2bfloat16(v1 - __bfloat162float(ph.h2[1]));
            *(uint32_t*)(outh + idx) = ph.u;
            *(uint32_t*)(outl + idx) = pl.u;
        }
    }
}

// ---------------- warp-mma QK^T row-max/row-mean -> sparsity ----------------
// 128 threads, 4 warps x m32; K streamed in 64-key tiles (hi+lo 16KB/stage),
// 2 stages + Q 32KB = 64KB smem -> 2 CTAs/SM.
#define SQ_HI 0
#define SQ_LO 16384
#define SK_BASE 32768
#define SK_STAGE 16384
#define SM_TOTAL (SK_BASE + 2*SK_STAGE)   // 64 KB

__device__ __forceinline__ void copy_qtile(uint32_t sdst, const __nv_bfloat16* gsrc, int tid) {
    #pragma unroll
    for (int i = 0; i < 8; i++) {
        int u = tid + i*128;            // 1024 units (128 rows)
        int row = u >> 3, cu = u & 7;
        uint32_t dst = sdst + row*128 + ((cu ^ (row & 7)) << 4);
        CP_ASYNC16(dst, (const char*)gsrc + (size_t)u*16);
    }
}
__device__ __forceinline__ void copy_ktile(uint32_t sdst, const __nv_bfloat16* gsrc, int tid) {
    #pragma unroll
    for (int i = 0; i < 4; i++) {
        int u = tid + i*128;            // 512 units (64 rows)
        int row = u >> 3, cu = u & 7;
        uint32_t dst = sdst + row*128 + ((cu ^ (row & 7)) << 4);
        CP_ASYNC16(dst, (const char*)gsrc + (size_t)u*16);
    }
}

__global__ void __launch_bounds__(128, 2) scores_mma_kernel() {
    extern __shared__ char smem[];
    uint32_t sb = smem_u32(smem);
    int tid = threadIdx.x;
    int w = tid >> 5, lane = tid & 31;
    int bh = blockIdx.x;
    int qt = blockIdx.y;

    const __nv_bfloat16* qh_g = g_Qhi + (size_t)(bh*S + qt*128)*DK;
    const __nv_bfloat16* ql_g = g_Qlo + (size_t)(bh*S + qt*128)*DK;
    const __nv_bfloat16* kh_g = g_Khi + (size_t)bh*S*DK;
    const __nv_bfloat16* kl_g = g_Klo + (size_t)bh*S*DK;

    copy_qtile(sb + SQ_HI, qh_g, tid);
    copy_qtile(sb + SQ_LO, ql_g, tid);
    copy_ktile(sb + SK_BASE + 0*SK_STAGE,        kh_g, tid);
    copy_ktile(sb + SK_BASE + 0*SK_STAGE + 8192, kl_g, tid);
    CP_COMMIT();
    copy_ktile(sb + SK_BASE + 1*SK_STAGE,        kh_g + 64*DK, tid);
    copy_ktile(sb + SK_BASE + 1*SK_STAGE + 8192, kl_g + 64*DK, tid);
    CP_COMMIT();

    CP_WAIT1();
    __syncthreads();

    uint32_t aHi[2][4][4], aLo[2][4][4];
    {
        int row16 = lane & 15;
        int half = lane >> 4;
        #pragma unroll
        for (int rb = 0; rb < 2; rb++) {
            uint32_t rowoff = (uint32_t)(w*32 + rb*16 + row16) * 128;
            #pragma unroll
            for (int ks = 0; ks < 4; ks++) {
                uint32_t unit = (uint32_t)(ks*2 + half);
                uint32_t off = rowoff + ((unit ^ (row16 & 7)) << 4);
                ldsm_x4(aHi[rb][ks][0], aHi[rb][ks][1], aHi[rb][ks][2], aHi[rb][ks][3], sb + SQ_HI + off);
                ldsm_x4(aLo[rb][ks][0], aLo[rb][ks][1], aLo[rb][ks][2], aLo[rb][ks][3], sb + SQ_LO + off);
            }
        }
    }

    float rmax0[2] = {-1e30f, -1e30f}, rmax1[2] = {-1e30f, -1e30f};
    float rsum0[2] = {0.f, 0.f},       rsum1[2] = {0.f, 0.f};
    int bi = lane >> 3;
    int br = lane & 7;

    #pragma unroll 1
    for (int kt = 0; kt < 32; kt++) {
        if (kt > 0) {
            CP_WAIT1();
            __syncthreads();
        }
        uint32_t kb_hi = sb + SK_BASE + (kt & 1)*SK_STAGE;
        uint32_t kb_lo = kb_hi + 8192;

        #pragma unroll
        for (int t = 0; t < 8; t++) {
            int row = t*8 + br;
            uint32_t rowoff = (uint32_t)row * 128;
            uint32_t sw0 = ((uint32_t)(bi    ) ^ (row & 7)) << 4;
            uint32_t sw1 = ((uint32_t)(bi + 4) ^ (row & 7)) << 4;
            uint32_t bh0,bh1,bh2,bh3,bh4,bh5,bh6,bh7;
            uint32_t bl0,bl1,bl2,bl3,bl4,bl5,bl6,bl7;
            ldsm_x4(bh0,bh1,bh2,bh3, kb_hi + rowoff + sw0);
            ldsm_x4(bh4,bh5,bh6,bh7, kb_hi + rowoff + sw1);
            ldsm_x4(bl0,bl1,bl2,bl3, kb_lo + rowoff + sw0);
            ldsm_x4(bl4,bl5,bl6,bl7, kb_lo + rowoff + sw1);

            #pragma unroll
            for (int rb = 0; rb < 2; rb++) {
                float cA0=0.f, cA1=0.f, cA2=0.f, cA3=0.f;
                float cB0=0.f, cB1=0.f, cB2=0.f, cB3=0.f;
                mma_bf16(cA0,cA1,cA2,cA3, aHi[rb][0][0],aHi[rb][0][1],aHi[rb][0][2],aHi[rb][0][3], bh0,bh1);
                mma_bf16(cB0,cB1,cB2,cB3, aHi[rb][0][0],aHi[rb][0][1],aHi[rb][0][2],aHi[rb][0][3], bl0,bl1);
                mma_bf16(cA0,cA1,cA2,cA3, aHi[rb][1][0],aHi[rb][1][1],aHi[rb][1][2],aHi[rb][1][3], bh2,bh3);
                mma_bf16(cB0,cB1,cB2,cB3, aHi[rb][1][0],aHi[rb][1][1],aHi[rb][1][2],aHi[rb][1][3], bl2,bl3);
                mma_bf16(cA0,cA1,cA2,cA3, aHi[rb][2][0],aHi[rb][2][1],aHi[rb][2][2],aHi[rb][2][3], bh4,bh5);
                mma_bf16(cB0,cB1,cB2,cB3, aHi[rb][2][0],aHi[rb][2][1],aHi[rb][2][2],aHi[rb][2][3], bl4,bl5);
                mma_bf16(cA0,cA1,cA2,cA3, aHi[rb][3][0],aHi[rb][3][1],aHi[rb][3][2],aHi[rb][3][3], bh6,bh7);
                mma_bf16(cB0,cB1,cB2,cB3, aHi[rb][3][0],aHi[rb][3][1],aHi[rb][3][2],aHi[rb][3][3], bl6,bl7);
                mma_bf16(cA0,cA1,cA2,cA3, aLo[rb][0][0],aLo[rb][0][1],aLo[rb][0][2],aLo[rb][0][3], bh0,bh1);
                mma_bf16(cB0,cB1,cB2,cB3, aLo[rb][2][0],aLo[rb][2][1],aLo[rb][2][2],aLo[rb][2][3], bh4,bh5);
                mma_bf16(cA0,cA1,cA2,cA3, aLo[rb][1][0],aLo[rb][1][1],aLo[rb][1][2],aLo[rb][1][3], bh2,bh3);
                mma_bf16(cB0,cB1,cB2,cB3, aLo[rb][3][0],aLo[rb][3][1],aLo[rb][3][2],aLo[rb][3][3], bh6,bh7);

                float c0 = cA0 + cB0, c1 = cA1 + cB1, c2 = cA2 + cB2, c3 = cA3 + cB3;
                rmax0[rb] = fmaxf(rmax0[rb], fmaxf(c0, c1));
                rsum0[rb] += c0 + c1;
                rmax1[rb] = fmaxf(rmax1[rb], fmaxf(c2, c3));
                rsum1[rb] += c2 + c3;
            }
        }
        __syncthreads();
        if (kt + 2 < 32) {
            copy_ktile(sb + SK_BASE + (kt & 1)*SK_STAGE,        kh_g + (size_t)(kt+2)*64*DK, tid);
            copy_ktile(sb + SK_BASE + (kt & 1)*SK_STAGE + 8192, kl_g + (size_t)(kt+2)*64*DK, tid);
        }
        CP_COMMIT();
    }

    #pragma unroll
    for (int rb = 0; rb < 2; rb++) {
        float m0v = rmax0[rb], m1v = rmax1[rb], s0v = rsum0[rb], s1v = rsum1[rb];
        #pragma unroll
        for (int off = 1; off < 4; off <<= 1) {
            m0v = fmaxf(m0v, __shfl_xor_sync(0xFFFFFFFFu, m0v, off));
            s0v += __shfl_xor_sync(0xFFFFFFFFu, s0v, off);
            m1v = fmaxf(m1v, __shfl_xor_sync(0xFFFFFFFFu, m1v, off));
            s1v += __shfl_xor_sync(0xFFFFFFFFu, s1v, off);
        }
        if ((lane & 3) == 0) {
            int r0 = qt*128 + w*32 + rb*16 + (lane >> 2);
            float inv_log = 1.0f / logf((float)S);
            g_spars[bh*S + r0]     = s0v * (0.125f / (float)S) - m0v * 0.125f * inv_log;
            g_spars[bh*S + r0 + 8] = s1v * (0.125f / (float)S) - m1v * 0.125f * inv_log;
        }
    }
}

// ---------------- iterative top-53 per (b,h) ----------------
__global__ void topk_kernel() {
    __shared__ float vals[S];
    __shared__ float wm[8];
    __shared__ int   wi[8];
    int bh = blockIdx.x, tid = threadIdx.x;
    int lane = tid & 31, wid = tid >> 5;
    for (int i = tid; i < S; i += 256) vals[i] = g_spars[bh*S + i];
    __syncthreads();
    for (int it = 0; it < U; it++) {
        float best = -1e30f; int bidx = S;
        #pragma unroll
        for (int k = 0; k < 8; k++) {
            int i = tid + k*256;
            float v = vals[i];
            if (v > best || (v == best && i < bidx)) { best = v; bidx = i; }
        }
        #pragma unroll
        for (int off = 16; off > 0; off >>= 1) {
            float v2 = __shfl_down_sync(0xFFFFFFFFu, best, off);
            int i2 = __shfl_down_sync(0xFFFFFFFFu, bidx, off);
            if (v2 > best || (v2 == best && i2 < bidx)) { best = v2; bidx = i2; }
        }
        if (lane == 0) { wm[wid] = best; wi[wid] = bidx; }
        __syncthreads();
        if (tid == 0) {
            float m = wm[0]; int mi = wi[0];
            #pragma unroll
            for (int t = 1; t < 8; t++)
                if (wm[t] > m || (wm[t] == m && wi[t] < mi)) { m = wm[t]; mi = wi[t]; }
            g_topidx[bh*U + it] = mi;
            vals[mi] = -1e30f;
        }
        __syncthreads();
    }
}

// ---------------- fused xsum-final + meanV + ybase (warp-per-output, coalesced) ----------------
__global__ void __launch_bounds__(512) meanv_ybase_kernel(
        const float* __restrict__ wv, const float* __restrict__ bv,
        const float* __restrict__ wo, const float* __restrict__ bo) {
    __shared__ float xs[D];
    __shared__ float mv[D];
    int b = blockIdx.x, tid = threadIdx.x;
    int lane = tid & 31, w = tid >> 5;      // 16 warps, 32 outputs each
    {
        float acc = 0.f;
        #pragma unroll 8
        for (int sc = 0; sc < 32; sc++) acc += g_xpart[(size_t)(b*32+sc)*D + tid];
        xs[tid] = acc;
    }
    __syncthreads();
    #pragma unroll 1
    for (int oo = 0; oo < 32; oo++) {
        int o = w*32 + oo;
        const float* wr = wv + (size_t)o*D + lane;
        float acc = 0.f;
        #pragma unroll
        for (int k = 0; k < 16; k++) acc += xs[lane + k*32] * wr[k*32];
        #pragma unroll
        for (int off = 16; off > 0; off >>= 1) acc += __shfl_xor_sync(0xFFFFFFFFu, acc, off);
        if (lane == 0) {
            float m = acc * (1.0f/(float)S) + bv[o];
            mv[o] = m;
            g_meanV[b*D + o] = m;
        }
    }
    __syncthreads();
    #pragma unroll 1
    for (int oo = 0; oo < 32; oo++) {
        int o = w*32 + oo;
        const float* wr = wo + (size_t)o*D + lane;
        float acc = 0.f;
        #pragma unroll
        for (int k = 0; k < 16; k++) acc += mv[lane + k*32] * wr[k*32];
        #pragma unroll
        for (int off = 16; off > 0; off >>= 1) acc += __shfl_xor_sync(0xFFFFFFFFu, acc, off);
        if (lane == 0) g_ybase[b*D + o] = acc + bo[o];
    }
}

// ---------------- corrections: one block per (b,h), 4x4 register-tiled ----------------
__global__ void __launch_bounds__(256) corr_kernel(const float* __restrict__ x,
                                                   const float* __restrict__ wv,
                                                   const float* __restrict__ bv) {
    __shared__ float sbuf[64*65 + 56*65];
    __shared__ int   s_idx[56];
    __shared__ float s_v[56];
    int bh = blockIdx.x;
    int b = bh / H, h = bh % H;
    int tid = threadIdx.x;
    if (tid < U) s_idx[tid] = g_topidx[bh*U + tid];
    __syncthreads();

    float* sq = sbuf;
    float* sk = sbuf + U*DK;
    for (int e = tid; e < U*DK; e += 256) sq[e] = g_Q[(size_t)bh*S*DK + e];
    for (int e = tid; e < U*DK; e += 256) {
        int i = e >> 6, d = e & 63;
        sk[e] = g_K[((size_t)bh*S + s_idx[i])*DK + d];
    }
    __syncthreads();
    if (tid < U) {
        float acc = 0.f;
        #pragma unroll 8
        for (int d = 0; d < DK; d++) acc += sq[tid*DK + d] * sk[tid*DK + d];
        s_v[tid] = acc * 0.125f;
    }
    __syncthreads();

    float* wvs = sbuf;
    float* xjs = sbuf + 64*65;
    int ci = tid & 15, ri = tid >> 4;
    float acc[4][4] = {};
    for (int dt = 0; dt < 8; dt++) {
        __syncthreads();
        for (int e = tid; e < 64*64; e += 256) {
            int r = e >> 6, c2 = e & 63;
            wvs[r*65 + c2] = wv[((size_t)(h*64 + r))*D + dt*64 + c2];
        }
        for (int e = tid; e < 56*64; e += 256) {
            int i = e >> 6, c2 = e & 63;
            xjs[i*65 + c2] = (i < U) ? x[((size_t)b*S + s_idx[i])*D + dt*64 + c2] : 0.f;
        }
        __syncthreads();
        if (ri < 14) {
            #pragma unroll 4
            for (int dd = 0; dd < 64; dd++) {
                float xv0 = xjs[(ri*4+0)*65 + dd];
                float xv1 = xjs[(ri*4+1)*65 + dd];
                float xv2 = xjs[(ri*4+2)*65 + dd];
                float xv3 = xjs[(ri*4+3)*65 + dd];
                float w0 = wvs[(ci*4+0)*65 + dd];
                float w1 = wvs[(ci*4+1)*65 + dd];
                float w2 = wvs[(ci*4+2)*65 + dd];
                float w3 = wvs[(ci*4+3)*65 + dd];
                acc[0][0] += xv0*w0; acc[0][1] += xv0*w1; acc[0][2] += xv0*w2; acc[0][3] += xv0*w3;
                acc[1][0] += xv1*w0; acc[1][1] += xv1*w1; acc[1][2] += xv1*w2; acc[1][3] += xv1*w3;
                acc[2][0] += xv2*w0; acc[2][1] += xv2*w1; acc[2][2] += xv2*w2; acc[2][3] += xv2*w3;
                acc[3][0] += xv3*w0; acc[3][1] += xv3*w1; acc[3][2] += xv3*w2; acc[3][3] += xv3*w3;
            }
        }
    }

    if (ri < 14) {
        #pragma unroll
        for (int r = 0; r < 4; r++) {
            int i = ri*4 + r;
            if (i >= U) continue;
            float ev = expf(s_v[i]);
            float em1 = ev - 1.0f;
            float Z = ev + (float)(S - 1);
            #pragma unroll
            for (int c2 = 0; c2 < 4; c2++) {
                int col = ci*4 + c2;
                float Vj = acc[r][c2] + bv[h*64 + col];
                float mvv = g_meanV[b*D + h*64 + col];
                g_outcat[((size_t)(b*U + i))*D + h*64 + col] = ((float)S * mvv + em1 * Vj) / Z;
            }
        }
    }
}

// ---------------- out-projection for the 212 corrected rows ----------------
__global__ void outproj_kernel(const float* __restrict__ wo, const float* __restrict__ bo,
                               float* __restrict__ y) {
    __shared__ float As[32][68];
    __shared__ float Bs[32][68];
    int tid = threadIdx.x;
    int tx = tid & 15, ty = tid >> 4;
    int m0 = blockIdx.x * 64;
    int n0 = blockIdx.y * 64;
    float acc[4][4] = {};
    for (int d0 = 0; d0 < D; d0 += 32) {
        #pragma unroll
        for (int i = 0; i < 2; i++) {
            int e = tid + i*256;
            int row = e >> 3;
            int c4 = e & 7;
            float4 v = make_float4(0.f, 0.f, 0.f, 0.f);
            if (m0 + row < B*U)
                v = *(const float4*)(g_outcat + (size_t)(m0+row)*D + d0 + c4*4);
            As[c4*4+0][row] = v.x; As[c4*4+1][row] = v.y;
            As[c4*4+2][row] = v.z; As[c4*4+3][row] = v.w;
            float4 u = *(const float4*)(wo + (size_t)(n0+row)*D + d0 + c4*4);
            Bs[c4*4+0][row] = u.x; Bs[c4*4+1][row] = u.y;
            Bs[c4*4+2][row] = u.z; Bs[c4*4+3][row] = u.w;
        }
        __syncthreads();
        #pragma unroll
        for (int kk = 0; kk < 32; kk++) {
            float4 a = *(const float4*)&As[kk][tx*4];
            float4 bv4 = *(const float4*)&Bs[kk][ty*4];
            float av[4] = {a.x, a.y, a.z, a.w};
            float bw[4] = {bv4.x, bv4.y, bv4.z, bv4.w};
            #pragma unroll
            for (int i = 0; i < 4; i++)
                #pragma unroll
                for (int j = 0; j < 4; j++)
                    acc[i][j] += av[i] * bw[j];
        }
        __syncthreads();
    }
    #pragma unroll
    for (int i = 0; i < 4; i++) {
        int m = m0 + tx*4 + i;
        if (m < B*U) {
            int b = m / U, s = m % U;
            float* op = y + ((size_t)b*S + s)*D + n0 + ty*4;
            #pragma unroll
            for (int j = 0; j < 4; j++)
                op[j] = acc[i][j] + bo[n0 + ty*4 + j];
        }
    }
}

// ---------------- broadcast the uniform rows (s >= U) ----------------
__global__ void bcast_kernel(float* __restrict__ y) {
    int id = blockIdx.x * blockDim.x + threadIdx.x;
    const int per_b = (S - U) * (D/4);
    const int total = B * per_b;
    if (id >= total) return;
    int b = id / per_b;
    int r = id % per_b;
    int s = U + r / (D/4);
    int d4 = r % (D/4);
    float4 v = *(const float4*)(g_ybase + b*D + d4*4);
    *(float4*)(y + ((size_t)b*S + s)*D + d4*4) = v;
}

extern "C" void kernel_launch(void* const* d_in, const int* in_sizes, int n_in,
                              void* d_out, int out_size) {
    const float* x  = (const float*)d_in[0];
    const float* wq = (const float*)d_in[1];
    const float* bq = (const float*)d_in[2];
    const float* wk = (const float*)d_in[3];
    const float* bk = (const float*)d_in[4];
    const float* wv = (const float*)d_in[5];
    const float* bv = (const float*)d_in[6];
    const float* wo = (const float*)d_in[7];
    const float* bo = (const float*)d_in[8];
    float* y = (float*)d_out;

    cudaFuncSetAttribute(scores_mma_kernel, cudaFuncAttributeMaxDynamicSharedMemorySize, SM_TOTAL);
    cudaFuncSetAttribute(proj_mma_kernel, cudaFuncAttributeMaxDynamicSharedMemorySize, PJ_SM_TOTAL);

    {
        const int total = XU + 2*WU;
        convert_xw_kernel<<<(total + 255)/256, 256>>>(x, wq, wk);          // u1
    }

    dim3 pg(B*S/128, D/64, 2);
    proj_mma_kernel<<<pg, 256, PJ_SM_TOTAL>>>(bq, bk);                     // u2

    sumx_part_kernel<<<B*32, 512>>>(x);                                    // u3

    dim3 sg(BH, 16);
    scores_mma_kernel<<<sg, 128, SM_TOTAL>>>();                            // u4 <- ncu

    topk_kernel<<<BH, 256>>>();                                            // u5

    meanv_ybase_kernel<<<B, 512>>>(wv, bv, wo, bo);                        // u6

    corr_kernel<<<BH, 256>>>(x, wv, bv);                                   // u7

    dim3 og((B*U + 63)/64, D/64);
    outproj_kernel<<<og, 256>>>(wo, bo, y);                                // u8

    const int per_b = (S - U) * (D/4);
    bcast_kernel<<<(B*per_b + 255)/256, 256>>>(y);                         // u9
}